// round 3
// baseline (speedup 1.0000x reference)
#include <cuda_runtime.h>
#include <math.h>

#define S_LEN 2048
#define BATCH 2
#define EMBED 1024
#define NHEAD 16
#define HDIM  64

// ---------------- scratch (static device globals; no allocation) ----------------
__device__ float g_sin[S_LEN * EMBED];          // sinusoid embedding  [S, D]
__device__ float g_pos[S_LEN * EMBED];          // pos projection      [S, D]
__device__ float g_q[BATCH * S_LEN * EMBED];    // Q  [B*S, D]
__device__ float g_k[BATCH * S_LEN * EMBED];    // K
__device__ float g_v[BATCH * S_LEN * EMBED];    // V
__device__ float g_attn[BATCH * S_LEN * EMBED]; // attention output (pre out-proj)

// ---------------- sinusoid position embedding ----------------
__global__ void sinusoid_kernel() {
    int idx = blockIdx.x * blockDim.x + threadIdx.x;
    if (idx >= S_LEN * (EMBED / 2)) return;
    int s = idx / (EMBED / 2);
    int i = idx % (EMBED / 2);
    // inv_freq = 10000^(-2i/D); compute in double then round (matches fp32 ref to ~1 ulp)
    double invf = exp(-(2.0 * (double)i / (double)EMBED) * log(10000.0));
    float ang = (float)s * (float)invf;         // fp32 product, like the reference
    double a = (double)ang;
    g_sin[s * EMBED + i]              = (float)sin(a);
    g_sin[s * EMBED + (EMBED/2) + i]  = (float)cos(a);
}

// ---------------- fp32 GEMM + bias: C[M,N] = A[M,K] @ B[K,N] + bias[N] ----------------
// BM=BN=128, BK=8, 256 threads, 8x8 microtile.
__global__ void __launch_bounds__(256) gemm_bias_kernel(
    const float* __restrict__ A, const float* __restrict__ B,
    const float* __restrict__ bias, float* __restrict__ C,
    int M, int N, int K)
{
    __shared__ float As[8][128];
    __shared__ float Bs[8][128];
    int tid = threadIdx.x;
    int tx = tid & 15, ty = tid >> 4;
    int bx = blockIdx.x, by = blockIdx.y;

    float acc[8][8];
#pragma unroll
    for (int i = 0; i < 8; i++)
#pragma unroll
        for (int j = 0; j < 8; j++) acc[i][j] = 0.f;

    int arow = tid >> 1;
    int acol = (tid & 1) * 4;
    int brow = tid >> 5;
    int bcol = (tid & 31) * 4;
    const float* Ap = A + (size_t)(by * 128 + arow) * K + acol;
    const float* Bp = B + (size_t)brow * N + bx * 128 + bcol;

    for (int k0 = 0; k0 < K; k0 += 8) {
        float4 av = *(const float4*)(Ap + k0);
        float4 bv = *(const float4*)(Bp + (size_t)k0 * N);
        __syncthreads();
        As[acol + 0][arow] = av.x;
        As[acol + 1][arow] = av.y;
        As[acol + 2][arow] = av.z;
        As[acol + 3][arow] = av.w;
        *(float4*)&Bs[brow][bcol] = bv;
        __syncthreads();
#pragma unroll
        for (int kk = 0; kk < 8; kk++) {
            float a[8], b[8];
            *(float4*)&a[0] = *(const float4*)&As[kk][ty * 8];
            *(float4*)&a[4] = *(const float4*)&As[kk][ty * 8 + 4];
            *(float4*)&b[0] = *(const float4*)&Bs[kk][tx * 8];
            *(float4*)&b[4] = *(const float4*)&Bs[kk][tx * 8 + 4];
#pragma unroll
            for (int i = 0; i < 8; i++)
#pragma unroll
                for (int j = 0; j < 8; j++)
                    acc[i][j] += a[i] * b[j];
        }
    }
#pragma unroll
    for (int i = 0; i < 8; i++) {
        int row = by * 128 + ty * 8 + i;
        float* Cp = C + (size_t)row * N + bx * 128 + tx * 8;
#pragma unroll
        for (int j = 0; j < 8; j++)
            Cp[j] = acc[i][j] + bias[bx * 128 + tx * 8 + j];
    }
}

// ---------------- fused relative attention (flash-style) ----------------
// Per block: one (b, h, 64-row s-tile). Loops 64-col t-tiles with online softmax.
// Relative shift (derived exactly from pad/reshape/slice):
//   t <= s   : pos col = t + S-1 - s, query row s
//   t == s+1 : 0
//   t >= s+2 : pos col = t - s - 2,   query row s+1   (!)
// Within a tile, pos col index is Toeplitz: idx = (tt - ss) + 63 into a 127-row band.
//
// smem layout (floats):
#define OFF_QS 0        // [65][65] pitch 65 : q + u (65 rows: extra row for s+1 case)
#define OFF_KS 4228     // [64][65]
#define OFF_VS 8388     // [64][64] (16B aligned for float4)
#define OFF_PS 12484    // [64][65] : exp'd probabilities
#define OFF_BA 16644    // [127][65] band A (t <= s)
#define OFF_BB 24900    // [127][65] band B (t >= s+2)
#define OFF_ZR 33156    // [64] zeros (for the t == s+1 diagonal)
#define OFF_DV 33220    // [64] (v - u) per head-dim
#define ATT_SMEM_FLOATS 33284

__global__ void __launch_bounds__(256) attn_kernel(
    const float* __restrict__ Q, const float* __restrict__ Km,
    const float* __restrict__ Vm, const float* __restrict__ POS,
    const float* __restrict__ ub, const float* __restrict__ vbias,
    float* __restrict__ OUT)
{
    extern __shared__ float sm[];
    float* Qs  = sm + OFF_QS;
    float* Ks  = sm + OFF_KS;
    float* Vs  = sm + OFF_VS;
    float* Ps  = sm + OFF_PS;
    float* bA  = sm + OFF_BA;
    float* bB  = sm + OFF_BB;
    float* zr  = sm + OFF_ZR;
    float* dvu = sm + OFF_DV;

    int tid = threadIdx.x;
    int tx = tid & 15, ty = tid >> 4;
    int s0 = blockIdx.x * 64;
    int h  = blockIdx.y;
    int b  = blockIdx.z;
    const int hoff = h * HDIM;

    if (tid < 64) {
        zr[tid]  = 0.f;
        dvu[tid] = vbias[hoff + tid] - ub[hoff + tid];
    }
    // Load Qs (65 rows), storing q+u. Row 64 (s0+64) only consumed when a t>=s+2
    // case exists for s=s0+63, which never happens for the last tile; clamp for safety.
    for (int q4 = tid; q4 < 65 * 16; q4 += 256) {
        int row = q4 >> 4;
        int p4  = (q4 & 15) * 4;
        int s   = s0 + row; if (s > S_LEN - 1) s = S_LEN - 1;
        float4 qv = *(const float4*)(Q + (size_t)(b * S_LEN + s) * EMBED + hoff + p4);
        float4 uu = *(const float4*)(ub + hoff + p4);
        Qs[row * 65 + p4 + 0] = qv.x + uu.x;
        Qs[row * 65 + p4 + 1] = qv.y + uu.y;
        Qs[row * 65 + p4 + 2] = qv.z + uu.z;
        Qs[row * 65 + p4 + 3] = qv.w + uu.w;
    }

    const int ssb = ty * 4, ttb = tx * 4;
    float m_r[4], l_r[4], acc[4][4];
#pragma unroll
    for (int i = 0; i < 4; i++) {
        m_r[i] = -1e30f; l_r[i] = 0.f;
#pragma unroll
        for (int j = 0; j < 4; j++) acc[i][j] = 0.f;
    }

    for (int t0 = 0; t0 < S_LEN; t0 += 64) {
        __syncthreads();   // protect K/V/bands/Ps from previous iteration readers
        // ---- load K, V tiles ----
        for (int q4 = tid; q4 < 64 * 16; q4 += 256) {
            int row = q4 >> 4;
            int p4  = (q4 & 15) * 4;
            size_t goff = (size_t)(b * S_LEN + t0 + row) * EMBED + hoff + p4;
            float4 kv = *(const float4*)(Km + goff);
            Ks[row * 65 + p4 + 0] = kv.x;
            Ks[row * 65 + p4 + 1] = kv.y;
            Ks[row * 65 + p4 + 2] = kv.z;
            Ks[row * 65 + p4 + 3] = kv.w;
            float4 vv = *(const float4*)(Vm + goff);
            *(float4*)&Vs[row * 64 + p4] = vv;
        }
        const int diag = t0 - s0;
        // ---- pos bands ----
        if (diag <= 0) {  // band A needed (some t <= s)
            int c0 = (S_LEN - 64) + diag;
            for (int q4 = tid; q4 < 127 * 16; q4 += 256) {
                int r  = q4 >> 4;
                int p4 = (q4 & 15) * 4;
                int c  = c0 + r;
                float4 pv = make_float4(0.f, 0.f, 0.f, 0.f);
                if (c >= 0 && c < S_LEN)
                    pv = *(const float4*)(POS + (size_t)c * EMBED + hoff + p4);
                bA[r * 65 + p4 + 0] = pv.x;
                bA[r * 65 + p4 + 1] = pv.y;
                bA[r * 65 + p4 + 2] = pv.z;
                bA[r * 65 + p4 + 3] = pv.w;
            }
        }
        if (diag >= 0) {  // band B needed (some t >= s+2)
            int c0 = diag - 65;
            for (int q4 = tid; q4 < 127 * 16; q4 += 256) {
                int r  = q4 >> 4;
                int p4 = (q4 & 15) * 4;
                int c  = c0 + r;
                float4 pv = make_float4(0.f, 0.f, 0.f, 0.f);
                if (c >= 0 && c < S_LEN)
                    pv = *(const float4*)(POS + (size_t)c * EMBED + hoff + p4);
                bB[r * 65 + p4 + 0] = pv.x;
                bB[r * 65 + p4 + 1] = pv.y;
                bB[r * 65 + p4 + 2] = pv.z;
                bB[r * 65 + p4 + 3] = pv.w;
            }
        }
        __syncthreads();

        // ---- per-thread band row pointers (7 diagonals of the 4x4 microtile) ----
        const float* bp[7];
        unsigned useB = 0;
#pragma unroll
        for (int dd = 0; dd < 7; dd++) {
            int off   = (ttb - ssb) + dd - 3;   // t - s (tile-local part)
            int idxd  = off + 63;               // band row, in [0,126]
            int tsrel = diag + off;             // global t - s
            bp[dd] = (tsrel <= 0) ? (bA + idxd * 65)
                   : ((tsrel == 1) ? zr : (bB + idxd * 65));
        }
#pragma unroll
        for (int i = 0; i < 4; i++)
#pragma unroll
            for (int j = 0; j < 4; j++)
                if (diag + (ttb + j) - (ssb + i) >= 2) useB |= 1u << (i * 4 + j);

        // ---- scores: content + shifted pos ----
        float sc[4][4];
#pragma unroll
        for (int i = 0; i < 4; i++)
#pragma unroll
            for (int j = 0; j < 4; j++) sc[i][j] = 0.f;

#pragma unroll 8
        for (int p = 0; p < 64; p++) {
            float dv = dvu[p];
            float qf[5], qv5[5], kf[4], bv[7];
#pragma unroll
            for (int i = 0; i < 5; i++) { qf[i] = Qs[(ssb + i) * 65 + p]; qv5[i] = qf[i] + dv; }
#pragma unroll
            for (int j = 0; j < 4; j++) kf[j] = Ks[(ttb + j) * 65 + p];
#pragma unroll
            for (int dd = 0; dd < 7; dd++) bv[dd] = bp[dd][p];
#pragma unroll
            for (int i = 0; i < 4; i++)
#pragma unroll
                for (int j = 0; j < 4; j++) {
                    float qd = ((useB >> (i * 4 + j)) & 1u) ? qv5[i + 1] : qv5[i];
                    sc[i][j] += qf[i] * kf[j];
                    sc[i][j] += qd * bv[j - i + 3];
                }
        }

        // ---- online softmax (scale 1/sqrt(64) = 0.125) ----
#pragma unroll
        for (int i = 0; i < 4; i++) {
#pragma unroll
            for (int j = 0; j < 4; j++) sc[i][j] *= 0.125f;
            float rmax = fmaxf(fmaxf(sc[i][0], sc[i][1]), fmaxf(sc[i][2], sc[i][3]));
#pragma unroll
            for (int msk = 1; msk < 16; msk <<= 1)
                rmax = fmaxf(rmax, __shfl_xor_sync(0xffffffffu, rmax, msk));
            float mnew = fmaxf(m_r[i], rmax);
            float corr = __expf(m_r[i] - mnew);
            float rsum = 0.f;
#pragma unroll
            for (int j = 0; j < 4; j++) {
                sc[i][j] = __expf(sc[i][j] - mnew);
                rsum += sc[i][j];
            }
#pragma unroll
            for (int msk = 1; msk < 16; msk <<= 1)
                rsum += __shfl_xor_sync(0xffffffffu, rsum, msk);
            l_r[i] = l_r[i] * corr + rsum;
            m_r[i] = mnew;
#pragma unroll
            for (int j = 0; j < 4; j++) acc[i][j] *= corr;
        }

        // ---- P @ V ----
#pragma unroll
        for (int i = 0; i < 4; i++)
#pragma unroll
            for (int j = 0; j < 4; j++)
                Ps[(ssb + i) * 65 + ttb + j] = sc[i][j];
        __syncthreads();

        const float4* Vs4 = (const float4*)Vs;
#pragma unroll 8
        for (int kk = 0; kk < 64; kk++) {
            float pf[4];
#pragma unroll
            for (int i = 0; i < 4; i++) pf[i] = Ps[(ssb + i) * 65 + kk];
            float4 vf = Vs4[kk * 16 + tx];
#pragma unroll
            for (int i = 0; i < 4; i++) {
                acc[i][0] += pf[i] * vf.x;
                acc[i][1] += pf[i] * vf.y;
                acc[i][2] += pf[i] * vf.z;
                acc[i][3] += pf[i] * vf.w;
            }
        }
    }

    // ---- epilogue: normalize, write [B,S,H,P] ----
#pragma unroll
    for (int i = 0; i < 4; i++) {
        float inv = 1.f / l_r[i];
        int s = s0 + ssb + i;
        float* op = OUT + (size_t)(b * S_LEN + s) * EMBED + hoff + ttb;
#pragma unroll
        for (int j = 0; j < 4; j++)
            op[j] = acc[i][j] * inv;
    }
}

// ---------------- launch ----------------
extern "C" void kernel_launch(void* const* d_in, const int* in_sizes, int n_in,
                              void* d_out, int out_size)
{
    const float* x   = (const float*)d_in[0];
    const float* Wq  = (const float*)d_in[1];
    const float* bq  = (const float*)d_in[2];
    const float* Wk  = (const float*)d_in[3];
    const float* bk  = (const float*)d_in[4];
    const float* Wv  = (const float*)d_in[5];
    const float* bv_ = (const float*)d_in[6];
    const float* Wp  = (const float*)d_in[7];
    const float* bp  = (const float*)d_in[8];
    const float* Wo  = (const float*)d_in[9];
    const float* bo  = (const float*)d_in[10];
    const float* u   = (const float*)d_in[11];
    const float* v   = (const float*)d_in[12];
    float* out = (float*)d_out;

    float *psin, *ppos, *pq, *pk, *pv, *pattn;
    cudaGetSymbolAddress((void**)&psin,  g_sin);
    cudaGetSymbolAddress((void**)&ppos,  g_pos);
    cudaGetSymbolAddress((void**)&pq,    g_q);
    cudaGetSymbolAddress((void**)&pk,    g_k);
    cudaGetSymbolAddress((void**)&pv,    g_v);
    cudaGetSymbolAddress((void**)&pattn, g_attn);

    cudaFuncSetAttribute(attn_kernel, cudaFuncAttributeMaxDynamicSharedMemorySize,
                         ATT_SMEM_FLOATS * 4);

    sinusoid_kernel<<<(S_LEN * (EMBED / 2) + 255) / 256, 256>>>();

    dim3 gBig(EMBED / 128, (BATCH * S_LEN) / 128);   // (8, 32)
    dim3 gPos(EMBED / 128, S_LEN / 128);             // (8, 16)
    gemm_bias_kernel<<<gBig, 256>>>(x, Wq, bq, pq, BATCH * S_LEN, EMBED, EMBED);
    gemm_bias_kernel<<<gBig, 256>>>(x, Wk, bk, pk, BATCH * S_LEN, EMBED, EMBED);
    gemm_bias_kernel<<<gBig, 256>>>(x, Wv, bv_, pv, BATCH * S_LEN, EMBED, EMBED);
    gemm_bias_kernel<<<gPos, 256>>>(psin, Wp, bp, ppos, S_LEN, EMBED, EMBED);

    dim3 gAtt(S_LEN / 64, NHEAD, BATCH);             // (32, 16, 2)
    attn_kernel<<<gAtt, 256, ATT_SMEM_FLOATS * 4>>>(pq, pk, pv, ppos, u, v, pattn);

    gemm_bias_kernel<<<gBig, 256>>>(pattn, Wo, bo, out, BATCH * S_LEN, EMBED, EMBED);
}

// round 7
// speedup vs baseline: 1.6993x; 1.6993x over previous
#include <cuda_runtime.h>
#include <math.h>
#include <stdint.h>

#define S_LEN 2048
#define BATCH 2
#define EMBED 1024
#define NHEAD 16
#define HDIM  64

// ---------------- scratch (static device globals; no allocation) ----------------
__device__ float g_sin[S_LEN * EMBED];          // sinusoid embedding  [S, D]
__device__ float g_pos[S_LEN * EMBED];          // pos projection      [S, D]
__device__ float g_q[BATCH * S_LEN * EMBED];    // Q  [B*S, D]
__device__ float g_k[BATCH * S_LEN * EMBED];    // K
__device__ float g_v[BATCH * S_LEN * EMBED];    // V
__device__ float g_attn[BATCH * S_LEN * EMBED]; // attention output (pre out-proj)

// ---------------- sinusoid position embedding ----------------
__global__ void sinusoid_kernel() {
    int idx = blockIdx.x * blockDim.x + threadIdx.x;
    if (idx >= S_LEN * (EMBED / 2)) return;
    int s = idx / (EMBED / 2);
    int i = idx % (EMBED / 2);
    double invf = exp(-(2.0 * (double)i / (double)EMBED) * log(10000.0));
    float ang = (float)s * (float)invf;
    double a = (double)ang;
    g_sin[s * EMBED + i]              = (float)sin(a);
    g_sin[s * EMBED + (EMBED/2) + i]  = (float)cos(a);
}

// ---------------- fp32 GEMM + bias (SIMT, known-good) ----------------
__device__ __forceinline__ void gemm_body(
    const float* __restrict__ A, const float* __restrict__ B,
    const float* __restrict__ bias, float* __restrict__ C,
    int M, int N, int K)
{
    __shared__ float As[8][128];
    __shared__ float Bs[8][128];
    int tid = threadIdx.x;
    int tx = tid & 15, ty = tid >> 4;
    int bx = blockIdx.x, by = blockIdx.y;

    float acc[8][8];
#pragma unroll
    for (int i = 0; i < 8; i++)
#pragma unroll
        for (int j = 0; j < 8; j++) acc[i][j] = 0.f;

    int arow = tid >> 1;
    int acol = (tid & 1) * 4;
    int brow = tid >> 5;
    int bcol = (tid & 31) * 4;
    const float* Ap = A + (size_t)(by * 128 + arow) * K + acol;
    const float* Bp = B + (size_t)brow * N + bx * 128 + bcol;

    for (int k0 = 0; k0 < K; k0 += 8) {
        float4 av = *(const float4*)(Ap + k0);
        float4 bv = *(const float4*)(Bp + (size_t)k0 * N);
        __syncthreads();
        As[acol + 0][arow] = av.x;
        As[acol + 1][arow] = av.y;
        As[acol + 2][arow] = av.z;
        As[acol + 3][arow] = av.w;
        *(float4*)&Bs[brow][bcol] = bv;
        __syncthreads();
#pragma unroll
        for (int kk = 0; kk < 8; kk++) {
            float a[8], b[8];
            *(float4*)&a[0] = *(const float4*)&As[kk][ty * 8];
            *(float4*)&a[4] = *(const float4*)&As[kk][ty * 8 + 4];
            *(float4*)&b[0] = *(const float4*)&Bs[kk][tx * 8];
            *(float4*)&b[4] = *(const float4*)&Bs[kk][tx * 8 + 4];
#pragma unroll
            for (int i = 0; i < 8; i++)
#pragma unroll
                for (int j = 0; j < 8; j++)
                    acc[i][j] += a[i] * b[j];
        }
    }
#pragma unroll
    for (int i = 0; i < 8; i++) {
        int row = by * 128 + ty * 8 + i;
        float* Cp = C + (size_t)row * N + bx * 128 + tx * 8;
#pragma unroll
        for (int j = 0; j < 8; j++)
            Cp[j] = acc[i][j] + bias[bx * 128 + tx * 8 + j];
    }
}

__global__ void __launch_bounds__(256) gemm_bias_kernel(
    const float* __restrict__ A, const float* __restrict__ B,
    const float* __restrict__ bias, float* __restrict__ C,
    int M, int N, int K)
{
    gemm_body(A, B, bias, C, M, N, K);
}

// Q/K/V fused into one launch via blockIdx.z (better wave packing: 768 blocks)
__global__ void __launch_bounds__(256) gemm_bias_qkv_kernel(
    const float* __restrict__ A,
    const float* __restrict__ W0, const float* __restrict__ c0,
    const float* __restrict__ W1, const float* __restrict__ c1,
    const float* __restrict__ W2, const float* __restrict__ c2,
    float* __restrict__ O0, float* __restrict__ O1, float* __restrict__ O2,
    int M, int N, int K)
{
    const float* B; const float* bias; float* C;
    if (blockIdx.z == 0)      { B = W0; bias = c0; C = O0; }
    else if (blockIdx.z == 1) { B = W1; bias = c1; C = O1; }
    else                      { B = W2; bias = c2; C = O2; }
    gemm_body(A, B, bias, C, M, N, K);
}

// ---------------- tf32 helpers ----------------
__device__ __forceinline__ float tf32f(float f) {
    uint32_t u;
    asm("cvt.rna.tf32.f32 %0, %1;" : "=r"(u) : "f"(f));
    return __uint_as_float(u);
}
__device__ __forceinline__ uint32_t fb(float f) { return __float_as_uint(f); }

__device__ __forceinline__ void mma_tf32(float* d,
    uint32_t a0, uint32_t a1, uint32_t a2, uint32_t a3,
    uint32_t b0, uint32_t b1)
{
    asm volatile(
        "mma.sync.aligned.m16n8k8.row.col.f32.tf32.tf32.f32 "
        "{%0,%1,%2,%3}, {%4,%5,%6,%7}, {%8,%9}, {%0,%1,%2,%3};"
        : "+f"(d[0]), "+f"(d[1]), "+f"(d[2]), "+f"(d[3])
        : "r"(a0), "r"(a1), "r"(a2), "r"(a3), "r"(b0), "r"(b1));
}

// ---------------- fused relative attention (tf32 tensor-core flash) ----------------
// Per block: one (b, h, 64-row s-tile); loop over 64-col t-tiles, online softmax.
// Relative shift:  d = t - s
//   d <= 0 : (q+v)[s]   . pos[S-1+d]
//   d == 1 : 0
//   d >= 2 : (q+v)[s+1] . pos[d-2]
// Band E[r] = POSROW(d = diag-63+r), r in [0,126]; within a tile the gather
// index is r = tt-ss+63. Query-row base (s vs s+1) handled by shifting the
// A-operand of the G = Qv @ E^T MMA; only diag==0 needs both passes
// (diag is a multiple of 64).
//
// smem layout (floats). ST=68: 64-wide rows + 4 pad -> MMA reads hit banks
// (4g+t4), conflict-free. VST=72 for V: PV B-reads hit banks (8*t4+g),
// conflict-free. Ps ALIASES Es (E reads all complete before the redmax
// sync that precedes the Ps store; next-tile E reload is after the loop-top
// sync that follows the PV reads of Ps).
#define ST  68
#define VST 72
#define GST 132
#define AOFF_QU  0               // 64*68  = 4352
#define AOFF_QV  4352            // 65*68  = 4420
#define AOFF_KS  8772            // 64*68  = 4352
#define AOFF_VS  13124           // 64*72  = 4608
#define AOFF_E   17732           // 128*68 = 8704   (Ps aliases this)
#define AOFF_G   26436           // 64*132 = 8448
#define AOFF_RMX 34884           // 128
#define AOFF_RSM 35012           // 128
#define ATT_SMEM_FLOATS 35140    // 140560 bytes

__global__ void __launch_bounds__(256) attn_kernel(
    const float* __restrict__ Q, const float* __restrict__ Km,
    const float* __restrict__ Vm, const float* __restrict__ POS,
    const float* __restrict__ ub, const float* __restrict__ vbias,
    float* __restrict__ OUT)
{
    extern __shared__ float sm[];
    float* Qu = sm + AOFF_QU;
    float* Qv = sm + AOFF_QV;
    float* Ks = sm + AOFF_KS;
    float* Vs = sm + AOFF_VS;
    float* Es = sm + AOFF_E;
    float* Ps = sm + AOFF_E;     // alias (disjoint lifetimes, see header)
    float* Gs = sm + AOFF_G;
    float* redmax = sm + AOFF_RMX;
    float* redsum = sm + AOFF_RSM;

    const int tid  = threadIdx.x;
    const int lane = tid & 31;
    const int wid  = tid >> 5;
    const int wr   = wid >> 1;     // 0..3 : row group (16 rows)
    const int wc   = wid & 1;      // 0..1 : col group (32 cols / 64 G-cols)
    const int g    = lane >> 2;    // 0..7
    const int t4   = lane & 3;     // 0..3

    const int s0   = blockIdx.x * 64;
    const int h    = blockIdx.y;
    const int b    = blockIdx.z;
    const int hoff = h * HDIM;

    // ---- prologue: zero E pad row 127 (cols live outside the Ps alias range,
    //      so this zero survives all tiles), load Qu (64 rows) and Qv (65 rows) ----
    if (tid < ST) Es[127 * ST + tid] = 0.f;
    for (int q4 = tid; q4 < 65 * 16; q4 += 256) {
        int row = q4 >> 4;
        int p4  = (q4 & 15) * 4;
        int s   = s0 + row; if (s > S_LEN - 1) s = S_LEN - 1;
        float4 qv = *(const float4*)(Q + (size_t)(b * S_LEN + s) * EMBED + hoff + p4);
        float4 uu = *(const float4*)(ub + hoff + p4);
        float4 vv = *(const float4*)(vbias + hoff + p4);
        float qa[4] = {qv.x, qv.y, qv.z, qv.w};
        float ua[4] = {uu.x, uu.y, uu.z, uu.w};
        float va[4] = {vv.x, vv.y, vv.z, vv.w};
#pragma unroll
        for (int i = 0; i < 4; i++) {
            if (row < 64) Qu[row * ST + p4 + i] = tf32f(qa[i] + ua[i]);
            Qv[row * ST + p4 + i] = tf32f(qa[i] + va[i]);
        }
    }

    float acc[4][4];
    float m_r[2], l_r[2];
#pragma unroll
    for (int nf = 0; nf < 4; nf++)
#pragma unroll
        for (int e = 0; e < 4; e++) acc[nf][e] = 0.f;
    m_r[0] = m_r[1] = -1e30f;
    l_r[0] = l_r[1] = 0.f;

    for (int t0 = 0; t0 < S_LEN; t0 += 64) {
        const int diag = t0 - s0;
        __syncthreads();   // previous iteration's PV (Ps reads) / gathers complete

        // ---- load K, V tiles (tf32-rounded) ----
        for (int q4 = tid; q4 < 64 * 16; q4 += 256) {
            int row = q4 >> 4;
            int p4  = (q4 & 15) * 4;
            size_t go = (size_t)(b * S_LEN + t0 + row) * EMBED + hoff + p4;
            float4 kv = *(const float4*)(Km + go);
            float4 vv = *(const float4*)(Vm + go);
            Ks[row * ST + p4 + 0] = tf32f(kv.x);
            Ks[row * ST + p4 + 1] = tf32f(kv.y);
            Ks[row * ST + p4 + 2] = tf32f(kv.z);
            Ks[row * ST + p4 + 3] = tf32f(kv.w);
            Vs[row * VST + p4 + 0] = tf32f(vv.x);
            Vs[row * VST + p4 + 1] = tf32f(vv.y);
            Vs[row * VST + p4 + 2] = tf32f(vv.z);
            Vs[row * VST + p4 + 3] = tf32f(vv.w);
        }
        // ---- load pos band E (127 rows; overwrites the Ps alias) ----
        for (int q4 = tid; q4 < 127 * 16; q4 += 256) {
            int r  = q4 >> 4;
            int p4 = (q4 & 15) * 4;
            int d  = diag - 63 + r;
            int c  = (d <= 0) ? (S_LEN - 1 + d) : ((d == 1) ? -1 : (d - 2));
            float4 pv = make_float4(0.f, 0.f, 0.f, 0.f);
            if (c >= 0)
                pv = *(const float4*)(POS + (size_t)c * EMBED + hoff + p4);
            Es[r * ST + p4 + 0] = tf32f(pv.x);
            Es[r * ST + p4 + 1] = tf32f(pv.y);
            Es[r * ST + p4 + 2] = tf32f(pv.z);
            Es[r * ST + p4 + 3] = tf32f(pv.w);
        }
        __syncthreads();

        // ---- content score MMA: sc = (q+u) @ K^T  (warp: 16x32) ----
        float sc[4][4];
#pragma unroll
        for (int nf = 0; nf < 4; nf++)
#pragma unroll
            for (int e = 0; e < 4; e++) sc[nf][e] = 0.f;
        {
            const float* Aq = Qu + (16 * wr + g) * ST + t4;
            const float* Bk = Ks + (g + 32 * wc) * ST + t4;
#pragma unroll
            for (int kk = 0; kk < 8; kk++) {
                uint32_t a0 = fb(Aq[kk * 8]);
                uint32_t a1 = fb(Aq[8 * ST + kk * 8]);
                uint32_t a2 = fb(Aq[kk * 8 + 4]);
                uint32_t a3 = fb(Aq[8 * ST + kk * 8 + 4]);
#pragma unroll
                for (int nf = 0; nf < 4; nf++) {
                    uint32_t b0 = fb(Bk[nf * 8 * ST + kk * 8]);
                    uint32_t b1 = fb(Bk[nf * 8 * ST + kk * 8 + 4]);
                    mma_tf32(sc[nf], a0, a1, a2, a3, b0, b1);
                }
            }
        }

        // ---- positional score: G = Qv(+base) @ E^T, then diagonal gather ----
        const bool passA = (diag <= 0);
        const bool passB = (diag >= 0);
#pragma unroll 1
        for (int pass = 0; pass < 2; pass++) {
            if (pass == 0 && !passA) continue;
            if (pass == 1 && !passB) continue;
            if (pass == 1 && passA) __syncthreads();   // pass-A gathers done before G overwrite

            float ga[8][4];
#pragma unroll
            for (int nf = 0; nf < 8; nf++)
#pragma unroll
                for (int e = 0; e < 4; e++) ga[nf][e] = 0.f;
            {
                const float* Aq = Qv + (16 * wr + g + pass) * ST + t4;
                const float* Be = Es + (g + 64 * wc) * ST + t4;
#pragma unroll
                for (int kk = 0; kk < 8; kk++) {
                    uint32_t a0 = fb(Aq[kk * 8]);
                    uint32_t a1 = fb(Aq[8 * ST + kk * 8]);
                    uint32_t a2 = fb(Aq[kk * 8 + 4]);
                    uint32_t a3 = fb(Aq[8 * ST + kk * 8 + 4]);
#pragma unroll
                    for (int nf = 0; nf < 8; nf++) {
                        uint32_t b0 = fb(Be[nf * 8 * ST + kk * 8]);
                        uint32_t b1 = fb(Be[nf * 8 * ST + kk * 8 + 4]);
                        mma_tf32(ga[nf], a0, a1, a2, a3, b0, b1);
                    }
                }
            }
            // store G (64 x 128)
#pragma unroll
            for (int nf = 0; nf < 8; nf++)
#pragma unroll
                for (int e = 0; e < 4; e++) {
                    int row = 16 * wr + g + 8 * (e >> 1);
                    int col = 2 * t4 + (e & 1) + 8 * nf + 64 * wc;
                    Gs[row * GST + col] = ga[nf][e];
                }
            __syncthreads();
            // gather-add along diagonals
#pragma unroll
            for (int nf = 0; nf < 4; nf++)
#pragma unroll
                for (int e = 0; e < 4; e++) {
                    int ss = 16 * wr + g + 8 * (e >> 1);
                    int tt = 2 * t4 + (e & 1) + 8 * nf + 32 * wc;
                    int d  = diag + tt - ss;
                    bool take = pass ? (d >= 2) : (d <= 0);
                    if (take) sc[nf][e] += Gs[ss * GST + (tt - ss + 63)];
                }
        }

        // ---- online softmax (scale 0.125), cross-warp row reduction ----
#pragma unroll
        for (int nf = 0; nf < 4; nf++)
#pragma unroll
            for (int e = 0; e < 4; e++) sc[nf][e] *= 0.125f;

        float rmx[2] = {-1e30f, -1e30f};
#pragma unroll
        for (int nf = 0; nf < 4; nf++)
#pragma unroll
            for (int e = 0; e < 4; e++)
                rmx[e >> 1] = fmaxf(rmx[e >> 1], sc[nf][e]);
#pragma unroll
        for (int msk = 1; msk < 4; msk <<= 1) {
            rmx[0] = fmaxf(rmx[0], __shfl_xor_sync(0xffffffffu, rmx[0], msk));
            rmx[1] = fmaxf(rmx[1], __shfl_xor_sync(0xffffffffu, rmx[1], msk));
        }
        if (t4 == 0) {
            redmax[(16 * wr + g) * 2 + wc]     = rmx[0];
            redmax[(16 * wr + g + 8) * 2 + wc] = rmx[1];
        }
        __syncthreads();   // also separates all E reads/gathers from the Ps store below

        float mnew[2], corr[2];
#pragma unroll
        for (int h2 = 0; h2 < 2; h2++) {
            int row = 16 * wr + g + 8 * h2;
            float rm = fmaxf(redmax[row * 2], redmax[row * 2 + 1]);
            mnew[h2] = fmaxf(m_r[h2], rm);
            corr[h2] = __expf(m_r[h2] - mnew[h2]);
            m_r[h2]  = mnew[h2];
        }
        float rs[2] = {0.f, 0.f};
#pragma unroll
        for (int nf = 0; nf < 4; nf++)
#pragma unroll
            for (int e = 0; e < 4; e++) {
                float p = __expf(sc[nf][e] - mnew[e >> 1]);
                sc[nf][e] = p;
                rs[e >> 1] += p;
            }
#pragma unroll
        for (int msk = 1; msk < 4; msk <<= 1) {
            rs[0] += __shfl_xor_sync(0xffffffffu, rs[0], msk);
            rs[1] += __shfl_xor_sync(0xffffffffu, rs[1], msk);
        }
        if (t4 == 0) {
            redsum[(16 * wr + g) * 2 + wc]     = rs[0];
            redsum[(16 * wr + g + 8) * 2 + wc] = rs[1];
        }
        // store P (exp'd, unnormalized) for the PV MMA — into the Es alias
#pragma unroll
        for (int nf = 0; nf < 4; nf++)
#pragma unroll
            for (int e = 0; e < 4; e++) {
                int row = 16 * wr + g + 8 * (e >> 1);
                int col = 2 * t4 + (e & 1) + 8 * nf + 32 * wc;
                Ps[row * ST + col] = tf32f(sc[nf][e]);
            }
        __syncthreads();

#pragma unroll
        for (int h2 = 0; h2 < 2; h2++) {
            int row = 16 * wr + g + 8 * h2;
            l_r[h2] = l_r[h2] * corr[h2] + redsum[row * 2] + redsum[row * 2 + 1];
        }
#pragma unroll
        for (int nf = 0; nf < 4; nf++)
#pragma unroll
            for (int e = 0; e < 4; e++) acc[nf][e] *= corr[e >> 1];

        // ---- PV MMA: acc += P @ V  (warp: 16x32) ----
        {
            const float* Ap = Ps + (16 * wr + g) * ST + t4;
            const float* Bv = Vs + t4 * VST + g + 32 * wc;
#pragma unroll
            for (int kk = 0; kk < 8; kk++) {
                uint32_t a0 = fb(Ap[kk * 8]);
                uint32_t a1 = fb(Ap[8 * ST + kk * 8]);
                uint32_t a2 = fb(Ap[kk * 8 + 4]);
                uint32_t a3 = fb(Ap[8 * ST + kk * 8 + 4]);
#pragma unroll
                for (int nf = 0; nf < 4; nf++) {
                    uint32_t b0 = fb(Bv[(8 * kk) * VST + 8 * nf]);
                    uint32_t b1 = fb(Bv[(8 * kk + 4) * VST + 8 * nf]);
                    mma_tf32(acc[nf], a0, a1, a2, a3, b0, b1);
                }
            }
        }
    }

    // ---- epilogue: normalize, write [B,S,H,P] ----
    float inv[2] = {1.f / l_r[0], 1.f / l_r[1]};
#pragma unroll
    for (int nf = 0; nf < 4; nf++)
#pragma unroll
        for (int e = 0; e < 4; e++) {
            int srow = s0 + 16 * wr + g + 8 * (e >> 1);
            int p    = 2 * t4 + (e & 1) + 8 * nf + 32 * wc;
            OUT[(size_t)(b * S_LEN + srow) * EMBED + hoff + p] = acc[nf][e] * inv[e >> 1];
        }
}

// ---------------- launch ----------------
extern "C" void kernel_launch(void* const* d_in, const int* in_sizes, int n_in,
                              void* d_out, int out_size)
{
    const float* x   = (const float*)d_in[0];
    const float* Wq  = (const float*)d_in[1];
    const float* bq  = (const float*)d_in[2];
    const float* Wk  = (const float*)d_in[3];
    const float* bk  = (const float*)d_in[4];
    const float* Wv  = (const float*)d_in[5];
    const float* bv_ = (const float*)d_in[6];
    const float* Wp  = (const float*)d_in[7];
    const float* bp  = (const float*)d_in[8];
    const float* Wo  = (const float*)d_in[9];
    const float* bo  = (const float*)d_in[10];
    const float* u   = (const float*)d_in[11];
    const float* v   = (const float*)d_in[12];
    float* out = (float*)d_out;

    float *psin, *ppos, *pq, *pk, *pv, *pattn;
    cudaGetSymbolAddress((void**)&psin,  g_sin);
    cudaGetSymbolAddress((void**)&ppos,  g_pos);
    cudaGetSymbolAddress((void**)&pq,    g_q);
    cudaGetSymbolAddress((void**)&pk,    g_k);
    cudaGetSymbolAddress((void**)&pv,    g_v);
    cudaGetSymbolAddress((void**)&pattn, g_attn);

    cudaFuncSetAttribute(attn_kernel, cudaFuncAttributeMaxDynamicSharedMemorySize,
                         ATT_SMEM_FLOATS * 4);

    sinusoid_kernel<<<(S_LEN * (EMBED / 2) + 255) / 256, 256>>>();

    dim3 gBig(EMBED / 128, (BATCH * S_LEN) / 128);         // (8, 32)
    dim3 gQKV(EMBED / 128, (BATCH * S_LEN) / 128, 3);      // (8, 32, 3)
    dim3 gPos(EMBED / 128, S_LEN / 128);                   // (8, 16)

    gemm_bias_qkv_kernel<<<gQKV, 256>>>(x, Wq, bq, Wk, bk, Wv, bv_,
                                        pq, pk, pv, BATCH * S_LEN, EMBED, EMBED);
    gemm_bias_kernel<<<gPos, 256>>>(psin, Wp, bp, ppos, S_LEN, EMBED, EMBED);

    dim3 gAtt(S_LEN / 64, NHEAD, BATCH);                   // (32, 16, 2)
    attn_kernel<<<gAtt, 256, ATT_SMEM_FLOATS * 4>>>(pq, pk, pv, ppos, u, v, pattn);

    gemm_bias_kernel<<<gBig, 256>>>(pattn, Wo, bo, out, BATCH * S_LEN, EMBED, EMBED);
}

// round 8
// speedup vs baseline: 2.7333x; 1.6085x over previous
#include <cuda_runtime.h>
#include <math.h>
#include <stdint.h>

#define S_LEN 2048
#define BATCH 2
#define EMBED 1024
#define NHEAD 16
#define HDIM  64

// ---------------- scratch (static device globals; no allocation) ----------------
__device__ float g_sin[S_LEN * EMBED];          // sinusoid embedding  [S, D]
__device__ float g_pos[S_LEN * EMBED];          // pos projection      [S, D]
__device__ float g_q[BATCH * S_LEN * EMBED];    // Q  [B*S, D]
__device__ float g_k[BATCH * S_LEN * EMBED];    // K
__device__ float g_v[BATCH * S_LEN * EMBED];    // V
__device__ float g_attn[BATCH * S_LEN * EMBED]; // attention output (pre out-proj)

// ---------------- sinusoid position embedding ----------------
__global__ void sinusoid_kernel() {
    int idx = blockIdx.x * blockDim.x + threadIdx.x;
    if (idx >= S_LEN * (EMBED / 2)) return;
    int s = idx / (EMBED / 2);
    int i = idx % (EMBED / 2);
    double invf = exp(-(2.0 * (double)i / (double)EMBED) * log(10000.0));
    float ang = (float)s * (float)invf;
    double a = (double)ang;
    g_sin[s * EMBED + i]              = (float)sin(a);
    g_sin[s * EMBED + (EMBED/2) + i]  = (float)cos(a);
}

// ---------------- tf32 helpers ----------------
__device__ __forceinline__ float tf32f(float f) {
    uint32_t u;
    asm("cvt.rna.tf32.f32 %0, %1;" : "=r"(u) : "f"(f));
    return __uint_as_float(u);
}
__device__ __forceinline__ uint32_t fb(float f) { return __float_as_uint(f); }

__device__ __forceinline__ void mma_tf32(float* d,
    uint32_t a0, uint32_t a1, uint32_t a2, uint32_t a3,
    uint32_t b0, uint32_t b1)
{
    asm volatile(
        "mma.sync.aligned.m16n8k8.row.col.f32.tf32.tf32.f32 "
        "{%0,%1,%2,%3}, {%4,%5,%6,%7}, {%8,%9}, {%0,%1,%2,%3};"
        : "+f"(d[0]), "+f"(d[1]), "+f"(d[2]), "+f"(d[3])
        : "r"(a0), "r"(a1), "r"(a2), "r"(a3), "r"(b0), "r"(b1));
}

// ---------------- fp32 GEMM + bias (SIMT, known-good — used for out-proj only) ----------------
__global__ void __launch_bounds__(256) gemm_bias_kernel(
    const float* __restrict__ A, const float* __restrict__ B,
    const float* __restrict__ bias, float* __restrict__ C,
    int M, int N, int K)
{
    __shared__ float As[8][128];
    __shared__ float Bs[8][128];
    int tid = threadIdx.x;
    int tx = tid & 15, ty = tid >> 4;
    int bx = blockIdx.x, by = blockIdx.y;

    float acc[8][8];
#pragma unroll
    for (int i = 0; i < 8; i++)
#pragma unroll
        for (int j = 0; j < 8; j++) acc[i][j] = 0.f;

    int arow = tid >> 1;
    int acol = (tid & 1) * 4;
    int brow = tid >> 5;
    int bcol = (tid & 31) * 4;
    const float* Ap = A + (size_t)(by * 128 + arow) * K + acol;
    const float* Bp = B + (size_t)brow * N + bx * 128 + bcol;

    for (int k0 = 0; k0 < K; k0 += 8) {
        float4 av = *(const float4*)(Ap + k0);
        float4 bv = *(const float4*)(Bp + (size_t)k0 * N);
        __syncthreads();
        As[acol + 0][arow] = av.x;
        As[acol + 1][arow] = av.y;
        As[acol + 2][arow] = av.z;
        As[acol + 3][arow] = av.w;
        *(float4*)&Bs[brow][bcol] = bv;
        __syncthreads();
#pragma unroll
        for (int kk = 0; kk < 8; kk++) {
            float a[8], b[8];
            *(float4*)&a[0] = *(const float4*)&As[kk][ty * 8];
            *(float4*)&a[4] = *(const float4*)&As[kk][ty * 8 + 4];
            *(float4*)&b[0] = *(const float4*)&Bs[kk][tx * 8];
            *(float4*)&b[4] = *(const float4*)&Bs[kk][tx * 8 + 4];
#pragma unroll
            for (int i = 0; i < 8; i++)
#pragma unroll
                for (int j = 0; j < 8; j++)
                    acc[i][j] += a[i] * b[j];
        }
    }
#pragma unroll
    for (int i = 0; i < 8; i++) {
        int row = by * 128 + ty * 8 + i;
        float* Cp = C + (size_t)row * N + bx * 128 + tx * 8;
#pragma unroll
        for (int j = 0; j < 8; j++)
            Cp[j] = acc[i][j] + bias[bx * 128 + tx * 8 + j];
    }
}

// ---------------- tf32 tensor-core GEMM + bias ----------------
// BM=BN=128, BK=16, 256 threads (8 warps: wr 0..1 x wc 0..3), warp tile 64x32.
// A smem [row][k] stride 20 (conflict-free frag reads: banks 20g+t4 distinct).
// B smem [k][n] stride 136 (frag reads: banks 8*t4+g distinct).
__device__ __forceinline__ void gemm_tf32_body(
    const float* __restrict__ A, const float* __restrict__ B,
    const float* __restrict__ bias, float* __restrict__ C,
    int M, int N, int K)
{
    __shared__ float As[128 * 20];
    __shared__ float Bs[16 * 136];
    const int tid  = threadIdx.x;
    const int lane = tid & 31;
    const int wid  = tid >> 5;
    const int wr   = wid >> 2;       // 0..1
    const int wc   = wid & 3;        // 0..3
    const int g    = lane >> 2;      // 0..7
    const int t4   = lane & 3;       // 0..3
    const int m0   = blockIdx.y * 128;
    const int n0   = blockIdx.x * 128;

    float acc[4][4][4];
#pragma unroll
    for (int mf = 0; mf < 4; mf++)
#pragma unroll
        for (int nf = 0; nf < 4; nf++)
#pragma unroll
            for (int e = 0; e < 4; e++) acc[mf][nf][e] = 0.f;

    const int a_row = tid >> 2;          // 0..63 (+64 second)
    const int a_k4  = (tid & 3) * 4;     // 0,4,8,12
    const int b_k   = tid >> 4;          // 0..15
    const int b_n4  = (tid & 15) * 4;    // 0..60 (+64 second)

    const float* Ap = A + (size_t)(m0 + a_row) * K + a_k4;
    const float* Bp = B + (size_t)b_k * N + n0 + b_n4;

    for (int k0 = 0; k0 < K; k0 += 16) {
        float4 av0 = *(const float4*)(Ap + k0);
        float4 av1 = *(const float4*)(Ap + (size_t)64 * K + k0);
        float4 bv0 = *(const float4*)(Bp + (size_t)k0 * N);
        float4 bv1 = *(const float4*)(Bp + (size_t)k0 * N + 64);
        __syncthreads();
        float* as0 = As + a_row * 20 + a_k4;
        as0[0] = tf32f(av0.x); as0[1] = tf32f(av0.y);
        as0[2] = tf32f(av0.z); as0[3] = tf32f(av0.w);
        float* as1 = As + (a_row + 64) * 20 + a_k4;
        as1[0] = tf32f(av1.x); as1[1] = tf32f(av1.y);
        as1[2] = tf32f(av1.z); as1[3] = tf32f(av1.w);
        float* bs0 = Bs + b_k * 136 + b_n4;
        bs0[0] = tf32f(bv0.x); bs0[1] = tf32f(bv0.y);
        bs0[2] = tf32f(bv0.z); bs0[3] = tf32f(bv0.w);
        float* bs1 = bs0 + 64;
        bs1[0] = tf32f(bv1.x); bs1[1] = tf32f(bv1.y);
        bs1[2] = tf32f(bv1.z); bs1[3] = tf32f(bv1.w);
        __syncthreads();
#pragma unroll
        for (int kk = 0; kk < 2; kk++) {
            uint32_t af[4][4];
#pragma unroll
            for (int mf = 0; mf < 4; mf++) {
                const float* pa = As + (64 * wr + 16 * mf + g) * 20 + 8 * kk + t4;
                af[mf][0] = fb(pa[0]);
                af[mf][1] = fb(pa[8 * 20]);
                af[mf][2] = fb(pa[4]);
                af[mf][3] = fb(pa[8 * 20 + 4]);
            }
#pragma unroll
            for (int nf = 0; nf < 4; nf++) {
                const float* pb = Bs + (8 * kk + t4) * 136 + 32 * wc + 8 * nf + g;
                uint32_t b0 = fb(pb[0]);
                uint32_t b1 = fb(pb[4 * 136]);
#pragma unroll
                for (int mf = 0; mf < 4; mf++)
                    mma_tf32(acc[mf][nf], af[mf][0], af[mf][1], af[mf][2], af[mf][3], b0, b1);
            }
        }
    }
    // epilogue: d0,d1 are adjacent cols -> float2 stores
#pragma unroll
    for (int mf = 0; mf < 4; mf++)
#pragma unroll
        for (int nf = 0; nf < 4; nf++)
#pragma unroll
            for (int h2 = 0; h2 < 2; h2++) {
                int row = m0 + 64 * wr + 16 * mf + g + 8 * h2;
                int col = n0 + 32 * wc + 8 * nf + 2 * t4;
                float2 o;
                o.x = acc[mf][nf][2 * h2 + 0] + bias[col];
                o.y = acc[mf][nf][2 * h2 + 1] + bias[col + 1];
                *(float2*)&C[(size_t)row * N + col] = o;
            }
}

__global__ void __launch_bounds__(256, 2) gemm_tf32_kernel(
    const float* __restrict__ A, const float* __restrict__ B,
    const float* __restrict__ bias, float* __restrict__ C,
    int M, int N, int K)
{
    gemm_tf32_body(A, B, bias, C, M, N, K);
}

__global__ void __launch_bounds__(256, 2) gemm_tf32_qkv_kernel(
    const float* __restrict__ A,
    const float* __restrict__ W0, const float* __restrict__ c0,
    const float* __restrict__ W1, const float* __restrict__ c1,
    const float* __restrict__ W2, const float* __restrict__ c2,
    float* __restrict__ O0, float* __restrict__ O1, float* __restrict__ O2,
    int M, int N, int K)
{
    const float* B; const float* bias; float* C;
    if (blockIdx.z == 0)      { B = W0; bias = c0; C = O0; }
    else if (blockIdx.z == 1) { B = W1; bias = c1; C = O1; }
    else                      { B = W2; bias = c2; C = O2; }
    gemm_tf32_body(A, B, bias, C, M, N, K);
}

// ---------------- fused relative attention (tf32 tensor-core flash) ----------------
// Relative shift:  d = t - s
//   d <= 0 : (q+v)[s]   . pos[S-1+d]
//   d == 1 : 0
//   d >= 2 : (q+v)[s+1] . pos[d-2]
// Band E[r] = POSROW(d = diag-63+r), r in [0,126]; gather index r = tt-ss+63.
//
// smem: E, G, and Ps all SHARE one region (disjoint lifetimes):
//   E loaded -> G-MMA reads E -> [bar] -> G store overwrites E -> [bar] ->
//   gather reads G -> [redmax bar] -> Ps store overwrites G -> [bar] -> PV reads Ps
//   -> loop-top bar -> next E load. Only the diag==0 tile runs both passes and
//   must RELOAD E between them. Row 127 of E (zero pad) lives above both G
//   (64*132=8448) and Ps (64*68=4352) so its prologue zero survives.
// Total 26,692 floats = 106,768 B -> 2 blocks/SM.
#define ST  68
#define VST 72
#define GST 132
#define AOFF_QU  0               // 64*68  = 4352
#define AOFF_QV  4352            // 65*68  = 4420
#define AOFF_KS  8772            // 64*68  = 4352
#define AOFF_VS  13124           // 64*72  = 4608
#define AOFF_E   17732           // 128*68 = 8704  (G and Ps alias this)
#define AOFF_RMX 26436           // 128
#define AOFF_RSM 26564           // 128
#define ATT_SMEM_FLOATS 26692    // 106768 bytes

__global__ void __launch_bounds__(256, 2) attn_kernel(
    const float* __restrict__ Q, const float* __restrict__ Km,
    const float* __restrict__ Vm, const float* __restrict__ POS,
    const float* __restrict__ ub, const float* __restrict__ vbias,
    float* __restrict__ OUT)
{
    extern __shared__ float sm[];
    float* Qu = sm + AOFF_QU;
    float* Qv = sm + AOFF_QV;
    float* Ks = sm + AOFF_KS;
    float* Vs = sm + AOFF_VS;
    float* Es = sm + AOFF_E;
    float* Gs = sm + AOFF_E;     // alias
    float* Ps = sm + AOFF_E;     // alias
    float* redmax = sm + AOFF_RMX;
    float* redsum = sm + AOFF_RSM;

    const int tid  = threadIdx.x;
    const int lane = tid & 31;
    const int wid  = tid >> 5;
    const int wr   = wid >> 1;     // 0..3 : row group (16 rows)
    const int wc   = wid & 1;      // 0..1 : col group (32 cols / 64 G-cols)
    const int g    = lane >> 2;    // 0..7
    const int t4   = lane & 3;     // 0..3

    const int s0   = blockIdx.x * 64;
    const int h    = blockIdx.y;
    const int b    = blockIdx.z;
    const int hoff = h * HDIM;

    // ---- prologue ----
    if (tid < ST) Es[127 * ST + tid] = 0.f;
    for (int q4 = tid; q4 < 65 * 16; q4 += 256) {
        int row = q4 >> 4;
        int p4  = (q4 & 15) * 4;
        int s   = s0 + row; if (s > S_LEN - 1) s = S_LEN - 1;
        float4 qv = *(const float4*)(Q + (size_t)(b * S_LEN + s) * EMBED + hoff + p4);
        float4 uu = *(const float4*)(ub + hoff + p4);
        float4 vv = *(const float4*)(vbias + hoff + p4);
        float qa[4] = {qv.x, qv.y, qv.z, qv.w};
        float ua[4] = {uu.x, uu.y, uu.z, uu.w};
        float va[4] = {vv.x, vv.y, vv.z, vv.w};
#pragma unroll
        for (int i = 0; i < 4; i++) {
            if (row < 64) Qu[row * ST + p4 + i] = tf32f(qa[i] + ua[i]);
            Qv[row * ST + p4 + i] = tf32f(qa[i] + va[i]);
        }
    }

    float acc[4][4];
    float m_r[2], l_r[2];
#pragma unroll
    for (int nf = 0; nf < 4; nf++)
#pragma unroll
        for (int e = 0; e < 4; e++) acc[nf][e] = 0.f;
    m_r[0] = m_r[1] = -1e30f;
    l_r[0] = l_r[1] = 0.f;

    for (int t0 = 0; t0 < S_LEN; t0 += 64) {
        const int diag = t0 - s0;
        __syncthreads();   // prev iteration's PV (Ps) reads complete

        // ---- load K, V tiles (tf32-rounded) ----
        for (int q4 = tid; q4 < 64 * 16; q4 += 256) {
            int row = q4 >> 4;
            int p4  = (q4 & 15) * 4;
            size_t go = (size_t)(b * S_LEN + t0 + row) * EMBED + hoff + p4;
            float4 kv = *(const float4*)(Km + go);
            float4 vv = *(const float4*)(Vm + go);
            Ks[row * ST + p4 + 0] = tf32f(kv.x);
            Ks[row * ST + p4 + 1] = tf32f(kv.y);
            Ks[row * ST + p4 + 2] = tf32f(kv.z);
            Ks[row * ST + p4 + 3] = tf32f(kv.w);
            Vs[row * VST + p4 + 0] = tf32f(vv.x);
            Vs[row * VST + p4 + 1] = tf32f(vv.y);
            Vs[row * VST + p4 + 2] = tf32f(vv.z);
            Vs[row * VST + p4 + 3] = tf32f(vv.w);
        }
        // ---- load pos band E (127 rows) ----
        for (int q4 = tid; q4 < 127 * 16; q4 += 256) {
            int r  = q4 >> 4;
            int p4 = (q4 & 15) * 4;
            int d  = diag - 63 + r;
            int c  = (d <= 0) ? (S_LEN - 1 + d) : ((d == 1) ? -1 : (d - 2));
            float4 pv = make_float4(0.f, 0.f, 0.f, 0.f);
            if (c >= 0)
                pv = *(const float4*)(POS + (size_t)c * EMBED + hoff + p4);
            Es[r * ST + p4 + 0] = tf32f(pv.x);
            Es[r * ST + p4 + 1] = tf32f(pv.y);
            Es[r * ST + p4 + 2] = tf32f(pv.z);
            Es[r * ST + p4 + 3] = tf32f(pv.w);
        }
        __syncthreads();

        // ---- content score MMA: sc = (q+u) @ K^T  (warp: 16x32) ----
        float sc[4][4];
#pragma unroll
        for (int nf = 0; nf < 4; nf++)
#pragma unroll
            for (int e = 0; e < 4; e++) sc[nf][e] = 0.f;
        {
            const float* Aq = Qu + (16 * wr + g) * ST + t4;
            const float* Bk = Ks + (g + 32 * wc) * ST + t4;
#pragma unroll
            for (int kk = 0; kk < 8; kk++) {
                uint32_t a0 = fb(Aq[kk * 8]);
                uint32_t a1 = fb(Aq[8 * ST + kk * 8]);
                uint32_t a2 = fb(Aq[kk * 8 + 4]);
                uint32_t a3 = fb(Aq[8 * ST + kk * 8 + 4]);
#pragma unroll
                for (int nf = 0; nf < 4; nf++) {
                    uint32_t b0 = fb(Bk[nf * 8 * ST + kk * 8]);
                    uint32_t b1 = fb(Bk[nf * 8 * ST + kk * 8 + 4]);
                    mma_tf32(sc[nf], a0, a1, a2, a3, b0, b1);
                }
            }
        }

        // ---- positional score: G = Qv(+base) @ E^T, diagonal gather ----
        const bool passA = (diag <= 0);
        const bool passB = (diag >= 0);
#pragma unroll 1
        for (int pass = 0; pass < 2; pass++) {
            if (pass == 0 && !passA) continue;
            if (pass == 1 && !passB) continue;
            if (pass == 1 && passA) {
                // diag==0 tile only: E was overwritten by pass-0's G; reload.
                __syncthreads();    // pass-0 gather reads of G complete
                for (int q4 = tid; q4 < 127 * 16; q4 += 256) {
                    int r  = q4 >> 4;
                    int p4 = (q4 & 15) * 4;
                    int d  = diag - 63 + r;
                    int c  = (d <= 0) ? (S_LEN - 1 + d) : ((d == 1) ? -1 : (d - 2));
                    float4 pv = make_float4(0.f, 0.f, 0.f, 0.f);
                    if (c >= 0)
                        pv = *(const float4*)(POS + (size_t)c * EMBED + hoff + p4);
                    Es[r * ST + p4 + 0] = tf32f(pv.x);
                    Es[r * ST + p4 + 1] = tf32f(pv.y);
                    Es[r * ST + p4 + 2] = tf32f(pv.z);
                    Es[r * ST + p4 + 3] = tf32f(pv.w);
                }
                __syncthreads();
            }

            float ga[8][4];
#pragma unroll
            for (int nf = 0; nf < 8; nf++)
#pragma unroll
                for (int e = 0; e < 4; e++) ga[nf][e] = 0.f;
            {
                const float* Aq = Qv + (16 * wr + g + pass) * ST + t4;
                const float* Be = Es + (g + 64 * wc) * ST + t4;
#pragma unroll
                for (int kk = 0; kk < 8; kk++) {
                    uint32_t a0 = fb(Aq[kk * 8]);
                    uint32_t a1 = fb(Aq[8 * ST + kk * 8]);
                    uint32_t a2 = fb(Aq[kk * 8 + 4]);
                    uint32_t a3 = fb(Aq[8 * ST + kk * 8 + 4]);
#pragma unroll
                    for (int nf = 0; nf < 8; nf++) {
                        uint32_t b0 = fb(Be[nf * 8 * ST + kk * 8]);
                        uint32_t b1 = fb(Be[nf * 8 * ST + kk * 8 + 4]);
                        mma_tf32(ga[nf], a0, a1, a2, a3, b0, b1);
                    }
                }
            }
            __syncthreads();   // ALL warps done reading E before G overwrites it
            // store G (64 x 128) into the E region
#pragma unroll
            for (int nf = 0; nf < 8; nf++)
#pragma unroll
                for (int e = 0; e < 4; e++) {
                    int row = 16 * wr + g + 8 * (e >> 1);
                    int col = 2 * t4 + (e & 1) + 8 * nf + 64 * wc;
                    Gs[row * GST + col] = ga[nf][e];
                }
            __syncthreads();
            // gather-add along diagonals
#pragma unroll
            for (int nf = 0; nf < 4; nf++)
#pragma unroll
                for (int e = 0; e < 4; e++) {
                    int ss = 16 * wr + g + 8 * (e >> 1);
                    int tt = 2 * t4 + (e & 1) + 8 * nf + 32 * wc;
                    int d  = diag + tt - ss;
                    bool take = pass ? (d >= 2) : (d <= 0);
                    if (take) sc[nf][e] += Gs[ss * GST + (tt - ss + 63)];
                }
        }

        // ---- online softmax (scale 0.125), cross-warp row reduction ----
#pragma unroll
        for (int nf = 0; nf < 4; nf++)
#pragma unroll
            for (int e = 0; e < 4; e++) sc[nf][e] *= 0.125f;

        float rmx[2] = {-1e30f, -1e30f};
#pragma unroll
        for (int nf = 0; nf < 4; nf++)
#pragma unroll
            for (int e = 0; e < 4; e++)
                rmx[e >> 1] = fmaxf(rmx[e >> 1], sc[nf][e]);
#pragma unroll
        for (int msk = 1; msk < 4; msk <<= 1) {
            rmx[0] = fmaxf(rmx[0], __shfl_xor_sync(0xffffffffu, rmx[0], msk));
            rmx[1] = fmaxf(rmx[1], __shfl_xor_sync(0xffffffffu, rmx[1], msk));
        }
        if (t4 == 0) {
            redmax[(16 * wr + g) * 2 + wc]     = rmx[0];
            redmax[(16 * wr + g + 8) * 2 + wc] = rmx[1];
        }
        __syncthreads();   // gather reads done; redmax visible; Ps store safe after

        float mnew[2], corr[2];
#pragma unroll
        for (int h2 = 0; h2 < 2; h2++) {
            int row = 16 * wr + g + 8 * h2;
            float rm = fmaxf(redmax[row * 2], redmax[row * 2 + 1]);
            mnew[h2] = fmaxf(m_r[h2], rm);
            corr[h2] = __expf(m_r[h2] - mnew[h2]);
            m_r[h2]  = mnew[h2];
        }
        float rs[2] = {0.f, 0.f};
#pragma unroll
        for (int nf = 0; nf < 4; nf++)
#pragma unroll
            for (int e = 0; e < 4; e++) {
                float p = __expf(sc[nf][e] - mnew[e >> 1]);
                sc[nf][e] = p;
                rs[e >> 1] += p;
            }
#pragma unroll
        for (int msk = 1; msk < 4; msk <<= 1) {
            rs[0] += __shfl_xor_sync(0xffffffffu, rs[0], msk);
            rs[1] += __shfl_xor_sync(0xffffffffu, rs[1], msk);
        }
        if (t4 == 0) {
            redsum[(16 * wr + g) * 2 + wc]     = rs[0];
            redsum[(16 * wr + g + 8) * 2 + wc] = rs[1];
        }
        // store P (exp'd, unnormalized) — into the shared E/G region
#pragma unroll
        for (int nf = 0; nf < 4; nf++)
#pragma unroll
            for (int e = 0; e < 4; e++) {
                int row = 16 * wr + g + 8 * (e >> 1);
                int col = 2 * t4 + (e & 1) + 8 * nf + 32 * wc;
                Ps[row * ST + col] = tf32f(sc[nf][e]);
            }
        __syncthreads();

#pragma unroll
        for (int h2 = 0; h2 < 2; h2++) {
            int row = 16 * wr + g + 8 * h2;
            l_r[h2] = l_r[h2] * corr[h2] + redsum[row * 2] + redsum[row * 2 + 1];
        }
#pragma unroll
        for (int nf = 0; nf < 4; nf++)
#pragma unroll
            for (int e = 0; e < 4; e++) acc[nf][e] *= corr[e >> 1];

        // ---- PV MMA: acc += P @ V  (warp: 16x32) ----
        {
            const float* Ap = Ps + (16 * wr + g) * ST + t4;
            const float* Bv = Vs + t4 * VST + g + 32 * wc;
#pragma unroll
            for (int kk = 0; kk < 8; kk++) {
                uint32_t a0 = fb(Ap[kk * 8]);
                uint32_t a1 = fb(Ap[8 * ST + kk * 8]);
                uint32_t a2 = fb(Ap[kk * 8 + 4]);
                uint32_t a3 = fb(Ap[8 * ST + kk * 8 + 4]);
#pragma unroll
                for (int nf = 0; nf < 4; nf++) {
                    uint32_t b0 = fb(Bv[(8 * kk) * VST + 8 * nf]);
                    uint32_t b1 = fb(Bv[(8 * kk + 4) * VST + 8 * nf]);
                    mma_tf32(acc[nf], a0, a1, a2, a3, b0, b1);
                }
            }
        }
    }

    // ---- epilogue: normalize, write [B,S,H,P] ----
    float inv[2] = {1.f / l_r[0], 1.f / l_r[1]};
#pragma unroll
    for (int nf = 0; nf < 4; nf++)
#pragma unroll
        for (int e = 0; e < 4; e++) {
            int srow = s0 + 16 * wr + g + 8 * (e >> 1);
            int p    = 2 * t4 + (e & 1) + 8 * nf + 32 * wc;
            OUT[(size_t)(b * S_LEN + srow) * EMBED + hoff + p] = acc[nf][e] * inv[e >> 1];
        }
}

// ---------------- launch ----------------
extern "C" void kernel_launch(void* const* d_in, const int* in_sizes, int n_in,
                              void* d_out, int out_size)
{
    const float* x   = (const float*)d_in[0];
    const float* Wq  = (const float*)d_in[1];
    const float* bq  = (const float*)d_in[2];
    const float* Wk  = (const float*)d_in[3];
    const float* bk  = (const float*)d_in[4];
    const float* Wv  = (const float*)d_in[5];
    const float* bv_ = (const float*)d_in[6];
    const float* Wp  = (const float*)d_in[7];
    const float* bp  = (const float*)d_in[8];
    const float* Wo  = (const float*)d_in[9];
    const float* bo  = (const float*)d_in[10];
    const float* u   = (const float*)d_in[11];
    const float* v   = (const float*)d_in[12];
    float* out = (float*)d_out;

    float *psin, *ppos, *pq, *pk, *pv, *pattn;
    cudaGetSymbolAddress((void**)&psin,  g_sin);
    cudaGetSymbolAddress((void**)&ppos,  g_pos);
    cudaGetSymbolAddress((void**)&pq,    g_q);
    cudaGetSymbolAddress((void**)&pk,    g_k);
    cudaGetSymbolAddress((void**)&pv,    g_v);
    cudaGetSymbolAddress((void**)&pattn, g_attn);

    cudaFuncSetAttribute(attn_kernel, cudaFuncAttributeMaxDynamicSharedMemorySize,
                         ATT_SMEM_FLOATS * 4);

    sinusoid_kernel<<<(S_LEN * (EMBED / 2) + 255) / 256, 256>>>();

    dim3 gBig(EMBED / 128, (BATCH * S_LEN) / 128);         // (8, 32)
    dim3 gQKV(EMBED / 128, (BATCH * S_LEN) / 128, 3);      // (8, 32, 3)
    dim3 gPos(EMBED / 128, S_LEN / 128);                   // (8, 16)

    gemm_tf32_qkv_kernel<<<gQKV, 256>>>(x, Wq, bq, Wk, bk, Wv, bv_,
                                        pq, pk, pv, BATCH * S_LEN, EMBED, EMBED);
    gemm_tf32_kernel<<<gPos, 256>>>(psin, Wp, bp, ppos, S_LEN, EMBED, EMBED);

    dim3 gAtt(S_LEN / 64, NHEAD, BATCH);                   // (32, 16, 2)
    attn_kernel<<<gAtt, 256, ATT_SMEM_FLOATS * 4>>>(pq, pk, pv, ppos, u, v, pattn);

    gemm_bias_kernel<<<gBig, 256>>>(pattn, Wo, bo, out, BATCH * S_LEN, EMBED, EMBED);
}

// round 9
// speedup vs baseline: 3.2342x; 1.1832x over previous
#include <cuda_runtime.h>
#include <cuda_fp16.h>
#include <math.h>
#include <stdint.h>

#define S_LEN 2048
#define BATCH 2
#define EMBED 1024
#define NHEAD 16
#define HDIM  64

// ---------------- scratch (static device globals; no allocation) ----------------
__device__ float g_sin[S_LEN * EMBED];
__device__ float g_pos[S_LEN * EMBED];
__device__ float g_q[BATCH * S_LEN * EMBED];
__device__ float g_k[BATCH * S_LEN * EMBED];
__device__ float g_v[BATCH * S_LEN * EMBED];
__device__ float g_attn[BATCH * S_LEN * EMBED];
__device__ float g_uk[BATCH * NHEAD * S_LEN];   // u . k_t   per (b,h,t)
__device__ float g_ve[NHEAD * S_LEN];           // v . pos_c per (h,c)

// ---------------- sinusoid position embedding ----------------
__global__ void sinusoid_kernel() {
    int idx = blockIdx.x * blockDim.x + threadIdx.x;
    if (idx >= S_LEN * (EMBED / 2)) return;
    int s = idx / (EMBED / 2);
    int i = idx % (EMBED / 2);
    double invf = exp(-(2.0 * (double)i / (double)EMBED) * log(10000.0));
    float ang = (float)s * (float)invf;
    double a = (double)ang;
    g_sin[s * EMBED + i]              = (float)sin(a);
    g_sin[s * EMBED + (EMBED/2) + i]  = (float)cos(a);
}

// ---------------- UK/VE precompute: one warp per dot-64 (fp32 exact) ----------------
__global__ void ukve_kernel(const float* __restrict__ K, const float* __restrict__ POS,
                            const float* __restrict__ u, const float* __restrict__ v)
{
    int w    = (blockIdx.x * blockDim.x + threadIdx.x) >> 5;
    int lane = threadIdx.x & 31;
    const int UKW = BATCH * NHEAD * S_LEN;
    if (w < UKW) {
        int t = w & (S_LEN - 1);
        int h = (w >> 11) & (NHEAD - 1);
        int b = w >> 15;
        const float* kp = K + ((size_t)(b * S_LEN + t)) * EMBED + h * HDIM;
        const float* up = u + h * HDIM;
        float s = kp[lane] * up[lane] + kp[lane + 32] * up[lane + 32];
#pragma unroll
        for (int m = 16; m; m >>= 1) s += __shfl_xor_sync(~0u, s, m);
        if (!lane) g_uk[w] = s;
    } else if (w < UKW + NHEAD * S_LEN) {
        int w2 = w - UKW;
        int c = w2 & (S_LEN - 1);
        int h = w2 >> 11;
        const float* pp = POS + (size_t)c * EMBED + h * HDIM;
        const float* vp = v + h * HDIM;
        float s = pp[lane] * vp[lane] + pp[lane + 32] * vp[lane + 32];
#pragma unroll
        for (int m = 16; m; m >>= 1) s += __shfl_xor_sync(~0u, s, m);
        if (!lane) g_ve[w2] = s;
    }
}

// ---------------- helpers ----------------
__device__ __forceinline__ float tf32f(float f) {
    uint32_t u;
    asm("cvt.rna.tf32.f32 %0, %1;" : "=r"(u) : "f"(f));
    return __uint_as_float(u);
}
__device__ __forceinline__ uint32_t fb(float f) { return __float_as_uint(f); }
__device__ __forceinline__ uint32_t h2(float x, float y) {
    __half2 h = __floats2half2_rn(x, y);
    return *(uint32_t*)&h;
}
__device__ __forceinline__ void mma_tf32(float* d,
    uint32_t a0, uint32_t a1, uint32_t a2, uint32_t a3, uint32_t b0, uint32_t b1)
{
    asm volatile(
        "mma.sync.aligned.m16n8k8.row.col.f32.tf32.tf32.f32 "
        "{%0,%1,%2,%3}, {%4,%5,%6,%7}, {%8,%9}, {%0,%1,%2,%3};"
        : "+f"(d[0]), "+f"(d[1]), "+f"(d[2]), "+f"(d[3])
        : "r"(a0), "r"(a1), "r"(a2), "r"(a3), "r"(b0), "r"(b1));
}
__device__ __forceinline__ void mma_f16(float* d,
    uint32_t a0, uint32_t a1, uint32_t a2, uint32_t a3, uint32_t b0, uint32_t b1)
{
    asm volatile(
        "mma.sync.aligned.m16n8k16.row.col.f32.f16.f16.f32 "
        "{%0,%1,%2,%3}, {%4,%5,%6,%7}, {%8,%9}, {%0,%1,%2,%3};"
        : "+f"(d[0]), "+f"(d[1]), "+f"(d[2]), "+f"(d[3])
        : "r"(a0), "r"(a1), "r"(a2), "r"(a3), "r"(b0), "r"(b1));
}

// ---------------- fp32 GEMM + bias (SIMT — out-proj only, protects error budget) ----------------
__global__ void __launch_bounds__(256) gemm_bias_kernel(
    const float* __restrict__ A, const float* __restrict__ B,
    const float* __restrict__ bias, float* __restrict__ C,
    int M, int N, int K)
{
    __shared__ float As[8][128];
    __shared__ float Bs[8][128];
    int tid = threadIdx.x;
    int tx = tid & 15, ty = tid >> 4;
    int bx = blockIdx.x, by = blockIdx.y;

    float acc[8][8];
#pragma unroll
    for (int i = 0; i < 8; i++)
#pragma unroll
        for (int j = 0; j < 8; j++) acc[i][j] = 0.f;

    int arow = tid >> 1;
    int acol = (tid & 1) * 4;
    int brow = tid >> 5;
    int bcol = (tid & 31) * 4;
    const float* Ap = A + (size_t)(by * 128 + arow) * K + acol;
    const float* Bp = B + (size_t)brow * N + bx * 128 + bcol;

    for (int k0 = 0; k0 < K; k0 += 8) {
        float4 av = *(const float4*)(Ap + k0);
        float4 bv = *(const float4*)(Bp + (size_t)k0 * N);
        __syncthreads();
        As[acol + 0][arow] = av.x;
        As[acol + 1][arow] = av.y;
        As[acol + 2][arow] = av.z;
        As[acol + 3][arow] = av.w;
        *(float4*)&Bs[brow][bcol] = bv;
        __syncthreads();
#pragma unroll
        for (int kk = 0; kk < 8; kk++) {
            float a[8], b[8];
            *(float4*)&a[0] = *(const float4*)&As[kk][ty * 8];
            *(float4*)&a[4] = *(const float4*)&As[kk][ty * 8 + 4];
            *(float4*)&b[0] = *(const float4*)&Bs[kk][tx * 8];
            *(float4*)&b[4] = *(const float4*)&Bs[kk][tx * 8 + 4];
#pragma unroll
            for (int i = 0; i < 8; i++)
#pragma unroll
                for (int j = 0; j < 8; j++)
                    acc[i][j] += a[i] * b[j];
        }
    }
#pragma unroll
    for (int i = 0; i < 8; i++) {
        int row = by * 128 + ty * 8 + i;
        float* Cp = C + (size_t)row * N + bx * 128 + tx * 8;
#pragma unroll
        for (int j = 0; j < 8; j++)
            Cp[j] = acc[i][j] + bias[bx * 128 + tx * 8 + j];
    }
}

// ---------------- tf32 tensor-core GEMM + bias (projections) ----------------
__device__ __forceinline__ void gemm_tf32_body(
    const float* __restrict__ A, const float* __restrict__ B,
    const float* __restrict__ bias, float* __restrict__ C,
    int M, int N, int K)
{
    __shared__ float As[128 * 20];
    __shared__ float Bs[16 * 136];
    const int tid  = threadIdx.x;
    const int lane = tid & 31;
    const int wid  = tid >> 5;
    const int wr   = wid >> 2;
    const int wc   = wid & 3;
    const int g    = lane >> 2;
    const int t4   = lane & 3;
    const int m0   = blockIdx.y * 128;
    const int n0   = blockIdx.x * 128;

    float acc[4][4][4];
#pragma unroll
    for (int mf = 0; mf < 4; mf++)
#pragma unroll
        for (int nf = 0; nf < 4; nf++)
#pragma unroll
            for (int e = 0; e < 4; e++) acc[mf][nf][e] = 0.f;

    const int a_row = tid >> 2;
    const int a_k4  = (tid & 3) * 4;
    const int b_k   = tid >> 4;
    const int b_n4  = (tid & 15) * 4;

    const float* Ap = A + (size_t)(m0 + a_row) * K + a_k4;
    const float* Bp = B + (size_t)b_k * N + n0 + b_n4;

    for (int k0 = 0; k0 < K; k0 += 16) {
        float4 av0 = *(const float4*)(Ap + k0);
        float4 av1 = *(const float4*)(Ap + (size_t)64 * K + k0);
        float4 bv0 = *(const float4*)(Bp + (size_t)k0 * N);
        float4 bv1 = *(const float4*)(Bp + (size_t)k0 * N + 64);
        __syncthreads();
        float* as0 = As + a_row * 20 + a_k4;
        as0[0] = tf32f(av0.x); as0[1] = tf32f(av0.y);
        as0[2] = tf32f(av0.z); as0[3] = tf32f(av0.w);
        float* as1 = As + (a_row + 64) * 20 + a_k4;
        as1[0] = tf32f(av1.x); as1[1] = tf32f(av1.y);
        as1[2] = tf32f(av1.z); as1[3] = tf32f(av1.w);
        float* bs0 = Bs + b_k * 136 + b_n4;
        bs0[0] = tf32f(bv0.x); bs0[1] = tf32f(bv0.y);
        bs0[2] = tf32f(bv0.z); bs0[3] = tf32f(bv0.w);
        float* bs1 = bs0 + 64;
        bs1[0] = tf32f(bv1.x); bs1[1] = tf32f(bv1.y);
        bs1[2] = tf32f(bv1.z); bs1[3] = tf32f(bv1.w);
        __syncthreads();
#pragma unroll
        for (int kk = 0; kk < 2; kk++) {
            uint32_t af[4][4];
#pragma unroll
            for (int mf = 0; mf < 4; mf++) {
                const float* pa = As + (64 * wr + 16 * mf + g) * 20 + 8 * kk + t4;
                af[mf][0] = fb(pa[0]);
                af[mf][1] = fb(pa[8 * 20]);
                af[mf][2] = fb(pa[4]);
                af[mf][3] = fb(pa[8 * 20 + 4]);
            }
#pragma unroll
            for (int nf = 0; nf < 4; nf++) {
                const float* pb = Bs + (8 * kk + t4) * 136 + 32 * wc + 8 * nf + g;
                uint32_t b0 = fb(pb[0]);
                uint32_t b1 = fb(pb[4 * 136]);
#pragma unroll
                for (int mf = 0; mf < 4; mf++)
                    mma_tf32(acc[mf][nf], af[mf][0], af[mf][1], af[mf][2], af[mf][3], b0, b1);
            }
        }
    }
#pragma unroll
    for (int mf = 0; mf < 4; mf++)
#pragma unroll
        for (int nf = 0; nf < 4; nf++)
#pragma unroll
            for (int h2i = 0; h2i < 2; h2i++) {
                int row = m0 + 64 * wr + 16 * mf + g + 8 * h2i;
                int col = n0 + 32 * wc + 8 * nf + 2 * t4;
                float2 o;
                o.x = acc[mf][nf][2 * h2i + 0] + bias[col];
                o.y = acc[mf][nf][2 * h2i + 1] + bias[col + 1];
                *(float2*)&C[(size_t)row * N + col] = o;
            }
}

__global__ void __launch_bounds__(256, 2) gemm_tf32_kernel(
    const float* __restrict__ A, const float* __restrict__ B,
    const float* __restrict__ bias, float* __restrict__ C,
    int M, int N, int K)
{
    gemm_tf32_body(A, B, bias, C, M, N, K);
}

__global__ void __launch_bounds__(256, 2) gemm_tf32_qkv_kernel(
    const float* __restrict__ A,
    const float* __restrict__ W0, const float* __restrict__ c0,
    const float* __restrict__ W1, const float* __restrict__ c1,
    const float* __restrict__ W2, const float* __restrict__ c2,
    float* __restrict__ O0, float* __restrict__ O1, float* __restrict__ O2,
    int M, int N, int K)
{
    const float* B; const float* bias; float* C;
    if (blockIdx.z == 0)      { B = W0; bias = c0; C = O0; }
    else if (blockIdx.z == 1) { B = W1; bias = c1; C = O1; }
    else                      { B = W2; bias = c2; C = O2; }
    gemm_tf32_body(A, B, bias, C, M, N, K);
}

// ---------------- fused relative attention (fp16 tensor-core flash) ----------------
// score[s][t] = ( q_s.k_t + UK[t]  +  shifted( q.E^T )[s][r] + VE[r] ) / 8
// Relative shift: d = t-s:  d<=0 -> pos[S-1+d] (row s); d==1 -> 0; d>=2 -> pos[d-2] (row s+1).
// Band E[r] <-> d = diag-63+r; gather index r = tt-ss+63. Row-base shift via the
// G-MMA A-operand (pass); only diag==0 needs both passes. UK/VE are the fp32
// row-independent u.k / v.e terms (u,v are per-head constants).
//
// Tiles are fp16, stored as half2 (u32) with row stride 36 u32 (=72 halves):
// fragment reads hit banks (4g+t4) — conflict-free. G region is separate from E
// (no reload on diag tile); Ps aliases G. V consumed via ldmatrix.x2.trans.
#define QS_OFF   0        // 65*36 = 2340 u32
#define KS_OFF   2340     // 64*36
#define VS_OFF   4644     // 64*36
#define ES_OFF   6948     // 128*36 = 4608
#define GS_OFF   11556    // 64*66  = 4224 (half2 stride 66; Ps aliases, stride 36)
#define UK_OFF   15780    // 64 f32
#define VE_OFF   15844    // 128 f32
#define RMX_OFF  15972    // 128 f32
#define RSM_OFF  16100    // 128 f32
#define ATT_SMEM_U32 16228  // 64,912 bytes -> 3 blocks/SM

__global__ void __launch_bounds__(256, 3) attn_kernel(
    const float* __restrict__ Q, const float* __restrict__ Km,
    const float* __restrict__ Vm, const float* __restrict__ POS,
    const float* __restrict__ UK, const float* __restrict__ VE,
    float* __restrict__ OUT)
{
    extern __shared__ uint32_t su[];
    uint32_t* Qsu = su + QS_OFF;
    uint32_t* Ksu = su + KS_OFF;
    uint32_t* Vsu = su + VS_OFF;
    uint32_t* Esu = su + ES_OFF;
    uint32_t* Gsu = su + GS_OFF;
    uint32_t* Psu = su + GS_OFF;            // alias (disjoint lifetimes)
    __half*   Gh  = (__half*)(su + GS_OFF);
    float* UKs    = (float*)(su + UK_OFF);
    float* VEs    = (float*)(su + VE_OFF);
    float* redmax = (float*)(su + RMX_OFF);
    float* redsum = (float*)(su + RSM_OFF);

    const int tid  = threadIdx.x;
    const int lane = tid & 31;
    const int wid  = tid >> 5;
    const int wr   = wid >> 1;     // 0..3 row group (16 rows)
    const int wc   = wid & 1;      // 0..1 col group
    const int g    = lane >> 2;    // 0..7
    const int t4   = lane & 3;     // 0..3

    const int s0   = blockIdx.x * 64;
    const int h    = blockIdx.y;
    const int b    = blockIdx.z;
    const int hoff = h * HDIM;

    const uint32_t vbase = (uint32_t)__cvta_generic_to_shared(Vsu);

    // ---- prologue: zero E row 127; load raw Q (65 rows) as fp16 ----
    if (tid < 32) Esu[127 * 36 + tid] = 0u;
    for (int q4 = tid; q4 < 65 * 16; q4 += 256) {
        int row = q4 >> 4;
        int p4  = (q4 & 15) * 4;
        int s   = s0 + row; if (s > S_LEN - 1) s = S_LEN - 1;
        float4 qv = *(const float4*)(Q + (size_t)(b * S_LEN + s) * EMBED + hoff + p4);
        Qsu[row * 36 + (p4 >> 1)]     = h2(qv.x, qv.y);
        Qsu[row * 36 + (p4 >> 1) + 1] = h2(qv.z, qv.w);
    }

    float acc[4][4];
    float m_r[2], l_r[2];
#pragma unroll
    for (int nf = 0; nf < 4; nf++)
#pragma unroll
        for (int e = 0; e < 4; e++) acc[nf][e] = 0.f;
    m_r[0] = m_r[1] = -1e30f;
    l_r[0] = l_r[1] = 0.f;

    for (int t0 = 0; t0 < S_LEN; t0 += 64) {
        const int diag = t0 - s0;
        __syncthreads();   // prev PV (Ps) reads complete

        // ---- fill K, V (fp16) ----
        for (int q4 = tid; q4 < 64 * 16; q4 += 256) {
            int row = q4 >> 4;
            int p4  = (q4 & 15) * 4;
            size_t go = (size_t)(b * S_LEN + t0 + row) * EMBED + hoff + p4;
            float4 kv = *(const float4*)(Km + go);
            float4 vv = *(const float4*)(Vm + go);
            Ksu[row * 36 + (p4 >> 1)]     = h2(kv.x, kv.y);
            Ksu[row * 36 + (p4 >> 1) + 1] = h2(kv.z, kv.w);
            Vsu[row * 36 + (p4 >> 1)]     = h2(vv.x, vv.y);
            Vsu[row * 36 + (p4 >> 1) + 1] = h2(vv.z, vv.w);
        }
        // ---- fill E band (127 rows, fp16) ----
        for (int q4 = tid; q4 < 127 * 16; q4 += 256) {
            int r  = q4 >> 4;
            int p4 = (q4 & 15) * 4;
            int d  = diag - 63 + r;
            int c  = (d <= 0) ? (S_LEN - 1 + d) : ((d == 1) ? -1 : (d - 2));
            float4 pv = make_float4(0.f, 0.f, 0.f, 0.f);
            if (c >= 0)
                pv = *(const float4*)(POS + (size_t)c * EMBED + hoff + p4);
            Esu[r * 36 + (p4 >> 1)]     = h2(pv.x, pv.y);
            Esu[r * 36 + (p4 >> 1) + 1] = h2(pv.z, pv.w);
        }
        // ---- per-tile fp32 correction vectors ----
        if (tid < 64) UKs[tid] = UK[((b * NHEAD + h) << 11) + t0 + tid];
        if (tid < 128) {
            int r = tid;
            float val = 0.f;
            if (r < 127) {
                int d = diag - 63 + r;
                int c = (d <= 0) ? (S_LEN - 1 + d) : ((d == 1) ? -1 : (d - 2));
                if (c >= 0) val = VE[(h << 11) + c];
            }
            VEs[r] = val;
        }
        __syncthreads();

        // ---- content score MMA: sc = q @ K^T (fp16 k16) ----
        float sc[4][4];
#pragma unroll
        for (int nf = 0; nf < 4; nf++)
#pragma unroll
            for (int e = 0; e < 4; e++) sc[nf][e] = 0.f;
        {
            const uint32_t* Aq = Qsu + (16 * wr + g) * 36 + t4;
            const uint32_t* Bk = Ksu + (32 * wc + g) * 36 + t4;
#pragma unroll
            for (int kk = 0; kk < 4; kk++) {
                uint32_t a0 = Aq[8 * kk];
                uint32_t a1 = Aq[8 * 36 + 8 * kk];
                uint32_t a2 = Aq[8 * kk + 4];
                uint32_t a3 = Aq[8 * 36 + 8 * kk + 4];
#pragma unroll
                for (int nf = 0; nf < 4; nf++) {
                    uint32_t b0 = Bk[nf * 8 * 36 + 8 * kk];
                    uint32_t b1 = Bk[nf * 8 * 36 + 8 * kk + 4];
                    mma_f16(sc[nf], a0, a1, a2, a3, b0, b1);
                }
            }
        }

        // ---- positional: G = q(+pass) @ E^T, store fp16, diagonal gather (+VE) ----
        const bool passA = (diag <= 0);
        const bool passB = (diag >= 0);
#pragma unroll 1
        for (int pass = 0; pass < 2; pass++) {
            if (pass == 0 && !passA) continue;
            if (pass == 1 && !passB) continue;
            if (pass == 1 && passA) __syncthreads();   // pass-0 gathers done before G overwrite

            const uint32_t* Aq = Qsu + (16 * wr + g + pass) * 36 + t4;
#pragma unroll 1
            for (int ch = 0; ch < 2; ch++) {
                float ga[4][4];
#pragma unroll
                for (int nf = 0; nf < 4; nf++)
#pragma unroll
                    for (int e = 0; e < 4; e++) ga[nf][e] = 0.f;
                const uint32_t* Be = Esu + (64 * wc + 32 * ch + g) * 36 + t4;
#pragma unroll
                for (int kk = 0; kk < 4; kk++) {
                    uint32_t a0 = Aq[8 * kk];
                    uint32_t a1 = Aq[8 * 36 + 8 * kk];
                    uint32_t a2 = Aq[8 * kk + 4];
                    uint32_t a3 = Aq[8 * 36 + 8 * kk + 4];
#pragma unroll
                    for (int nf = 0; nf < 4; nf++) {
                        uint32_t b0 = Be[nf * 8 * 36 + 8 * kk];
                        uint32_t b1 = Be[nf * 8 * 36 + 8 * kk + 4];
                        mma_f16(ga[nf], a0, a1, a2, a3, b0, b1);
                    }
                }
#pragma unroll
                for (int nf = 0; nf < 4; nf++)
#pragma unroll
                    for (int he = 0; he < 2; he++) {
                        int row = 16 * wr + g + 8 * he;
                        int h2c = 32 * wc + 16 * ch + 4 * nf + t4;
                        Gsu[row * 66 + h2c] = h2(ga[nf][2 * he], ga[nf][2 * he + 1]);
                    }
            }
            __syncthreads();   // G stores visible
#pragma unroll
            for (int nf = 0; nf < 4; nf++)
#pragma unroll
                for (int e = 0; e < 4; e++) {
                    int ss = 16 * wr + g + 8 * (e >> 1);
                    int tt = 2 * t4 + (e & 1) + 8 * nf + 32 * wc;
                    int d  = diag + tt - ss;
                    bool take = pass ? (d >= 2) : (d <= 0);
                    if (take) {
                        int r = tt - ss + 63;
                        sc[nf][e] += __half2float(Gh[ss * 132 + r]) + VEs[r];
                    }
                }
        }

        // ---- add UK, scale, online softmax ----
#pragma unroll
        for (int nf = 0; nf < 4; nf++)
#pragma unroll
            for (int e = 0; e < 4; e++) {
                int tt = 2 * t4 + (e & 1) + 8 * nf + 32 * wc;
                sc[nf][e] = (sc[nf][e] + UKs[tt]) * 0.125f;
            }

        float rmx[2] = {-1e30f, -1e30f};
#pragma unroll
        for (int nf = 0; nf < 4; nf++)
#pragma unroll
            for (int e = 0; e < 4; e++)
                rmx[e >> 1] = fmaxf(rmx[e >> 1], sc[nf][e]);
#pragma unroll
        for (int msk = 1; msk < 4; msk <<= 1) {
            rmx[0] = fmaxf(rmx[0], __shfl_xor_sync(0xffffffffu, rmx[0], msk));
            rmx[1] = fmaxf(rmx[1], __shfl_xor_sync(0xffffffffu, rmx[1], msk));
        }
        if (t4 == 0) {
            redmax[(16 * wr + g) * 2 + wc]     = rmx[0];
            redmax[(16 * wr + g + 8) * 2 + wc] = rmx[1];
        }
        __syncthreads();   // gathers done; redmax visible; Ps store safe after

        float mnew[2], corr[2];
#pragma unroll
        for (int hh = 0; hh < 2; hh++) {
            int row = 16 * wr + g + 8 * hh;
            float rm = fmaxf(redmax[row * 2], redmax[row * 2 + 1]);
            mnew[hh] = fmaxf(m_r[hh], rm);
            corr[hh] = __expf(m_r[hh] - mnew[hh]);
            m_r[hh]  = mnew[hh];
        }
        float rs[2] = {0.f, 0.f};
#pragma unroll
        for (int nf = 0; nf < 4; nf++)
#pragma unroll
            for (int e = 0; e < 4; e++) {
                float p = __expf(sc[nf][e] - mnew[e >> 1]);
                sc[nf][e] = p;
                rs[e >> 1] += p;
            }
#pragma unroll
        for (int msk = 1; msk < 4; msk <<= 1) {
            rs[0] += __shfl_xor_sync(0xffffffffu, rs[0], msk);
            rs[1] += __shfl_xor_sync(0xffffffffu, rs[1], msk);
        }
        if (t4 == 0) {
            redsum[(16 * wr + g) * 2 + wc]     = rs[0];
            redsum[(16 * wr + g + 8) * 2 + wc] = rs[1];
        }
        // store P (exp'd, fp16) into the G alias
#pragma unroll
        for (int nf = 0; nf < 4; nf++)
#pragma unroll
            for (int he = 0; he < 2; he++) {
                int row = 16 * wr + g + 8 * he;
                int h2c = 16 * wc + 4 * nf + t4;
                Psu[row * 36 + h2c] = h2(sc[nf][2 * he], sc[nf][2 * he + 1]);
            }
        __syncthreads();

#pragma unroll
        for (int hh = 0; hh < 2; hh++) {
            int row = 16 * wr + g + 8 * hh;
            l_r[hh] = l_r[hh] * corr[hh] + redsum[row * 2] + redsum[row * 2 + 1];
        }
#pragma unroll
        for (int nf = 0; nf < 4; nf++)
#pragma unroll
            for (int e = 0; e < 4; e++) acc[nf][e] *= corr[e >> 1];

        // ---- PV MMA: acc += P @ V  (B via ldmatrix.trans from row-major V) ----
        {
            const uint32_t* Ap = Psu + (16 * wr + g) * 36 + t4;
#pragma unroll
            for (int kk = 0; kk < 4; kk++) {
                uint32_t a0 = Ap[8 * kk];
                uint32_t a1 = Ap[8 * 36 + 8 * kk];
                uint32_t a2 = Ap[8 * kk + 4];
                uint32_t a3 = Ap[8 * 36 + 8 * kk + 4];
                uint32_t rowaddr = vbase + (((16 * kk + (lane & 15)) * 36) + 16 * wc) * 4;
#pragma unroll
                for (int nf = 0; nf < 4; nf++) {
                    uint32_t b0, b1;
                    asm volatile(
                        "ldmatrix.sync.aligned.m8n8.x2.trans.shared.b16 {%0,%1}, [%2];"
                        : "=r"(b0), "=r"(b1) : "r"(rowaddr + nf * 16));
                    mma_f16(acc[nf], a0, a1, a2, a3, b0, b1);
                }
            }
        }
    }

    // ---- epilogue ----
    float inv[2] = {1.f / l_r[0], 1.f / l_r[1]};
#pragma unroll
    for (int nf = 0; nf < 4; nf++)
#pragma unroll
        for (int e = 0; e < 4; e++) {
            int srow = s0 + 16 * wr + g + 8 * (e >> 1);
            int p    = 2 * t4 + (e & 1) + 8 * nf + 32 * wc;
            OUT[(size_t)(b * S_LEN + srow) * EMBED + hoff + p] = acc[nf][e] * inv[e >> 1];
        }
}

// ---------------- launch ----------------
extern "C" void kernel_launch(void* const* d_in, const int* in_sizes, int n_in,
                              void* d_out, int out_size)
{
    const float* x   = (const float*)d_in[0];
    const float* Wq  = (const float*)d_in[1];
    const float* bq  = (const float*)d_in[2];
    const float* Wk  = (const float*)d_in[3];
    const float* bk  = (const float*)d_in[4];
    const float* Wv  = (const float*)d_in[5];
    const float* bv_ = (const float*)d_in[6];
    const float* Wp  = (const float*)d_in[7];
    const float* bp  = (const float*)d_in[8];
    const float* Wo  = (const float*)d_in[9];
    const float* bo  = (const float*)d_in[10];
    const float* u   = (const float*)d_in[11];
    const float* v   = (const float*)d_in[12];
    float* out = (float*)d_out;

    float *psin, *ppos, *pq, *pk, *pv, *pattn, *puk, *pve;
    cudaGetSymbolAddress((void**)&psin,  g_sin);
    cudaGetSymbolAddress((void**)&ppos,  g_pos);
    cudaGetSymbolAddress((void**)&pq,    g_q);
    cudaGetSymbolAddress((void**)&pk,    g_k);
    cudaGetSymbolAddress((void**)&pv,    g_v);
    cudaGetSymbolAddress((void**)&pattn, g_attn);
    cudaGetSymbolAddress((void**)&puk,   g_uk);
    cudaGetSymbolAddress((void**)&pve,   g_ve);

    cudaFuncSetAttribute(attn_kernel, cudaFuncAttributeMaxDynamicSharedMemorySize,
                         ATT_SMEM_U32 * 4);

    sinusoid_kernel<<<(S_LEN * (EMBED / 2) + 255) / 256, 256>>>();

    dim3 gBig(EMBED / 128, (BATCH * S_LEN) / 128);         // (8, 32)
    dim3 gQKV(EMBED / 128, (BATCH * S_LEN) / 128, 3);      // (8, 32, 3)
    dim3 gPos(EMBED / 128, S_LEN / 128);                   // (8, 16)

    gemm_tf32_qkv_kernel<<<gQKV, 256>>>(x, Wq, bq, Wk, bk, Wv, bv_,
                                        pq, pk, pv, BATCH * S_LEN, EMBED, EMBED);
    gemm_tf32_kernel<<<gPos, 256>>>(psin, Wp, bp, ppos, S_LEN, EMBED, EMBED);

    // UK/VE precompute: one warp per dot (needs K and POS)
    int nwarp = BATCH * NHEAD * S_LEN + NHEAD * S_LEN;     // 98,304
    ukve_kernel<<<(nwarp * 32 + 255) / 256, 256>>>(pk, ppos, u, v);

    dim3 gAtt(S_LEN / 64, NHEAD, BATCH);                   // (32, 16, 2)
    attn_kernel<<<gAtt, 256, ATT_SMEM_U32 * 4>>>(pq, pk, pv, ppos, puk, pve, pattn);

    gemm_bias_kernel<<<gBig, 256>>>(pattn, Wo, bo, out, BATCH * S_LEN, EMBED, EMBED);
}

// round 10
// speedup vs baseline: 4.3274x; 1.3380x over previous
#include <cuda_runtime.h>
#include <cuda_fp16.h>
#include <math.h>
#include <stdint.h>

#define S_LEN 2048
#define BATCH 2
#define EMBED 1024
#define NHEAD 16
#define HDIM  64

// ---------------- scratch (static device globals; no allocation) ----------------
__device__ float g_sin[S_LEN * EMBED];
__device__ float g_pos[S_LEN * EMBED];
__device__ float g_q[BATCH * S_LEN * EMBED];
__device__ float g_k[BATCH * S_LEN * EMBED];
__device__ float g_v[BATCH * S_LEN * EMBED];
__device__ float g_attn[BATCH * S_LEN * EMBED];
__device__ float g_uk[BATCH * NHEAD * S_LEN];   // u . k_t   per (b,h,t)
__device__ float g_ve[NHEAD * S_LEN];           // v . pos_c per (h,c)
__device__ float g_invf[EMBED / 2];             // double-exact inv_freq

// ---------------- sinusoid position embedding (fp32 fast path) ----------------
__global__ void invf_kernel() {
    int i = blockIdx.x * blockDim.x + threadIdx.x;
    if (i >= EMBED / 2) return;
    double invf = exp(-(2.0 * (double)i / (double)EMBED) * log(10000.0));
    g_invf[i] = (float)invf;
}

__global__ void sinusoid_kernel() {
    int idx = blockIdx.x * blockDim.x + threadIdx.x;
    if (idx >= S_LEN * (EMBED / 2)) return;
    int s = idx / (EMBED / 2);
    int i = idx % (EMBED / 2);
    float ang = (float)s * g_invf[i];       // fp32 product, like the reference
    float sv, cv;
    sincosf(ang, &sv, &cv);                 // accurate fp32 (full range reduction)
    g_sin[s * EMBED + i]             = sv;
    g_sin[s * EMBED + (EMBED/2) + i] = cv;
}

// ---------------- UK/VE precompute: one warp per dot-64 (fp32 exact) ----------------
__global__ void ukve_kernel(const float* __restrict__ K, const float* __restrict__ POS,
                            const float* __restrict__ u, const float* __restrict__ v)
{
    int w    = (blockIdx.x * blockDim.x + threadIdx.x) >> 5;
    int lane = threadIdx.x & 31;
    const int UKW = BATCH * NHEAD * S_LEN;
    if (w < UKW) {
        int t = w & (S_LEN - 1);
        int h = (w >> 11) & (NHEAD - 1);
        int b = w >> 15;
        const float* kp = K + ((size_t)(b * S_LEN + t)) * EMBED + h * HDIM;
        const float* up = u + h * HDIM;
        float s = kp[lane] * up[lane] + kp[lane + 32] * up[lane + 32];
#pragma unroll
        for (int m = 16; m; m >>= 1) s += __shfl_xor_sync(~0u, s, m);
        if (!lane) g_uk[w] = s;
    } else if (w < UKW + NHEAD * S_LEN) {
        int w2 = w - UKW;
        int c = w2 & (S_LEN - 1);
        int h = w2 >> 11;
        const float* pp = POS + (size_t)c * EMBED + h * HDIM;
        const float* vp = v + h * HDIM;
        float s = pp[lane] * vp[lane] + pp[lane + 32] * vp[lane + 32];
#pragma unroll
        for (int m = 16; m; m >>= 1) s += __shfl_xor_sync(~0u, s, m);
        if (!lane) g_ve[w2] = s;
    }
}

// ---------------- helpers ----------------
__device__ __forceinline__ float tf32f(float f) {
    uint32_t u;
    asm("cvt.rna.tf32.f32 %0, %1;" : "=r"(u) : "f"(f));
    return __uint_as_float(u);
}
__device__ __forceinline__ uint32_t fb(float f) { return __float_as_uint(f); }
__device__ __forceinline__ uint32_t h2(float x, float y) {
    __half2 h = __floats2half2_rn(x, y);
    return *(uint32_t*)&h;
}
// hi/lo fp16 split of two floats (residual capture)
__device__ __forceinline__ void split2(float x, float y, uint32_t& hi, uint32_t& lo) {
    __half hx = __float2half_rn(x), hy = __float2half_rn(y);
    float rx = x - __half2float(hx), ry = y - __half2float(hy);
    __half2 hh; hh.x = hx; hh.y = hy;
    hi = *(uint32_t*)&hh;
    lo = h2(rx, ry);
}
__device__ __forceinline__ void mma_tf32(float* d,
    uint32_t a0, uint32_t a1, uint32_t a2, uint32_t a3, uint32_t b0, uint32_t b1)
{
    asm volatile(
        "mma.sync.aligned.m16n8k8.row.col.f32.tf32.tf32.f32 "
        "{%0,%1,%2,%3}, {%4,%5,%6,%7}, {%8,%9}, {%0,%1,%2,%3};"
        : "+f"(d[0]), "+f"(d[1]), "+f"(d[2]), "+f"(d[3])
        : "r"(a0), "r"(a1), "r"(a2), "r"(a3), "r"(b0), "r"(b1));
}
__device__ __forceinline__ void mma_f16(float* d,
    uint32_t a0, uint32_t a1, uint32_t a2, uint32_t a3, uint32_t b0, uint32_t b1)
{
    asm volatile(
        "mma.sync.aligned.m16n8k16.row.col.f32.f16.f16.f32 "
        "{%0,%1,%2,%3}, {%4,%5,%6,%7}, {%8,%9}, {%0,%1,%2,%3};"
        : "+f"(d[0]), "+f"(d[1]), "+f"(d[2]), "+f"(d[3])
        : "r"(a0), "r"(a1), "r"(a2), "r"(a3), "r"(b0), "r"(b1));
}

// ---------------- tf32 tensor-core GEMM + bias (projections) ----------------
__device__ __forceinline__ void gemm_tf32_body(
    const float* __restrict__ A, const float* __restrict__ B,
    const float* __restrict__ bias, float* __restrict__ C,
    int M, int N, int K)
{
    __shared__ float As[128 * 20];
    __shared__ float Bs[16 * 136];
    const int tid  = threadIdx.x;
    const int lane = tid & 31;
    const int wid  = tid >> 5;
    const int wr   = wid >> 2;
    const int wc   = wid & 3;
    const int g    = lane >> 2;
    const int t4   = lane & 3;
    const int m0   = blockIdx.y * 128;
    const int n0   = blockIdx.x * 128;

    float acc[4][4][4];
#pragma unroll
    for (int mf = 0; mf < 4; mf++)
#pragma unroll
        for (int nf = 0; nf < 4; nf++)
#pragma unroll
            for (int e = 0; e < 4; e++) acc[mf][nf][e] = 0.f;

    const int a_row = tid >> 2;
    const int a_k4  = (tid & 3) * 4;
    const int b_k   = tid >> 4;
    const int b_n4  = (tid & 15) * 4;

    const float* Ap = A + (size_t)(m0 + a_row) * K + a_k4;
    const float* Bp = B + (size_t)b_k * N + n0 + b_n4;

    for (int k0 = 0; k0 < K; k0 += 16) {
        float4 av0 = *(const float4*)(Ap + k0);
        float4 av1 = *(const float4*)(Ap + (size_t)64 * K + k0);
        float4 bv0 = *(const float4*)(Bp + (size_t)k0 * N);
        float4 bv1 = *(const float4*)(Bp + (size_t)k0 * N + 64);
        __syncthreads();
        float* as0 = As + a_row * 20 + a_k4;
        as0[0] = tf32f(av0.x); as0[1] = tf32f(av0.y);
        as0[2] = tf32f(av0.z); as0[3] = tf32f(av0.w);
        float* as1 = As + (a_row + 64) * 20 + a_k4;
        as1[0] = tf32f(av1.x); as1[1] = tf32f(av1.y);
        as1[2] = tf32f(av1.z); as1[3] = tf32f(av1.w);
        float* bs0 = Bs + b_k * 136 + b_n4;
        bs0[0] = tf32f(bv0.x); bs0[1] = tf32f(bv0.y);
        bs0[2] = tf32f(bv0.z); bs0[3] = tf32f(bv0.w);
        float* bs1 = bs0 + 64;
        bs1[0] = tf32f(bv1.x); bs1[1] = tf32f(bv1.y);
        bs1[2] = tf32f(bv1.z); bs1[3] = tf32f(bv1.w);
        __syncthreads();
#pragma unroll
        for (int kk = 0; kk < 2; kk++) {
            uint32_t af[4][4];
#pragma unroll
            for (int mf = 0; mf < 4; mf++) {
                const float* pa = As + (64 * wr + 16 * mf + g) * 20 + 8 * kk + t4;
                af[mf][0] = fb(pa[0]);
                af[mf][1] = fb(pa[8 * 20]);
                af[mf][2] = fb(pa[4]);
                af[mf][3] = fb(pa[8 * 20 + 4]);
            }
#pragma unroll
            for (int nf = 0; nf < 4; nf++) {
                const float* pb = Bs + (8 * kk + t4) * 136 + 32 * wc + 8 * nf + g;
                uint32_t b0 = fb(pb[0]);
                uint32_t b1 = fb(pb[4 * 136]);
#pragma unroll
                for (int mf = 0; mf < 4; mf++)
                    mma_tf32(acc[mf][nf], af[mf][0], af[mf][1], af[mf][2], af[mf][3], b0, b1);
            }
        }
    }
#pragma unroll
    for (int mf = 0; mf < 4; mf++)
#pragma unroll
        for (int nf = 0; nf < 4; nf++)
#pragma unroll
            for (int h2i = 0; h2i < 2; h2i++) {
                int row = m0 + 64 * wr + 16 * mf + g + 8 * h2i;
                int col = n0 + 32 * wc + 8 * nf + 2 * t4;
                float2 o;
                o.x = acc[mf][nf][2 * h2i + 0] + bias[col];
                o.y = acc[mf][nf][2 * h2i + 1] + bias[col + 1];
                *(float2*)&C[(size_t)row * N + col] = o;
            }
}

__global__ void __launch_bounds__(256, 2) gemm_tf32_kernel(
    const float* __restrict__ A, const float* __restrict__ B,
    const float* __restrict__ bias, float* __restrict__ C,
    int M, int N, int K)
{
    gemm_tf32_body(A, B, bias, C, M, N, K);
}

__global__ void __launch_bounds__(256, 2) gemm_tf32_qkv_kernel(
    const float* __restrict__ A,
    const float* __restrict__ W0, const float* __restrict__ c0,
    const float* __restrict__ W1, const float* __restrict__ c1,
    const float* __restrict__ W2, const float* __restrict__ c2,
    float* __restrict__ O0, float* __restrict__ O1, float* __restrict__ O2,
    int M, int N, int K)
{
    const float* B; const float* bias; float* C;
    if (blockIdx.z == 0)      { B = W0; bias = c0; C = O0; }
    else if (blockIdx.z == 1) { B = W1; bias = c1; C = O1; }
    else                      { B = W2; bias = c2; C = O2; }
    gemm_tf32_body(A, B, bias, C, M, N, K);
}

// ---------------- fp16-split tensor-core GEMM + bias (out-proj; ~fp32 accuracy) ----------------
// C = A@W + bias with A = a1+a2, W = w1+w2 (fp16 hi/lo); C ~= a1w1 + a1w2 + a2w1.
// Residual ~2^-21 relative. BM=BN=128, BK=16, 8 warps (wr 0..1 x wc 0..3), warp 64x32.
// A smem: [row][k] half2, u32 stride 12 (frag banks 12g+t4: all distinct).
// W smem: [k][n] half2, u32 stride 68 (68%32=4: ldmatrix 4-row phases hit disjoint
// 4-bank spans). W frags via ldmatrix.x2.trans (same pattern as validated PV path).
#define OP_AST 12
#define OP_WST 68
__global__ void __launch_bounds__(256, 2) gemm_f16x3_kernel(
    const float* __restrict__ A, const float* __restrict__ W,
    const float* __restrict__ bias, float* __restrict__ C,
    int M, int N, int K)
{
    __shared__ uint32_t A1[128 * OP_AST];
    __shared__ uint32_t A2[128 * OP_AST];
    __shared__ uint32_t W1[16 * OP_WST];
    __shared__ uint32_t W2[16 * OP_WST];
    const int tid  = threadIdx.x;
    const int lane = tid & 31;
    const int wid  = tid >> 5;
    const int wr   = wid >> 2;       // 0..1
    const int wc   = wid & 3;        // 0..3
    const int g    = lane >> 2;      // 0..7
    const int t4   = lane & 3;       // 0..3
    const int m0   = blockIdx.y * 128;
    const int n0   = blockIdx.x * 128;

    const uint32_t w1base = (uint32_t)__cvta_generic_to_shared(W1);
    const uint32_t w2base = (uint32_t)__cvta_generic_to_shared(W2);

    float acc[4][4][4];
#pragma unroll
    for (int mf = 0; mf < 4; mf++)
#pragma unroll
        for (int nf = 0; nf < 4; nf++)
#pragma unroll
            for (int e = 0; e < 4; e++) acc[mf][nf][e] = 0.f;

    const int a_row = tid >> 2;          // 0..63 (+64 second half)
    const int a_k4  = (tid & 3) * 4;     // k offset 0,4,8,12
    const int b_k   = tid >> 4;          // 0..15
    const int b_n4  = (tid & 15) * 4;    // 0..60 (+64 second half)

    const float* Ap = A + (size_t)(m0 + a_row) * K + a_k4;
    const float* Wp = W + (size_t)b_k * N + n0 + b_n4;

    for (int k0 = 0; k0 < K; k0 += 16) {
        float4 av0 = *(const float4*)(Ap + k0);
        float4 av1 = *(const float4*)(Ap + (size_t)64 * K + k0);
        float4 wv0 = *(const float4*)(Wp + (size_t)k0 * N);
        float4 wv1 = *(const float4*)(Wp + (size_t)k0 * N + 64);
        __syncthreads();
        {
            uint32_t hi, lo;
            uint32_t* p1 = A1 + a_row * OP_AST + (a_k4 >> 1);
            uint32_t* p2 = A2 + a_row * OP_AST + (a_k4 >> 1);
            split2(av0.x, av0.y, hi, lo); p1[0] = hi; p2[0] = lo;
            split2(av0.z, av0.w, hi, lo); p1[1] = hi; p2[1] = lo;
            p1 = A1 + (a_row + 64) * OP_AST + (a_k4 >> 1);
            p2 = A2 + (a_row + 64) * OP_AST + (a_k4 >> 1);
            split2(av1.x, av1.y, hi, lo); p1[0] = hi; p2[0] = lo;
            split2(av1.z, av1.w, hi, lo); p1[1] = hi; p2[1] = lo;

            uint32_t* q1 = W1 + b_k * OP_WST + (b_n4 >> 1);
            uint32_t* q2 = W2 + b_k * OP_WST + (b_n4 >> 1);
            split2(wv0.x, wv0.y, hi, lo); q1[0] = hi; q2[0] = lo;
            split2(wv0.z, wv0.w, hi, lo); q1[1] = hi; q2[1] = lo;
            split2(wv1.x, wv1.y, hi, lo); q1[32] = hi; q2[32] = lo;
            split2(wv1.z, wv1.w, hi, lo); q1[33] = hi; q2[33] = lo;
        }
        __syncthreads();

        // A fragments (both splits), rows 64*wr + 16*mf + g (+8)
        uint32_t af1[4][4], af2[4][4];
#pragma unroll
        for (int mf = 0; mf < 4; mf++) {
            const uint32_t* pa1 = A1 + (64 * wr + 16 * mf + g) * OP_AST + t4;
            const uint32_t* pa2 = A2 + (64 * wr + 16 * mf + g) * OP_AST + t4;
            af1[mf][0] = pa1[0];  af1[mf][1] = pa1[8 * OP_AST];
            af1[mf][2] = pa1[4];  af1[mf][3] = pa1[8 * OP_AST + 4];
            af2[mf][0] = pa2[0];  af2[mf][1] = pa2[8 * OP_AST];
            af2[mf][2] = pa2[4];  af2[mf][3] = pa2[8 * OP_AST + 4];
        }
#pragma unroll
        for (int nf = 0; nf < 4; nf++) {
            uint32_t off = (((lane & 15) * OP_WST) + 16 * wc + 4 * nf) * 4;
            uint32_t b10, b11, b20, b21;
            asm volatile("ldmatrix.sync.aligned.m8n8.x2.trans.shared.b16 {%0,%1}, [%2];"
                         : "=r"(b10), "=r"(b11) : "r"(w1base + off));
            asm volatile("ldmatrix.sync.aligned.m8n8.x2.trans.shared.b16 {%0,%1}, [%2];"
                         : "=r"(b20), "=r"(b21) : "r"(w2base + off));
#pragma unroll
            for (int mf = 0; mf < 4; mf++) {
                mma_f16(acc[mf][nf], af1[mf][0], af1[mf][1], af1[mf][2], af1[mf][3], b10, b11);
                mma_f16(acc[mf][nf], af1[mf][0], af1[mf][1], af1[mf][2], af1[mf][3], b20, b21);
                mma_f16(acc[mf][nf], af2[mf][0], af2[mf][1], af2[mf][2], af2[mf][3], b10, b11);
            }
        }
    }
#pragma unroll
    for (int mf = 0; mf < 4; mf++)
#pragma unroll
        for (int nf = 0; nf < 4; nf++)
#pragma unroll
            for (int he = 0; he < 2; he++) {
                int row = m0 + 64 * wr + 16 * mf + g + 8 * he;
                int col = n0 + 32 * wc + 8 * nf + 2 * t4;
                float2 o;
                o.x = acc[mf][nf][2 * he + 0] + bias[col];
                o.y = acc[mf][nf][2 * he + 1] + bias[col + 1];
                *(float2*)&C[(size_t)row * N + col] = o;
            }
}

// ---------------- fused relative attention (fp16 tensor-core flash) ----------------
// score[s][t] = ( q_s.k_t + UK[t] + shifted(q.E^T)[s][r] + VE[r] ) / 8
// d = t-s:  d<=0 -> pos[S-1+d] (row s); d==1 -> 0; d>=2 -> pos[d-2] (row s+1).
#define QS_OFF   0        // 65*36
#define KS_OFF   2340     // 64*36
#define VS_OFF   4644     // 64*36
#define ES_OFF   6948     // 128*36
#define GS_OFF   11556    // 64*66 (Ps aliases, stride 36)
#define UK_OFF   15780    // 64 f32
#define VE_OFF   15844    // 128 f32
#define RMX_OFF  15972    // 128 f32
#define RSM_OFF  16100    // 128 f32
#define ATT_SMEM_U32 16228  // 64,912 B -> 3 blocks/SM

__global__ void __launch_bounds__(256, 3) attn_kernel(
    const float* __restrict__ Q, const float* __restrict__ Km,
    const float* __restrict__ Vm, const float* __restrict__ POS,
    const float* __restrict__ UK, const float* __restrict__ VE,
    float* __restrict__ OUT)
{
    extern __shared__ uint32_t su[];
    uint32_t* Qsu = su + QS_OFF;
    uint32_t* Ksu = su + KS_OFF;
    uint32_t* Vsu = su + VS_OFF;
    uint32_t* Esu = su + ES_OFF;
    uint32_t* Gsu = su + GS_OFF;
    uint32_t* Psu = su + GS_OFF;            // alias (disjoint lifetimes)
    __half*   Gh  = (__half*)(su + GS_OFF);
    float* UKs    = (float*)(su + UK_OFF);
    float* VEs    = (float*)(su + VE_OFF);
    float* redmax = (float*)(su + RMX_OFF);
    float* redsum = (float*)(su + RSM_OFF);

    const int tid  = threadIdx.x;
    const int lane = tid & 31;
    const int wid  = tid >> 5;
    const int wr   = wid >> 1;
    const int wc   = wid & 1;
    const int g    = lane >> 2;
    const int t4   = lane & 3;

    const int s0   = blockIdx.x * 64;
    const int h    = blockIdx.y;
    const int b    = blockIdx.z;
    const int hoff = h * HDIM;

    const uint32_t vbase = (uint32_t)__cvta_generic_to_shared(Vsu);

    if (tid < 32) Esu[127 * 36 + tid] = 0u;
    for (int q4 = tid; q4 < 65 * 16; q4 += 256) {
        int row = q4 >> 4;
        int p4  = (q4 & 15) * 4;
        int s   = s0 + row; if (s > S_LEN - 1) s = S_LEN - 1;
        float4 qv = *(const float4*)(Q + (size_t)(b * S_LEN + s) * EMBED + hoff + p4);
        Qsu[row * 36 + (p4 >> 1)]     = h2(qv.x, qv.y);
        Qsu[row * 36 + (p4 >> 1) + 1] = h2(qv.z, qv.w);
    }

    float acc[4][4];
    float m_r[2], l_r[2];
#pragma unroll
    for (int nf = 0; nf < 4; nf++)
#pragma unroll
        for (int e = 0; e < 4; e++) acc[nf][e] = 0.f;
    m_r[0] = m_r[1] = -1e30f;
    l_r[0] = l_r[1] = 0.f;

    for (int t0 = 0; t0 < S_LEN; t0 += 64) {
        const int diag = t0 - s0;
        __syncthreads();

        for (int q4 = tid; q4 < 64 * 16; q4 += 256) {
            int row = q4 >> 4;
            int p4  = (q4 & 15) * 4;
            size_t go = (size_t)(b * S_LEN + t0 + row) * EMBED + hoff + p4;
            float4 kv = *(const float4*)(Km + go);
            float4 vv = *(const float4*)(Vm + go);
            Ksu[row * 36 + (p4 >> 1)]     = h2(kv.x, kv.y);
            Ksu[row * 36 + (p4 >> 1) + 1] = h2(kv.z, kv.w);
            Vsu[row * 36 + (p4 >> 1)]     = h2(vv.x, vv.y);
            Vsu[row * 36 + (p4 >> 1) + 1] = h2(vv.z, vv.w);
        }
        for (int q4 = tid; q4 < 127 * 16; q4 += 256) {
            int r  = q4 >> 4;
            int p4 = (q4 & 15) * 4;
            int d  = diag - 63 + r;
            int c  = (d <= 0) ? (S_LEN - 1 + d) : ((d == 1) ? -1 : (d - 2));
            float4 pv = make_float4(0.f, 0.f, 0.f, 0.f);
            if (c >= 0)
                pv = *(const float4*)(POS + (size_t)c * EMBED + hoff + p4);
            Esu[r * 36 + (p4 >> 1)]     = h2(pv.x, pv.y);
            Esu[r * 36 + (p4 >> 1) + 1] = h2(pv.z, pv.w);
        }
        if (tid < 64) UKs[tid] = UK[((b * NHEAD + h) << 11) + t0 + tid];
        if (tid < 128) {
            int r = tid;
            float val = 0.f;
            if (r < 127) {
                int d = diag - 63 + r;
                int c = (d <= 0) ? (S_LEN - 1 + d) : ((d == 1) ? -1 : (d - 2));
                if (c >= 0) val = VE[(h << 11) + c];
            }
            VEs[r] = val;
        }
        __syncthreads();

        float sc[4][4];
#pragma unroll
        for (int nf = 0; nf < 4; nf++)
#pragma unroll
            for (int e = 0; e < 4; e++) sc[nf][e] = 0.f;
        {
            const uint32_t* Aq = Qsu + (16 * wr + g) * 36 + t4;
            const uint32_t* Bk = Ksu + (32 * wc + g) * 36 + t4;
#pragma unroll
            for (int kk = 0; kk < 4; kk++) {
                uint32_t a0 = Aq[8 * kk];
                uint32_t a1 = Aq[8 * 36 + 8 * kk];
                uint32_t a2 = Aq[8 * kk + 4];
                uint32_t a3 = Aq[8 * 36 + 8 * kk + 4];
#pragma unroll
                for (int nf = 0; nf < 4; nf++) {
                    uint32_t b0 = Bk[nf * 8 * 36 + 8 * kk];
                    uint32_t b1 = Bk[nf * 8 * 36 + 8 * kk + 4];
                    mma_f16(sc[nf], a0, a1, a2, a3, b0, b1);
                }
            }
        }

        const bool passA = (diag <= 0);
        const bool passB = (diag >= 0);
#pragma unroll 1
        for (int pass = 0; pass < 2; pass++) {
            if (pass == 0 && !passA) continue;
            if (pass == 1 && !passB) continue;
            if (pass == 1 && passA) __syncthreads();

            const uint32_t* Aq = Qsu + (16 * wr + g + pass) * 36 + t4;
#pragma unroll 1
            for (int ch = 0; ch < 2; ch++) {
                float ga[4][4];
#pragma unroll
                for (int nf = 0; nf < 4; nf++)
#pragma unroll
                    for (int e = 0; e < 4; e++) ga[nf][e] = 0.f;
                const uint32_t* Be = Esu + (64 * wc + 32 * ch + g) * 36 + t4;
#pragma unroll
                for (int kk = 0; kk < 4; kk++) {
                    uint32_t a0 = Aq[8 * kk];
                    uint32_t a1 = Aq[8 * 36 + 8 * kk];
                    uint32_t a2 = Aq[8 * kk + 4];
                    uint32_t a3 = Aq[8 * 36 + 8 * kk + 4];
#pragma unroll
                    for (int nf = 0; nf < 4; nf++) {
                        uint32_t b0 = Be[nf * 8 * 36 + 8 * kk];
                        uint32_t b1 = Be[nf * 8 * 36 + 8 * kk + 4];
                        mma_f16(ga[nf], a0, a1, a2, a3, b0, b1);
                    }
                }
#pragma unroll
                for (int nf = 0; nf < 4; nf++)
#pragma unroll
                    for (int he = 0; he < 2; he++) {
                        int row = 16 * wr + g + 8 * he;
                        int h2c = 32 * wc + 16 * ch + 4 * nf + t4;
                        Gsu[row * 66 + h2c] = h2(ga[nf][2 * he], ga[nf][2 * he + 1]);
                    }
            }
            __syncthreads();
#pragma unroll
            for (int nf = 0; nf < 4; nf++)
#pragma unroll
                for (int e = 0; e < 4; e++) {
                    int ss = 16 * wr + g + 8 * (e >> 1);
                    int tt = 2 * t4 + (e & 1) + 8 * nf + 32 * wc;
                    int d  = diag + tt - ss;
                    bool take = pass ? (d >= 2) : (d <= 0);
                    if (take) {
                        int r = tt - ss + 63;
                        sc[nf][e] += __half2float(Gh[ss * 132 + r]) + VEs[r];
                    }
                }
        }

#pragma unroll
        for (int nf = 0; nf < 4; nf++)
#pragma unroll
            for (int e = 0; e < 4; e++) {
                int tt = 2 * t4 + (e & 1) + 8 * nf + 32 * wc;
                sc[nf][e] = (sc[nf][e] + UKs[tt]) * 0.125f;
            }

        float rmx[2] = {-1e30f, -1e30f};
#pragma unroll
        for (int nf = 0; nf < 4; nf++)
#pragma unroll
            for (int e = 0; e < 4; e++)
                rmx[e >> 1] = fmaxf(rmx[e >> 1], sc[nf][e]);
#pragma unroll
        for (int msk = 1; msk < 4; msk <<= 1) {
            rmx[0] = fmaxf(rmx[0], __shfl_xor_sync(0xffffffffu, rmx[0], msk));
            rmx[1] = fmaxf(rmx[1], __shfl_xor_sync(0xffffffffu, rmx[1], msk));
        }
        if (t4 == 0) {
            redmax[(16 * wr + g) * 2 + wc]     = rmx[0];
            redmax[(16 * wr + g + 8) * 2 + wc] = rmx[1];
        }
        __syncthreads();

        float mnew[2], corr[2];
#pragma unroll
        for (int hh = 0; hh < 2; hh++) {
            int row = 16 * wr + g + 8 * hh;
            float rm = fmaxf(redmax[row * 2], redmax[row * 2 + 1]);
            mnew[hh] = fmaxf(m_r[hh], rm);
            corr[hh] = __expf(m_r[hh] - mnew[hh]);
            m_r[hh]  = mnew[hh];
        }
        float rs[2] = {0.f, 0.f};
#pragma unroll
        for (int nf = 0; nf < 4; nf++)
#pragma unroll
            for (int e = 0; e < 4; e++) {
                float p = __expf(sc[nf][e] - mnew[e >> 1]);
                sc[nf][e] = p;
                rs[e >> 1] += p;
            }
#pragma unroll
        for (int msk = 1; msk < 4; msk <<= 1) {
            rs[0] += __shfl_xor_sync(0xffffffffu, rs[0], msk);
            rs[1] += __shfl_xor_sync(0xffffffffu, rs[1], msk);
        }
        if (t4 == 0) {
            redsum[(16 * wr + g) * 2 + wc]     = rs[0];
            redsum[(16 * wr + g + 8) * 2 + wc] = rs[1];
        }
#pragma unroll
        for (int nf = 0; nf < 4; nf++)
#pragma unroll
            for (int he = 0; he < 2; he++) {
                int row = 16 * wr + g + 8 * he;
                int h2c = 16 * wc + 4 * nf + t4;
                Psu[row * 36 + h2c] = h2(sc[nf][2 * he], sc[nf][2 * he + 1]);
            }
        __syncthreads();

#pragma unroll
        for (int hh = 0; hh < 2; hh++) {
            int row = 16 * wr + g + 8 * hh;
            l_r[hh] = l_r[hh] * corr[hh] + redsum[row * 2] + redsum[row * 2 + 1];
        }
#pragma unroll
        for (int nf = 0; nf < 4; nf++)
#pragma unroll
            for (int e = 0; e < 4; e++) acc[nf][e] *= corr[e >> 1];

        {
            const uint32_t* Ap = Psu + (16 * wr + g) * 36 + t4;
#pragma unroll
            for (int kk = 0; kk < 4; kk++) {
                uint32_t a0 = Ap[8 * kk];
                uint32_t a1 = Ap[8 * 36 + 8 * kk];
                uint32_t a2 = Ap[8 * kk + 4];
                uint32_t a3 = Ap[8 * 36 + 8 * kk + 4];
                uint32_t rowaddr = vbase + (((16 * kk + (lane & 15)) * 36) + 16 * wc) * 4;
#pragma unroll
                for (int nf = 0; nf < 4; nf++) {
                    uint32_t b0, b1;
                    asm volatile(
                        "ldmatrix.sync.aligned.m8n8.x2.trans.shared.b16 {%0,%1}, [%2];"
                        : "=r"(b0), "=r"(b1) : "r"(rowaddr + nf * 16));
                    mma_f16(acc[nf], a0, a1, a2, a3, b0, b1);
                }
            }
        }
    }

    float inv[2] = {1.f / l_r[0], 1.f / l_r[1]};
#pragma unroll
    for (int nf = 0; nf < 4; nf++)
#pragma unroll
        for (int e = 0; e < 4; e++) {
            int srow = s0 + 16 * wr + g + 8 * (e >> 1);
            int p    = 2 * t4 + (e & 1) + 8 * nf + 32 * wc;
            OUT[(size_t)(b * S_LEN + srow) * EMBED + hoff + p] = acc[nf][e] * inv[e >> 1];
        }
}

// ---------------- launch ----------------
extern "C" void kernel_launch(void* const* d_in, const int* in_sizes, int n_in,
                              void* d_out, int out_size)
{
    const float* x   = (const float*)d_in[0];
    const float* Wq  = (const float*)d_in[1];
    const float* bq  = (const float*)d_in[2];
    const float* Wk  = (const float*)d_in[3];
    const float* bk  = (const float*)d_in[4];
    const float* Wv  = (const float*)d_in[5];
    const float* bv_ = (const float*)d_in[6];
    const float* Wp  = (const float*)d_in[7];
    const float* bp  = (const float*)d_in[8];
    const float* Wo  = (const float*)d_in[9];
    const float* bo  = (const float*)d_in[10];
    const float* u   = (const float*)d_in[11];
    const float* v   = (const float*)d_in[12];
    float* out = (float*)d_out;

    float *psin, *ppos, *pq, *pk, *pv, *pattn, *puk, *pve;
    cudaGetSymbolAddress((void**)&psin,  g_sin);
    cudaGetSymbolAddress((void**)&ppos,  g_pos);
    cudaGetSymbolAddress((void**)&pq,    g_q);
    cudaGetSymbolAddress((void**)&pk,    g_k);
    cudaGetSymbolAddress((void**)&pv,    g_v);
    cudaGetSymbolAddress((void**)&pattn, g_attn);
    cudaGetSymbolAddress((void**)&puk,   g_uk);
    cudaGetSymbolAddress((void**)&pve,   g_ve);

    cudaFuncSetAttribute(attn_kernel, cudaFuncAttributeMaxDynamicSharedMemorySize,
                         ATT_SMEM_U32 * 4);

    invf_kernel<<<2, 256>>>();
    sinusoid_kernel<<<(S_LEN * (EMBED / 2) + 255) / 256, 256>>>();

    dim3 gBig(EMBED / 128, (BATCH * S_LEN) / 128);         // (8, 32)
    dim3 gQKV(EMBED / 128, (BATCH * S_LEN) / 128, 3);      // (8, 32, 3)
    dim3 gPos(EMBED / 128, S_LEN / 128);                   // (8, 16)

    gemm_tf32_qkv_kernel<<<gQKV, 256>>>(x, Wq, bq, Wk, bk, Wv, bv_,
                                        pq, pk, pv, BATCH * S_LEN, EMBED, EMBED);
    gemm_tf32_kernel<<<gPos, 256>>>(psin, Wp, bp, ppos, S_LEN, EMBED, EMBED);

    int nwarp = BATCH * NHEAD * S_LEN + NHEAD * S_LEN;
    ukve_kernel<<<(nwarp * 32 + 255) / 256, 256>>>(pk, ppos, u, v);

    dim3 gAtt(S_LEN / 64, NHEAD, BATCH);                   // (32, 16, 2)
    attn_kernel<<<gAtt, 256, ATT_SMEM_U32 * 4>>>(pq, pk, pv, ppos, puk, pve, pattn);

    gemm_f16x3_kernel<<<gBig, 256>>>(pattn, Wo, bo, out, BATCH * S_LEN, EMBED, EMBED);
}

// round 11
// speedup vs baseline: 4.5580x; 1.0533x over previous
#include <cuda_runtime.h>
#include <cuda_fp16.h>
#include <math.h>
#include <stdint.h>

#define S_LEN 2048
#define BATCH 2
#define EMBED 1024
#define NHEAD 16
#define HDIM  64

// ---------------- scratch (static device globals; no allocation) ----------------
__device__ float g_sin[S_LEN * EMBED];
__device__ float g_pos[S_LEN * EMBED];
__device__ float g_q[BATCH * S_LEN * EMBED];
__device__ float g_k[BATCH * S_LEN * EMBED];
__device__ float g_v[BATCH * S_LEN * EMBED];
__device__ float g_attn[BATCH * S_LEN * EMBED];
__device__ float g_uk[BATCH * NHEAD * S_LEN];   // u . k_t   per (b,h,t)
__device__ float g_ve[NHEAD * S_LEN];           // v . pos_c per (h,c)
__device__ float g_invf[EMBED / 2];             // double-exact inv_freq

// ---------------- sinusoid position embedding (fp32 fast path) ----------------
__global__ void invf_kernel() {
    int i = blockIdx.x * blockDim.x + threadIdx.x;
    if (i >= EMBED / 2) return;
    double invf = exp(-(2.0 * (double)i / (double)EMBED) * log(10000.0));
    g_invf[i] = (float)invf;
}

__global__ void sinusoid_kernel() {
    int idx = blockIdx.x * blockDim.x + threadIdx.x;
    if (idx >= S_LEN * (EMBED / 2)) return;
    int s = idx / (EMBED / 2);
    int i = idx % (EMBED / 2);
    float ang = (float)s * g_invf[i];
    float sv, cv;
    sincosf(ang, &sv, &cv);
    g_sin[s * EMBED + i]             = sv;
    g_sin[s * EMBED + (EMBED/2) + i] = cv;
}

// ---------------- UK/VE precompute: one warp per dot-64 (fp32 exact) ----------------
__global__ void ukve_kernel(const float* __restrict__ K, const float* __restrict__ POS,
                            const float* __restrict__ u, const float* __restrict__ v)
{
    int w    = (blockIdx.x * blockDim.x + threadIdx.x) >> 5;
    int lane = threadIdx.x & 31;
    const int UKW = BATCH * NHEAD * S_LEN;
    if (w < UKW) {
        int t = w & (S_LEN - 1);
        int h = (w >> 11) & (NHEAD - 1);
        int b = w >> 15;
        const float* kp = K + ((size_t)(b * S_LEN + t)) * EMBED + h * HDIM;
        const float* up = u + h * HDIM;
        float s = kp[lane] * up[lane] + kp[lane + 32] * up[lane + 32];
#pragma unroll
        for (int m = 16; m; m >>= 1) s += __shfl_xor_sync(~0u, s, m);
        if (!lane) g_uk[w] = s;
    } else if (w < UKW + NHEAD * S_LEN) {
        int w2 = w - UKW;
        int c = w2 & (S_LEN - 1);
        int h = w2 >> 11;
        const float* pp = POS + (size_t)c * EMBED + h * HDIM;
        const float* vp = v + h * HDIM;
        float s = pp[lane] * vp[lane] + pp[lane + 32] * vp[lane + 32];
#pragma unroll
        for (int m = 16; m; m >>= 1) s += __shfl_xor_sync(~0u, s, m);
        if (!lane) g_ve[w2] = s;
    }
}

// ---------------- helpers ----------------
__device__ __forceinline__ float tf32f(float f) {
    uint32_t u;
    asm("cvt.rna.tf32.f32 %0, %1;" : "=r"(u) : "f"(f));
    return __uint_as_float(u);
}
__device__ __forceinline__ uint32_t fb(float f) { return __float_as_uint(f); }
__device__ __forceinline__ uint32_t h2(float x, float y) {
    __half2 h = __floats2half2_rn(x, y);
    return *(uint32_t*)&h;
}
__device__ __forceinline__ void split2(float x, float y, uint32_t& hi, uint32_t& lo) {
    __half hx = __float2half_rn(x), hy = __float2half_rn(y);
    float rx = x - __half2float(hx), ry = y - __half2float(hy);
    __half2 hh; hh.x = hx; hh.y = hy;
    hi = *(uint32_t*)&hh;
    lo = h2(rx, ry);
}
__device__ __forceinline__ void mma_tf32(float* d,
    uint32_t a0, uint32_t a1, uint32_t a2, uint32_t a3, uint32_t b0, uint32_t b1)
{
    asm volatile(
        "mma.sync.aligned.m16n8k8.row.col.f32.tf32.tf32.f32 "
        "{%0,%1,%2,%3}, {%4,%5,%6,%7}, {%8,%9}, {%0,%1,%2,%3};"
        : "+f"(d[0]), "+f"(d[1]), "+f"(d[2]), "+f"(d[3])
        : "r"(a0), "r"(a1), "r"(a2), "r"(a3), "r"(b0), "r"(b1));
}
__device__ __forceinline__ void mma_f16(float* d,
    uint32_t a0, uint32_t a1, uint32_t a2, uint32_t a3, uint32_t b0, uint32_t b1)
{
    asm volatile(
        "mma.sync.aligned.m16n8k16.row.col.f32.f16.f16.f32 "
        "{%0,%1,%2,%3}, {%4,%5,%6,%7}, {%8,%9}, {%0,%1,%2,%3};"
        : "+f"(d[0]), "+f"(d[1]), "+f"(d[2]), "+f"(d[3])
        : "r"(a0), "r"(a1), "r"(a2), "r"(a3), "r"(b0), "r"(b1));
}

// ---------------- tf32 tensor-core GEMM + bias (software-pipelined) ----------------
// Rotation: sync -> store(cur) -> sync -> issue load(next) -> MMA -> cur=next.
// The gmem load latency overlaps the same iteration's MMA + barrier window.
__device__ __forceinline__ void gemm_tf32_body(
    const float* __restrict__ A, const float* __restrict__ B,
    const float* __restrict__ bias, float* __restrict__ C,
    int N, int K)
{
    __shared__ float As[128 * 20];
    __shared__ float Bs[16 * 136];
    const int tid  = threadIdx.x;
    const int lane = tid & 31;
    const int wid  = tid >> 5;
    const int wr   = wid >> 2;
    const int wc   = wid & 3;
    const int g    = lane >> 2;
    const int t4   = lane & 3;
    const int m0   = blockIdx.y * 128;
    const int n0   = blockIdx.x * 128;

    float acc[4][4][4];
#pragma unroll
    for (int mf = 0; mf < 4; mf++)
#pragma unroll
        for (int nf = 0; nf < 4; nf++)
#pragma unroll
            for (int e = 0; e < 4; e++) acc[mf][nf][e] = 0.f;

    const int a_row = tid >> 2;
    const int a_k4  = (tid & 3) * 4;
    const int b_k   = tid >> 4;
    const int b_n4  = (tid & 15) * 4;

    const float* Ap = A + (size_t)(m0 + a_row) * K + a_k4;
    const float* Bp = B + (size_t)b_k * N + n0 + b_n4;

    // prologue: preload k0 = 0
    float4 av0 = *(const float4*)(Ap);
    float4 av1 = *(const float4*)(Ap + (size_t)64 * K);
    float4 bv0 = *(const float4*)(Bp);
    float4 bv1 = *(const float4*)(Bp + 64);

    for (int k0 = 0; k0 < K; k0 += 16) {
        __syncthreads();                     // prev MMA smem reads done
        float* as0 = As + a_row * 20 + a_k4;
        as0[0] = tf32f(av0.x); as0[1] = tf32f(av0.y);
        as0[2] = tf32f(av0.z); as0[3] = tf32f(av0.w);
        float* as1 = As + (a_row + 64) * 20 + a_k4;
        as1[0] = tf32f(av1.x); as1[1] = tf32f(av1.y);
        as1[2] = tf32f(av1.z); as1[3] = tf32f(av1.w);
        float* bs0 = Bs + b_k * 136 + b_n4;
        bs0[0] = tf32f(bv0.x); bs0[1] = tf32f(bv0.y);
        bs0[2] = tf32f(bv0.z); bs0[3] = tf32f(bv0.w);
        float* bs1 = bs0 + 64;
        bs1[0] = tf32f(bv1.x); bs1[1] = tf32f(bv1.y);
        bs1[2] = tf32f(bv1.z); bs1[3] = tf32f(bv1.w);
        __syncthreads();

        // issue next-iteration gmem loads NOW (overlap with MMA below)
        int kn = (k0 + 16 < K) ? (k0 + 16) : 0;   // dummy reload on last iter
        av0 = *(const float4*)(Ap + kn);
        av1 = *(const float4*)(Ap + (size_t)64 * K + kn);
        bv0 = *(const float4*)(Bp + (size_t)kn * N);
        bv1 = *(const float4*)(Bp + (size_t)kn * N + 64);

#pragma unroll
        for (int kk = 0; kk < 2; kk++) {
            uint32_t af[4][4];
#pragma unroll
            for (int mf = 0; mf < 4; mf++) {
                const float* pa = As + (64 * wr + 16 * mf + g) * 20 + 8 * kk + t4;
                af[mf][0] = fb(pa[0]);
                af[mf][1] = fb(pa[8 * 20]);
                af[mf][2] = fb(pa[4]);
                af[mf][3] = fb(pa[8 * 20 + 4]);
            }
#pragma unroll
            for (int nf = 0; nf < 4; nf++) {
                const float* pb = Bs + (8 * kk + t4) * 136 + 32 * wc + 8 * nf + g;
                uint32_t b0 = fb(pb[0]);
                uint32_t b1 = fb(pb[4 * 136]);
#pragma unroll
                for (int mf = 0; mf < 4; mf++)
                    mma_tf32(acc[mf][nf], af[mf][0], af[mf][1], af[mf][2], af[mf][3], b0, b1);
            }
        }
    }
#pragma unroll
    for (int mf = 0; mf < 4; mf++)
#pragma unroll
        for (int nf = 0; nf < 4; nf++)
#pragma unroll
            for (int h2i = 0; h2i < 2; h2i++) {
                int row = m0 + 64 * wr + 16 * mf + g + 8 * h2i;
                int col = n0 + 32 * wc + 8 * nf + 2 * t4;
                float2 o;
                o.x = acc[mf][nf][2 * h2i + 0] + bias[col];
                o.y = acc[mf][nf][2 * h2i + 1] + bias[col + 1];
                *(float2*)&C[(size_t)row * N + col] = o;
            }
}

// Q/K/V/pos fused into ONE launch via blockIdx.z (z=3 is the pos proj, y<16)
__global__ void __launch_bounds__(256, 2) gemm_tf32_qkvp_kernel(
    const float* __restrict__ x, const float* __restrict__ sinu,
    const float* __restrict__ W0, const float* __restrict__ c0,
    const float* __restrict__ W1, const float* __restrict__ c1,
    const float* __restrict__ W2, const float* __restrict__ c2,
    const float* __restrict__ W3, const float* __restrict__ c3,
    float* __restrict__ O0, float* __restrict__ O1, float* __restrict__ O2,
    float* __restrict__ O3, int N, int K)
{
    const float* A; const float* B; const float* bias; float* C;
    if (blockIdx.z == 0)      { A = x;    B = W0; bias = c0; C = O0; }
    else if (blockIdx.z == 1) { A = x;    B = W1; bias = c1; C = O1; }
    else if (blockIdx.z == 2) { A = x;    B = W2; bias = c2; C = O2; }
    else {
        if (blockIdx.y >= 16) return;    // pos proj has M = 2048 only
        A = sinu; B = W3; bias = c3; C = O3;
    }
    gemm_tf32_body(A, B, bias, C, N, K);
}

// ---------------- fp16-split tensor-core GEMM + bias (out-proj; ~fp32 accuracy) ----
// C ~= a1w1 + a1w2 + a2w1 (hi/lo fp16 splits). Software-pipelined like above.
#define OP_AST 12
#define OP_WST 68
__global__ void __launch_bounds__(256, 2) gemm_f16x3_kernel(
    const float* __restrict__ A, const float* __restrict__ W,
    const float* __restrict__ bias, float* __restrict__ C,
    int M, int N, int K)
{
    __shared__ uint32_t A1[128 * OP_AST];
    __shared__ uint32_t A2[128 * OP_AST];
    __shared__ uint32_t W1[16 * OP_WST];
    __shared__ uint32_t W2[16 * OP_WST];
    const int tid  = threadIdx.x;
    const int lane = tid & 31;
    const int wid  = tid >> 5;
    const int wr   = wid >> 2;
    const int wc   = wid & 3;
    const int g    = lane >> 2;
    const int t4   = lane & 3;
    const int m0   = blockIdx.y * 128;
    const int n0   = blockIdx.x * 128;

    const uint32_t w1base = (uint32_t)__cvta_generic_to_shared(W1);
    const uint32_t w2base = (uint32_t)__cvta_generic_to_shared(W2);

    float acc[4][4][4];
#pragma unroll
    for (int mf = 0; mf < 4; mf++)
#pragma unroll
        for (int nf = 0; nf < 4; nf++)
#pragma unroll
            for (int e = 0; e < 4; e++) acc[mf][nf][e] = 0.f;

    const int a_row = tid >> 2;
    const int a_k4  = (tid & 3) * 4;
    const int b_k   = tid >> 4;
    const int b_n4  = (tid & 15) * 4;

    const float* Ap = A + (size_t)(m0 + a_row) * K + a_k4;
    const float* Wp = W + (size_t)b_k * N + n0 + b_n4;

    // prologue
    float4 av0 = *(const float4*)(Ap);
    float4 av1 = *(const float4*)(Ap + (size_t)64 * K);
    float4 wv0 = *(const float4*)(Wp);
    float4 wv1 = *(const float4*)(Wp + 64);

    for (int k0 = 0; k0 < K; k0 += 16) {
        __syncthreads();
        {
            uint32_t hi, lo;
            uint32_t* p1 = A1 + a_row * OP_AST + (a_k4 >> 1);
            uint32_t* p2 = A2 + a_row * OP_AST + (a_k4 >> 1);
            split2(av0.x, av0.y, hi, lo); p1[0] = hi; p2[0] = lo;
            split2(av0.z, av0.w, hi, lo); p1[1] = hi; p2[1] = lo;
            p1 = A1 + (a_row + 64) * OP_AST + (a_k4 >> 1);
            p2 = A2 + (a_row + 64) * OP_AST + (a_k4 >> 1);
            split2(av1.x, av1.y, hi, lo); p1[0] = hi; p2[0] = lo;
            split2(av1.z, av1.w, hi, lo); p1[1] = hi; p2[1] = lo;

            uint32_t* q1 = W1 + b_k * OP_WST + (b_n4 >> 1);
            uint32_t* q2 = W2 + b_k * OP_WST + (b_n4 >> 1);
            split2(wv0.x, wv0.y, hi, lo); q1[0] = hi; q2[0] = lo;
            split2(wv0.z, wv0.w, hi, lo); q1[1] = hi; q2[1] = lo;
            split2(wv1.x, wv1.y, hi, lo); q1[32] = hi; q2[32] = lo;
            split2(wv1.z, wv1.w, hi, lo); q1[33] = hi; q2[33] = lo;
        }
        __syncthreads();

        // issue next-iteration gmem loads (overlap with MMA)
        int kn = (k0 + 16 < K) ? (k0 + 16) : 0;
        av0 = *(const float4*)(Ap + kn);
        av1 = *(const float4*)(Ap + (size_t)64 * K + kn);
        wv0 = *(const float4*)(Wp + (size_t)kn * N);
        wv1 = *(const float4*)(Wp + (size_t)kn * N + 64);

        uint32_t af1[4][4], af2[4][4];
#pragma unroll
        for (int mf = 0; mf < 4; mf++) {
            const uint32_t* pa1 = A1 + (64 * wr + 16 * mf + g) * OP_AST + t4;
            const uint32_t* pa2 = A2 + (64 * wr + 16 * mf + g) * OP_AST + t4;
            af1[mf][0] = pa1[0];  af1[mf][1] = pa1[8 * OP_AST];
            af1[mf][2] = pa1[4];  af1[mf][3] = pa1[8 * OP_AST + 4];
            af2[mf][0] = pa2[0];  af2[mf][1] = pa2[8 * OP_AST];
            af2[mf][2] = pa2[4];  af2[mf][3] = pa2[8 * OP_AST + 4];
        }
#pragma unroll
        for (int nf = 0; nf < 4; nf++) {
            uint32_t off = (((lane & 15) * OP_WST) + 16 * wc + 4 * nf) * 4;
            uint32_t b10, b11, b20, b21;
            asm volatile("ldmatrix.sync.aligned.m8n8.x2.trans.shared.b16 {%0,%1}, [%2];"
                         : "=r"(b10), "=r"(b11) : "r"(w1base + off));
            asm volatile("ldmatrix.sync.aligned.m8n8.x2.trans.shared.b16 {%0,%1}, [%2];"
                         : "=r"(b20), "=r"(b21) : "r"(w2base + off));
#pragma unroll
            for (int mf = 0; mf < 4; mf++) {
                mma_f16(acc[mf][nf], af1[mf][0], af1[mf][1], af1[mf][2], af1[mf][3], b10, b11);
                mma_f16(acc[mf][nf], af1[mf][0], af1[mf][1], af1[mf][2], af1[mf][3], b20, b21);
                mma_f16(acc[mf][nf], af2[mf][0], af2[mf][1], af2[mf][2], af2[mf][3], b10, b11);
            }
        }
    }
#pragma unroll
    for (int mf = 0; mf < 4; mf++)
#pragma unroll
        for (int nf = 0; nf < 4; nf++)
#pragma unroll
            for (int he = 0; he < 2; he++) {
                int row = m0 + 64 * wr + 16 * mf + g + 8 * he;
                int col = n0 + 32 * wc + 8 * nf + 2 * t4;
                float2 o;
                o.x = acc[mf][nf][2 * he + 0] + bias[col];
                o.y = acc[mf][nf][2 * he + 1] + bias[col + 1];
                *(float2*)&C[(size_t)row * N + col] = o;
            }
}

// ---------------- fused relative attention (fp16 tensor-core flash) ----------------
// score[s][t] = ( q_s.k_t + UK[t] + shifted(q.E^T)[s][r] + VE[r] ) / 8
// d = t-s:  d<=0 -> pos[S-1+d] (row s); d==1 -> 0; d>=2 -> pos[d-2] (row s+1).
#define QS_OFF   0        // 65*36
#define KS_OFF   2340     // 64*36
#define VS_OFF   4644     // 64*36
#define ES_OFF   6948     // 128*36
#define GS_OFF   11556    // 64*66 (Ps aliases, stride 36)
#define UK_OFF   15780    // 64 f32
#define VE_OFF   15844    // 128 f32
#define RMX_OFF  15972    // 128 f32
#define RSM_OFF  16100    // 128 f32
#define ATT_SMEM_U32 16228  // 64,912 B -> 3 blocks/SM

__global__ void __launch_bounds__(256, 3) attn_kernel(
    const float* __restrict__ Q, const float* __restrict__ Km,
    const float* __restrict__ Vm, const float* __restrict__ POS,
    const float* __restrict__ UK, const float* __restrict__ VE,
    float* __restrict__ OUT)
{
    extern __shared__ uint32_t su[];
    uint32_t* Qsu = su + QS_OFF;
    uint32_t* Ksu = su + KS_OFF;
    uint32_t* Vsu = su + VS_OFF;
    uint32_t* Esu = su + ES_OFF;
    uint32_t* Gsu = su + GS_OFF;
    uint32_t* Psu = su + GS_OFF;            // alias (disjoint lifetimes)
    __half*   Gh  = (__half*)(su + GS_OFF);
    float* UKs    = (float*)(su + UK_OFF);
    float* VEs    = (float*)(su + VE_OFF);
    float* redmax = (float*)(su + RMX_OFF);
    float* redsum = (float*)(su + RSM_OFF);

    const int tid  = threadIdx.x;
    const int lane = tid & 31;
    const int wid  = tid >> 5;
    const int wr   = wid >> 1;
    const int wc   = wid & 1;
    const int g    = lane >> 2;
    const int t4   = lane & 3;

    const int s0   = blockIdx.x * 64;
    const int h    = blockIdx.y;
    const int b    = blockIdx.z;
    const int hoff = h * HDIM;

    const uint32_t vbase = (uint32_t)__cvta_generic_to_shared(Vsu);

    if (tid < 32) Esu[127 * 36 + tid] = 0u;
    for (int q4 = tid; q4 < 65 * 16; q4 += 256) {
        int row = q4 >> 4;
        int p4  = (q4 & 15) * 4;
        int s   = s0 + row; if (s > S_LEN - 1) s = S_LEN - 1;
        float4 qv = *(const float4*)(Q + (size_t)(b * S_LEN + s) * EMBED + hoff + p4);
        Qsu[row * 36 + (p4 >> 1)]     = h2(qv.x, qv.y);
        Qsu[row * 36 + (p4 >> 1) + 1] = h2(qv.z, qv.w);
    }

    float acc[4][4];
    float m_r[2], l_r[2];
#pragma unroll
    for (int nf = 0; nf < 4; nf++)
#pragma unroll
        for (int e = 0; e < 4; e++) acc[nf][e] = 0.f;
    m_r[0] = m_r[1] = -1e30f;
    l_r[0] = l_r[1] = 0.f;

    for (int t0 = 0; t0 < S_LEN; t0 += 64) {
        const int diag = t0 - s0;
        __syncthreads();

        for (int q4 = tid; q4 < 64 * 16; q4 += 256) {
            int row = q4 >> 4;
            int p4  = (q4 & 15) * 4;
            size_t go = (size_t)(b * S_LEN + t0 + row) * EMBED + hoff + p4;
            float4 kv = *(const float4*)(Km + go);
            float4 vv = *(const float4*)(Vm + go);
            Ksu[row * 36 + (p4 >> 1)]     = h2(kv.x, kv.y);
            Ksu[row * 36 + (p4 >> 1) + 1] = h2(kv.z, kv.w);
            Vsu[row * 36 + (p4 >> 1)]     = h2(vv.x, vv.y);
            Vsu[row * 36 + (p4 >> 1) + 1] = h2(vv.z, vv.w);
        }
        for (int q4 = tid; q4 < 127 * 16; q4 += 256) {
            int r  = q4 >> 4;
            int p4 = (q4 & 15) * 4;
            int d  = diag - 63 + r;
            int c  = (d <= 0) ? (S_LEN - 1 + d) : ((d == 1) ? -1 : (d - 2));
            float4 pv = make_float4(0.f, 0.f, 0.f, 0.f);
            if (c >= 0)
                pv = *(const float4*)(POS + (size_t)c * EMBED + hoff + p4);
            Esu[r * 36 + (p4 >> 1)]     = h2(pv.x, pv.y);
            Esu[r * 36 + (p4 >> 1) + 1] = h2(pv.z, pv.w);
        }
        if (tid < 64) UKs[tid] = UK[((b * NHEAD + h) << 11) + t0 + tid];
        if (tid < 128) {
            int r = tid;
            float val = 0.f;
            if (r < 127) {
                int d = diag - 63 + r;
                int c = (d <= 0) ? (S_LEN - 1 + d) : ((d == 1) ? -1 : (d - 2));
                if (c >= 0) val = VE[(h << 11) + c];
            }
            VEs[r] = val;
        }
        __syncthreads();

        float sc[4][4];
#pragma unroll
        for (int nf = 0; nf < 4; nf++)
#pragma unroll
            for (int e = 0; e < 4; e++) sc[nf][e] = 0.f;
        {
            const uint32_t* Aq = Qsu + (16 * wr + g) * 36 + t4;
            const uint32_t* Bk = Ksu + (32 * wc + g) * 36 + t4;
#pragma unroll
            for (int kk = 0; kk < 4; kk++) {
                uint32_t a0 = Aq[8 * kk];
                uint32_t a1 = Aq[8 * 36 + 8 * kk];
                uint32_t a2 = Aq[8 * kk + 4];
                uint32_t a3 = Aq[8 * 36 + 8 * kk + 4];
#pragma unroll
                for (int nf = 0; nf < 4; nf++) {
                    uint32_t b0 = Bk[nf * 8 * 36 + 8 * kk];
                    uint32_t b1 = Bk[nf * 8 * 36 + 8 * kk + 4];
                    mma_f16(sc[nf], a0, a1, a2, a3, b0, b1);
                }
            }
        }

        const bool passA = (diag <= 0);
        const bool passB = (diag >= 0);
#pragma unroll 1
        for (int pass = 0; pass < 2; pass++) {
            if (pass == 0 && !passA) continue;
            if (pass == 1 && !passB) continue;
            if (pass == 1 && passA) __syncthreads();

            const uint32_t* Aq = Qsu + (16 * wr + g + pass) * 36 + t4;
#pragma unroll 1
            for (int ch = 0; ch < 2; ch++) {
                float ga[4][4];
#pragma unroll
                for (int nf = 0; nf < 4; nf++)
#pragma unroll
                    for (int e = 0; e < 4; e++) ga[nf][e] = 0.f;
                const uint32_t* Be = Esu + (64 * wc + 32 * ch + g) * 36 + t4;
#pragma unroll
                for (int kk = 0; kk < 4; kk++) {
                    uint32_t a0 = Aq[8 * kk];
                    uint32_t a1 = Aq[8 * 36 + 8 * kk];
                    uint32_t a2 = Aq[8 * kk + 4];
                    uint32_t a3 = Aq[8 * 36 + 8 * kk + 4];
#pragma unroll
                    for (int nf = 0; nf < 4; nf++) {
                        uint32_t b0 = Be[nf * 8 * 36 + 8 * kk];
                        uint32_t b1 = Be[nf * 8 * 36 + 8 * kk + 4];
                        mma_f16(ga[nf], a0, a1, a2, a3, b0, b1);
                    }
                }
#pragma unroll
                for (int nf = 0; nf < 4; nf++)
#pragma unroll
                    for (int he = 0; he < 2; he++) {
                        int row = 16 * wr + g + 8 * he;
                        int h2c = 32 * wc + 16 * ch + 4 * nf + t4;
                        Gsu[row * 66 + h2c] = h2(ga[nf][2 * he], ga[nf][2 * he + 1]);
                    }
            }
            __syncthreads();
#pragma unroll
            for (int nf = 0; nf < 4; nf++)
#pragma unroll
                for (int e = 0; e < 4; e++) {
                    int ss = 16 * wr + g + 8 * (e >> 1);
                    int tt = 2 * t4 + (e & 1) + 8 * nf + 32 * wc;
                    int d  = diag + tt - ss;
                    bool take = pass ? (d >= 2) : (d <= 0);
                    if (take) {
                        int r = tt - ss + 63;
                        sc[nf][e] += __half2float(Gh[ss * 132 + r]) + VEs[r];
                    }
                }
        }

#pragma unroll
        for (int nf = 0; nf < 4; nf++)
#pragma unroll
            for (int e = 0; e < 4; e++) {
                int tt = 2 * t4 + (e & 1) + 8 * nf + 32 * wc;
                sc[nf][e] = (sc[nf][e] + UKs[tt]) * 0.125f;
            }

        float rmx[2] = {-1e30f, -1e30f};
#pragma unroll
        for (int nf = 0; nf < 4; nf++)
#pragma unroll
            for (int e = 0; e < 4; e++)
                rmx[e >> 1] = fmaxf(rmx[e >> 1], sc[nf][e]);
#pragma unroll
        for (int msk = 1; msk < 4; msk <<= 1) {
            rmx[0] = fmaxf(rmx[0], __shfl_xor_sync(0xffffffffu, rmx[0], msk));
            rmx[1] = fmaxf(rmx[1], __shfl_xor_sync(0xffffffffu, rmx[1], msk));
        }
        if (t4 == 0) {
            redmax[(16 * wr + g) * 2 + wc]     = rmx[0];
            redmax[(16 * wr + g + 8) * 2 + wc] = rmx[1];
        }
        __syncthreads();

        float mnew[2], corr[2];
#pragma unroll
        for (int hh = 0; hh < 2; hh++) {
            int row = 16 * wr + g + 8 * hh;
            float rm = fmaxf(redmax[row * 2], redmax[row * 2 + 1]);
            mnew[hh] = fmaxf(m_r[hh], rm);
            corr[hh] = __expf(m_r[hh] - mnew[hh]);
            m_r[hh]  = mnew[hh];
        }
        float rs[2] = {0.f, 0.f};
#pragma unroll
        for (int nf = 0; nf < 4; nf++)
#pragma unroll
            for (int e = 0; e < 4; e++) {
                float p = __expf(sc[nf][e] - mnew[e >> 1]);
                sc[nf][e] = p;
                rs[e >> 1] += p;
            }
#pragma unroll
        for (int msk = 1; msk < 4; msk <<= 1) {
            rs[0] += __shfl_xor_sync(0xffffffffu, rs[0], msk);
            rs[1] += __shfl_xor_sync(0xffffffffu, rs[1], msk);
        }
        if (t4 == 0) {
            redsum[(16 * wr + g) * 2 + wc]     = rs[0];
            redsum[(16 * wr + g + 8) * 2 + wc] = rs[1];
        }
#pragma unroll
        for (int nf = 0; nf < 4; nf++)
#pragma unroll
            for (int he = 0; he < 2; he++) {
                int row = 16 * wr + g + 8 * he;
                int h2c = 16 * wc + 4 * nf + t4;
                Psu[row * 36 + h2c] = h2(sc[nf][2 * he], sc[nf][2 * he + 1]);
            }
        __syncthreads();

#pragma unroll
        for (int hh = 0; hh < 2; hh++) {
            int row = 16 * wr + g + 8 * hh;
            l_r[hh] = l_r[hh] * corr[hh] + redsum[row * 2] + redsum[row * 2 + 1];
        }
#pragma unroll
        for (int nf = 0; nf < 4; nf++)
#pragma unroll
            for (int e = 0; e < 4; e++) acc[nf][e] *= corr[e >> 1];

        {
            const uint32_t* Ap = Psu + (16 * wr + g) * 36 + t4;
#pragma unroll
            for (int kk = 0; kk < 4; kk++) {
                uint32_t a0 = Ap[8 * kk];
                uint32_t a1 = Ap[8 * 36 + 8 * kk];
                uint32_t a2 = Ap[8 * kk + 4];
                uint32_t a3 = Ap[8 * 36 + 8 * kk + 4];
                uint32_t rowaddr = vbase + (((16 * kk + (lane & 15)) * 36) + 16 * wc) * 4;
#pragma unroll
                for (int nf = 0; nf < 4; nf++) {
                    uint32_t b0, b1;
                    asm volatile(
                        "ldmatrix.sync.aligned.m8n8.x2.trans.shared.b16 {%0,%1}, [%2];"
                        : "=r"(b0), "=r"(b1) : "r"(rowaddr + nf * 16));
                    mma_f16(acc[nf], a0, a1, a2, a3, b0, b1);
                }
            }
        }
    }

    float inv[2] = {1.f / l_r[0], 1.f / l_r[1]};
#pragma unroll
    for (int nf = 0; nf < 4; nf++)
#pragma unroll
        for (int e = 0; e < 4; e++) {
            int srow = s0 + 16 * wr + g + 8 * (e >> 1);
            int p    = 2 * t4 + (e & 1) + 8 * nf + 32 * wc;
            OUT[(size_t)(b * S_LEN + srow) * EMBED + hoff + p] = acc[nf][e] * inv[e >> 1];
        }
}

// ---------------- launch ----------------
extern "C" void kernel_launch(void* const* d_in, const int* in_sizes, int n_in,
                              void* d_out, int out_size)
{
    const float* x   = (const float*)d_in[0];
    const float* Wq  = (const float*)d_in[1];
    const float* bq  = (const float*)d_in[2];
    const float* Wk  = (const float*)d_in[3];
    const float* bk  = (const float*)d_in[4];
    const float* Wv  = (const float*)d_in[5];
    const float* bv_ = (const float*)d_in[6];
    const float* Wp  = (const float*)d_in[7];
    const float* bp  = (const float*)d_in[8];
    const float* Wo  = (const float*)d_in[9];
    const float* bo  = (const float*)d_in[10];
    const float* u   = (const float*)d_in[11];
    const float* v   = (const float*)d_in[12];
    float* out = (float*)d_out;

    float *psin, *ppos, *pq, *pk, *pv, *pattn, *puk, *pve;
    cudaGetSymbolAddress((void**)&psin,  g_sin);
    cudaGetSymbolAddress((void**)&ppos,  g_pos);
    cudaGetSymbolAddress((void**)&pq,    g_q);
    cudaGetSymbolAddress((void**)&pk,    g_k);
    cudaGetSymbolAddress((void**)&pv,    g_v);
    cudaGetSymbolAddress((void**)&pattn, g_attn);
    cudaGetSymbolAddress((void**)&puk,   g_uk);
    cudaGetSymbolAddress((void**)&pve,   g_ve);

    cudaFuncSetAttribute(attn_kernel, cudaFuncAttributeMaxDynamicSharedMemorySize,
                         ATT_SMEM_U32 * 4);

    invf_kernel<<<2, 256>>>();
    sinusoid_kernel<<<(S_LEN * (EMBED / 2) + 255) / 256, 256>>>();

    dim3 gBig(EMBED / 128, (BATCH * S_LEN) / 128);         // (8, 32)
    dim3 gQKVP(EMBED / 128, (BATCH * S_LEN) / 128, 4);     // (8, 32, 4)

    gemm_tf32_qkvp_kernel<<<gQKVP, 256>>>(x, psin,
                                          Wq, bq, Wk, bk, Wv, bv_, Wp, bp,
                                          pq, pk, pv, ppos, EMBED, EMBED);

    int nwarp = BATCH * NHEAD * S_LEN + NHEAD * S_LEN;
    ukve_kernel<<<(nwarp * 32 + 255) / 256, 256>>>(pk, ppos, u, v);

    dim3 gAtt(S_LEN / 64, NHEAD, BATCH);                   // (32, 16, 2)
    attn_kernel<<<gAtt, 256, ATT_SMEM_U32 * 4>>>(pq, pk, pv, ppos, puk, pve, pattn);

    gemm_f16x3_kernel<<<gBig, 256>>>(pattn, Wo, bo, out, BATCH * S_LEN, EMBED, EMBED);
}

// round 12
// speedup vs baseline: 4.5652x; 1.0016x over previous
#include <cuda_runtime.h>
#include <cuda_fp16.h>
#include <math.h>
#include <stdint.h>

#define S_LEN 2048
#define BATCH 2
#define EMBED 1024
#define NHEAD 16
#define HDIM  64

// ---------------- scratch (static device globals; no allocation) ----------------
__device__ float g_sin[S_LEN * EMBED];
__device__ float g_pos[S_LEN * EMBED];
__device__ float g_q[BATCH * S_LEN * EMBED];
__device__ float g_k[BATCH * S_LEN * EMBED];
__device__ float g_v[BATCH * S_LEN * EMBED];
__device__ float g_attn[BATCH * S_LEN * EMBED];
__device__ float g_uk[BATCH * NHEAD * S_LEN];   // u . k_t   per (b,h,t)
__device__ float g_ve[NHEAD * S_LEN];           // v . pos_c per (h,c)
__device__ float g_invf[EMBED / 2];             // double-exact inv_freq

// ---------------- sinusoid position embedding (fp32 fast path) ----------------
__global__ void invf_kernel() {
    int i = blockIdx.x * blockDim.x + threadIdx.x;
    if (i >= EMBED / 2) return;
    double invf = exp(-(2.0 * (double)i / (double)EMBED) * log(10000.0));
    g_invf[i] = (float)invf;
}

__global__ void sinusoid_kernel() {
    int idx = blockIdx.x * blockDim.x + threadIdx.x;
    if (idx >= S_LEN * (EMBED / 2)) return;
    int s = idx / (EMBED / 2);
    int i = idx % (EMBED / 2);
    float ang = (float)s * g_invf[i];
    float sv, cv;
    sincosf(ang, &sv, &cv);
    g_sin[s * EMBED + i]             = sv;
    g_sin[s * EMBED + (EMBED/2) + i] = cv;
}

// ---------------- UK/VE precompute: one warp per dot-64 (fp32 exact) ----------------
__global__ void ukve_kernel(const float* __restrict__ K, const float* __restrict__ POS,
                            const float* __restrict__ u, const float* __restrict__ v)
{
    int w    = (blockIdx.x * blockDim.x + threadIdx.x) >> 5;
    int lane = threadIdx.x & 31;
    const int UKW = BATCH * NHEAD * S_LEN;
    if (w < UKW) {
        int t = w & (S_LEN - 1);
        int h = (w >> 11) & (NHEAD - 1);
        int b = w >> 15;
        const float* kp = K + ((size_t)(b * S_LEN + t)) * EMBED + h * HDIM;
        const float* up = u + h * HDIM;
        float s = kp[lane] * up[lane] + kp[lane + 32] * up[lane + 32];
#pragma unroll
        for (int m = 16; m; m >>= 1) s += __shfl_xor_sync(~0u, s, m);
        if (!lane) g_uk[w] = s;
    } else if (w < UKW + NHEAD * S_LEN) {
        int w2 = w - UKW;
        int c = w2 & (S_LEN - 1);
        int h = w2 >> 11;
        const float* pp = POS + (size_t)c * EMBED + h * HDIM;
        const float* vp = v + h * HDIM;
        float s = pp[lane] * vp[lane] + pp[lane + 32] * vp[lane + 32];
#pragma unroll
        for (int m = 16; m; m >>= 1) s += __shfl_xor_sync(~0u, s, m);
        if (!lane) g_ve[w2] = s;
    }
}

// ---------------- helpers ----------------
__device__ __forceinline__ float tf32f(float f) {
    uint32_t u;
    asm("cvt.rna.tf32.f32 %0, %1;" : "=r"(u) : "f"(f));
    return __uint_as_float(u);
}
__device__ __forceinline__ uint32_t fb(float f) { return __float_as_uint(f); }
__device__ __forceinline__ uint32_t h2(float x, float y) {
    __half2 h = __floats2half2_rn(x, y);
    return *(uint32_t*)&h;
}
__device__ __forceinline__ void split2(float x, float y, uint32_t& hi, uint32_t& lo) {
    __half hx = __float2half_rn(x), hy = __float2half_rn(y);
    float rx = x - __half2float(hx), ry = y - __half2float(hy);
    __half2 hh; hh.x = hx; hh.y = hy;
    hi = *(uint32_t*)&hh;
    lo = h2(rx, ry);
}
__device__ __forceinline__ void mma_tf32(float* d,
    uint32_t a0, uint32_t a1, uint32_t a2, uint32_t a3, uint32_t b0, uint32_t b1)
{
    asm volatile(
        "mma.sync.aligned.m16n8k8.row.col.f32.tf32.tf32.f32 "
        "{%0,%1,%2,%3}, {%4,%5,%6,%7}, {%8,%9}, {%0,%1,%2,%3};"
        : "+f"(d[0]), "+f"(d[1]), "+f"(d[2]), "+f"(d[3])
        : "r"(a0), "r"(a1), "r"(a2), "r"(a3), "r"(b0), "r"(b1));
}
__device__ __forceinline__ void mma_f16(float* d,
    uint32_t a0, uint32_t a1, uint32_t a2, uint32_t a3, uint32_t b0, uint32_t b1)
{
    asm volatile(
        "mma.sync.aligned.m16n8k16.row.col.f32.f16.f16.f32 "
        "{%0,%1,%2,%3}, {%4,%5,%6,%7}, {%8,%9}, {%0,%1,%2,%3};"
        : "+f"(d[0]), "+f"(d[1]), "+f"(d[2]), "+f"(d[3])
        : "r"(a0), "r"(a1), "r"(a2), "r"(a3), "r"(b0), "r"(b1));
}

// ---------------- tf32 tensor-core GEMM + bias (2-stage double buffer) ------------
// One sync per k-iter: while MMA runs on buf[cur], next tile stores to buf[cur^1].
__device__ __forceinline__ void gemm_tf32_body(
    const float* __restrict__ A, const float* __restrict__ B,
    const float* __restrict__ bias, float* __restrict__ C,
    int N, int K)
{
    __shared__ float As[2][128 * 20];
    __shared__ float Bs[2][16 * 136];
    const int tid  = threadIdx.x;
    const int lane = tid & 31;
    const int wid  = tid >> 5;
    const int wr   = wid >> 2;
    const int wc   = wid & 3;
    const int g    = lane >> 2;
    const int t4   = lane & 3;
    const int m0   = blockIdx.y * 128;
    const int n0   = blockIdx.x * 128;

    float acc[4][4][4];
#pragma unroll
    for (int mf = 0; mf < 4; mf++)
#pragma unroll
        for (int nf = 0; nf < 4; nf++)
#pragma unroll
            for (int e = 0; e < 4; e++) acc[mf][nf][e] = 0.f;

    const int a_row = tid >> 2;
    const int a_k4  = (tid & 3) * 4;
    const int b_k   = tid >> 4;
    const int b_n4  = (tid & 15) * 4;

    const float* Ap = A + (size_t)(m0 + a_row) * K + a_k4;
    const float* Bp = B + (size_t)b_k * N + n0 + b_n4;

    // prologue: load + store k0=0 into buf 0
    {
        float4 av0 = *(const float4*)(Ap);
        float4 av1 = *(const float4*)(Ap + (size_t)64 * K);
        float4 bv0 = *(const float4*)(Bp);
        float4 bv1 = *(const float4*)(Bp + 64);
        float* as0 = As[0] + a_row * 20 + a_k4;
        as0[0] = tf32f(av0.x); as0[1] = tf32f(av0.y);
        as0[2] = tf32f(av0.z); as0[3] = tf32f(av0.w);
        float* as1 = As[0] + (a_row + 64) * 20 + a_k4;
        as1[0] = tf32f(av1.x); as1[1] = tf32f(av1.y);
        as1[2] = tf32f(av1.z); as1[3] = tf32f(av1.w);
        float* bs0 = Bs[0] + b_k * 136 + b_n4;
        bs0[0] = tf32f(bv0.x); bs0[1] = tf32f(bv0.y);
        bs0[2] = tf32f(bv0.z); bs0[3] = tf32f(bv0.w);
        float* bs1 = bs0 + 64;
        bs1[0] = tf32f(bv1.x); bs1[1] = tf32f(bv1.y);
        bs1[2] = tf32f(bv1.z); bs1[3] = tf32f(bv1.w);
    }
    int cur = 0;

    for (int k0 = 0; k0 < K; k0 += 16) {
        __syncthreads();            // buf[cur] visible; buf[cur^1] readers (iter-2) done
        const bool more = (k0 + 16 < K);
        float4 av0, av1, bv0, bv1;
        if (more) {
            int kn = k0 + 16;
            av0 = *(const float4*)(Ap + kn);
            av1 = *(const float4*)(Ap + (size_t)64 * K + kn);
            bv0 = *(const float4*)(Bp + (size_t)kn * N);
            bv1 = *(const float4*)(Bp + (size_t)kn * N + 64);
        }

        const float* Acur = As[cur];
        const float* Bcur = Bs[cur];
#pragma unroll
        for (int kk = 0; kk < 2; kk++) {
            uint32_t af[4][4];
#pragma unroll
            for (int mf = 0; mf < 4; mf++) {
                const float* pa = Acur + (64 * wr + 16 * mf + g) * 20 + 8 * kk + t4;
                af[mf][0] = fb(pa[0]);
                af[mf][1] = fb(pa[8 * 20]);
                af[mf][2] = fb(pa[4]);
                af[mf][3] = fb(pa[8 * 20 + 4]);
            }
#pragma unroll
            for (int nf = 0; nf < 4; nf++) {
                const float* pb = Bcur + (8 * kk + t4) * 136 + 32 * wc + 8 * nf + g;
                uint32_t b0 = fb(pb[0]);
                uint32_t b1 = fb(pb[4 * 136]);
#pragma unroll
                for (int mf = 0; mf < 4; mf++)
                    mma_tf32(acc[mf][nf], af[mf][0], af[mf][1], af[mf][2], af[mf][3], b0, b1);
            }
        }

        if (more) {
            int nxt = cur ^ 1;
            float* as0 = As[nxt] + a_row * 20 + a_k4;
            as0[0] = tf32f(av0.x); as0[1] = tf32f(av0.y);
            as0[2] = tf32f(av0.z); as0[3] = tf32f(av0.w);
            float* as1 = As[nxt] + (a_row + 64) * 20 + a_k4;
            as1[0] = tf32f(av1.x); as1[1] = tf32f(av1.y);
            as1[2] = tf32f(av1.z); as1[3] = tf32f(av1.w);
            float* bs0 = Bs[nxt] + b_k * 136 + b_n4;
            bs0[0] = tf32f(bv0.x); bs0[1] = tf32f(bv0.y);
            bs0[2] = tf32f(bv0.z); bs0[3] = tf32f(bv0.w);
            float* bs1 = bs0 + 64;
            bs1[0] = tf32f(bv1.x); bs1[1] = tf32f(bv1.y);
            bs1[2] = tf32f(bv1.z); bs1[3] = tf32f(bv1.w);
            cur = nxt;
        }
    }
#pragma unroll
    for (int mf = 0; mf < 4; mf++)
#pragma unroll
        for (int nf = 0; nf < 4; nf++)
#pragma unroll
            for (int h2i = 0; h2i < 2; h2i++) {
                int row = m0 + 64 * wr + 16 * mf + g + 8 * h2i;
                int col = n0 + 32 * wc + 8 * nf + 2 * t4;
                float2 o;
                o.x = acc[mf][nf][2 * h2i + 0] + bias[col];
                o.y = acc[mf][nf][2 * h2i + 1] + bias[col + 1];
                *(float2*)&C[(size_t)row * N + col] = o;
            }
}

// Q/K/V/pos fused into ONE launch via blockIdx.z (z=3 is the pos proj, y<16)
__global__ void __launch_bounds__(256, 2) gemm_tf32_qkvp_kernel(
    const float* __restrict__ x, const float* __restrict__ sinu,
    const float* __restrict__ W0, const float* __restrict__ c0,
    const float* __restrict__ W1, const float* __restrict__ c1,
    const float* __restrict__ W2, const float* __restrict__ c2,
    const float* __restrict__ W3, const float* __restrict__ c3,
    float* __restrict__ O0, float* __restrict__ O1, float* __restrict__ O2,
    float* __restrict__ O3, int N, int K)
{
    const float* A; const float* B; const float* bias; float* C;
    if (blockIdx.z == 0)      { A = x;    B = W0; bias = c0; C = O0; }
    else if (blockIdx.z == 1) { A = x;    B = W1; bias = c1; C = O1; }
    else if (blockIdx.z == 2) { A = x;    B = W2; bias = c2; C = O2; }
    else {
        if (blockIdx.y >= 16) return;
        A = sinu; B = W3; bias = c3; C = O3;
    }
    gemm_tf32_body(A, B, bias, C, N, K);
}

// ---------------- fp16-split tensor-core GEMM + bias (out-proj; 2-stage) ----------
#define OP_AST 12
#define OP_WST 68
__global__ void __launch_bounds__(256, 2) gemm_f16x3_kernel(
    const float* __restrict__ A, const float* __restrict__ W,
    const float* __restrict__ bias, float* __restrict__ C,
    int M, int N, int K)
{
    __shared__ uint32_t A1[2][128 * OP_AST];
    __shared__ uint32_t A2[2][128 * OP_AST];
    __shared__ uint32_t W1[2][16 * OP_WST];
    __shared__ uint32_t W2[2][16 * OP_WST];
    const int tid  = threadIdx.x;
    const int lane = tid & 31;
    const int wid  = tid >> 5;
    const int wr   = wid >> 2;
    const int wc   = wid & 3;
    const int g    = lane >> 2;
    const int t4   = lane & 3;
    const int m0   = blockIdx.y * 128;
    const int n0   = blockIdx.x * 128;

    uint32_t w1b[2], w2b[2];
    w1b[0] = (uint32_t)__cvta_generic_to_shared(W1[0]);
    w1b[1] = (uint32_t)__cvta_generic_to_shared(W1[1]);
    w2b[0] = (uint32_t)__cvta_generic_to_shared(W2[0]);
    w2b[1] = (uint32_t)__cvta_generic_to_shared(W2[1]);

    float acc[4][4][4];
#pragma unroll
    for (int mf = 0; mf < 4; mf++)
#pragma unroll
        for (int nf = 0; nf < 4; nf++)
#pragma unroll
            for (int e = 0; e < 4; e++) acc[mf][nf][e] = 0.f;

    const int a_row = tid >> 2;
    const int a_k4  = (tid & 3) * 4;
    const int b_k   = tid >> 4;
    const int b_n4  = (tid & 15) * 4;

    const float* Ap = A + (size_t)(m0 + a_row) * K + a_k4;
    const float* Wp = W + (size_t)b_k * N + n0 + b_n4;

    // prologue into buf 0
    {
        float4 av0 = *(const float4*)(Ap);
        float4 av1 = *(const float4*)(Ap + (size_t)64 * K);
        float4 wv0 = *(const float4*)(Wp);
        float4 wv1 = *(const float4*)(Wp + 64);
        uint32_t hi, lo;
        uint32_t* p1 = A1[0] + a_row * OP_AST + (a_k4 >> 1);
        uint32_t* p2 = A2[0] + a_row * OP_AST + (a_k4 >> 1);
        split2(av0.x, av0.y, hi, lo); p1[0] = hi; p2[0] = lo;
        split2(av0.z, av0.w, hi, lo); p1[1] = hi; p2[1] = lo;
        p1 = A1[0] + (a_row + 64) * OP_AST + (a_k4 >> 1);
        p2 = A2[0] + (a_row + 64) * OP_AST + (a_k4 >> 1);
        split2(av1.x, av1.y, hi, lo); p1[0] = hi; p2[0] = lo;
        split2(av1.z, av1.w, hi, lo); p1[1] = hi; p2[1] = lo;
        uint32_t* q1 = W1[0] + b_k * OP_WST + (b_n4 >> 1);
        uint32_t* q2 = W2[0] + b_k * OP_WST + (b_n4 >> 1);
        split2(wv0.x, wv0.y, hi, lo); q1[0] = hi; q2[0] = lo;
        split2(wv0.z, wv0.w, hi, lo); q1[1] = hi; q2[1] = lo;
        split2(wv1.x, wv1.y, hi, lo); q1[32] = hi; q2[32] = lo;
        split2(wv1.z, wv1.w, hi, lo); q1[33] = hi; q2[33] = lo;
    }
    int cur = 0;

    for (int k0 = 0; k0 < K; k0 += 16) {
        __syncthreads();
        const bool more = (k0 + 16 < K);
        float4 av0, av1, wv0, wv1;
        if (more) {
            int kn = k0 + 16;
            av0 = *(const float4*)(Ap + kn);
            av1 = *(const float4*)(Ap + (size_t)64 * K + kn);
            wv0 = *(const float4*)(Wp + (size_t)kn * N);
            wv1 = *(const float4*)(Wp + (size_t)kn * N + 64);
        }

        uint32_t af1[4][4], af2[4][4];
#pragma unroll
        for (int mf = 0; mf < 4; mf++) {
            const uint32_t* pa1 = A1[cur] + (64 * wr + 16 * mf + g) * OP_AST + t4;
            const uint32_t* pa2 = A2[cur] + (64 * wr + 16 * mf + g) * OP_AST + t4;
            af1[mf][0] = pa1[0];  af1[mf][1] = pa1[8 * OP_AST];
            af1[mf][2] = pa1[4];  af1[mf][3] = pa1[8 * OP_AST + 4];
            af2[mf][0] = pa2[0];  af2[mf][1] = pa2[8 * OP_AST];
            af2[mf][2] = pa2[4];  af2[mf][3] = pa2[8 * OP_AST + 4];
        }
#pragma unroll
        for (int nf = 0; nf < 4; nf++) {
            uint32_t off = (((lane & 15) * OP_WST) + 16 * wc + 4 * nf) * 4;
            uint32_t b10, b11, b20, b21;
            asm volatile("ldmatrix.sync.aligned.m8n8.x2.trans.shared.b16 {%0,%1}, [%2];"
                         : "=r"(b10), "=r"(b11) : "r"(w1b[cur] + off));
            asm volatile("ldmatrix.sync.aligned.m8n8.x2.trans.shared.b16 {%0,%1}, [%2];"
                         : "=r"(b20), "=r"(b21) : "r"(w2b[cur] + off));
#pragma unroll
            for (int mf = 0; mf < 4; mf++) {
                mma_f16(acc[mf][nf], af1[mf][0], af1[mf][1], af1[mf][2], af1[mf][3], b10, b11);
                mma_f16(acc[mf][nf], af1[mf][0], af1[mf][1], af1[mf][2], af1[mf][3], b20, b21);
                mma_f16(acc[mf][nf], af2[mf][0], af2[mf][1], af2[mf][2], af2[mf][3], b10, b11);
            }
        }

        if (more) {
            int nxt = cur ^ 1;
            uint32_t hi, lo;
            uint32_t* p1 = A1[nxt] + a_row * OP_AST + (a_k4 >> 1);
            uint32_t* p2 = A2[nxt] + a_row * OP_AST + (a_k4 >> 1);
            split2(av0.x, av0.y, hi, lo); p1[0] = hi; p2[0] = lo;
            split2(av0.z, av0.w, hi, lo); p1[1] = hi; p2[1] = lo;
            p1 = A1[nxt] + (a_row + 64) * OP_AST + (a_k4 >> 1);
            p2 = A2[nxt] + (a_row + 64) * OP_AST + (a_k4 >> 1);
            split2(av1.x, av1.y, hi, lo); p1[0] = hi; p2[0] = lo;
            split2(av1.z, av1.w, hi, lo); p1[1] = hi; p2[1] = lo;
            uint32_t* q1 = W1[nxt] + b_k * OP_WST + (b_n4 >> 1);
            uint32_t* q2 = W2[nxt] + b_k * OP_WST + (b_n4 >> 1);
            split2(wv0.x, wv0.y, hi, lo); q1[0] = hi; q2[0] = lo;
            split2(wv0.z, wv0.w, hi, lo); q1[1] = hi; q2[1] = lo;
            split2(wv1.x, wv1.y, hi, lo); q1[32] = hi; q2[32] = lo;
            split2(wv1.z, wv1.w, hi, lo); q1[33] = hi; q2[33] = lo;
            cur = nxt;
        }
    }
#pragma unroll
    for (int mf = 0; mf < 4; mf++)
#pragma unroll
        for (int nf = 0; nf < 4; nf++)
#pragma unroll
            for (int he = 0; he < 2; he++) {
                int row = m0 + 64 * wr + 16 * mf + g + 8 * he;
                int col = n0 + 32 * wc + 8 * nf + 2 * t4;
                float2 o;
                o.x = acc[mf][nf][2 * he + 0] + bias[col];
                o.y = acc[mf][nf][2 * he + 1] + bias[col + 1];
                *(float2*)&C[(size_t)row * N + col] = o;
            }
}

// ---------------- fused relative attention (fp16, P kept in registers) -------------
// score[s][t] = ( q_s.k_t + UK[t] + shifted(q.E^T)[s][r] + VE[r] ) / 8
// d = t-s: d<=0 -> pos[S-1+d] (row s); d==1 -> 0; d>=2 -> pos[d-2] (row s+1).
// QK C-fragment == PV A-fragment layout (m16n8k16), so P = exp(score) converts
// in-register (h2 packs); each warp contracts its own 32 t-cols and the two
// col-half warps combine acc once in the epilogue via smem (GS region reuse).
// Softmax: one sync — publish (rowmax, sumexp) per warp, merge with exp algebra.
#define QS_OFF   0        // 65*36
#define KS_OFF   2340     // 64*36
#define VS_OFF   4644     // 64*36
#define ES_OFF   6948     // 128*36
#define GS_OFF   11556    // G: 64*66 u32; epilogue combine buffer 64*65 f32 aliases
#define UK_OFF   15780    // 64 f32
#define VE_OFF   15844    // 128 f32
#define RMX_OFF  15972    // 128 f32
#define RSM_OFF  16100    // 128 f32
#define ATT_SMEM_U32 16228  // 64,912 B -> 3 blocks/SM

__global__ void __launch_bounds__(256, 3) attn_kernel(
    const float* __restrict__ Q, const float* __restrict__ Km,
    const float* __restrict__ Vm, const float* __restrict__ POS,
    const float* __restrict__ UK, const float* __restrict__ VE,
    float* __restrict__ OUT)
{
    extern __shared__ uint32_t su[];
    uint32_t* Qsu = su + QS_OFF;
    uint32_t* Ksu = su + KS_OFF;
    uint32_t* Vsu = su + VS_OFF;
    uint32_t* Esu = su + ES_OFF;
    uint32_t* Gsu = su + GS_OFF;
    __half*   Gh  = (__half*)(su + GS_OFF);
    float*    CB  = (float*)(su + GS_OFF);  // epilogue combine (G dead by then)
    float* UKs    = (float*)(su + UK_OFF);
    float* VEs    = (float*)(su + VE_OFF);
    float* redmax = (float*)(su + RMX_OFF);
    float* redsum = (float*)(su + RSM_OFF);

    const int tid  = threadIdx.x;
    const int lane = tid & 31;
    const int wid  = tid >> 5;
    const int wr   = wid >> 1;     // 0..3 : 16-row group
    const int wc   = wid & 1;      // 0..1 : 32-col half
    const int g    = lane >> 2;
    const int t4   = lane & 3;

    const int s0   = blockIdx.x * 64;
    const int h    = blockIdx.y;
    const int b    = blockIdx.z;
    const int hoff = h * HDIM;

    const uint32_t vbase = (uint32_t)__cvta_generic_to_shared(Vsu);

    if (tid < 32) Esu[127 * 36 + tid] = 0u;
    for (int q4 = tid; q4 < 65 * 16; q4 += 256) {
        int row = q4 >> 4;
        int p4  = (q4 & 15) * 4;
        int s   = s0 + row; if (s > S_LEN - 1) s = S_LEN - 1;
        float4 qv = *(const float4*)(Q + (size_t)(b * S_LEN + s) * EMBED + hoff + p4);
        Qsu[row * 36 + (p4 >> 1)]     = h2(qv.x, qv.y);
        Qsu[row * 36 + (p4 >> 1) + 1] = h2(qv.z, qv.w);
    }

    float acc[8][4];               // 16 rows x 64 head-dims (full width!)
    float m_r[2], l_r[2];
#pragma unroll
    for (int nf = 0; nf < 8; nf++)
#pragma unroll
        for (int e = 0; e < 4; e++) acc[nf][e] = 0.f;
    m_r[0] = m_r[1] = -1e30f;
    l_r[0] = l_r[1] = 0.f;

    for (int t0 = 0; t0 < S_LEN; t0 += 64) {
        const int diag = t0 - s0;
        __syncthreads();           // prev PV reads of VS complete

        for (int q4 = tid; q4 < 64 * 16; q4 += 256) {
            int row = q4 >> 4;
            int p4  = (q4 & 15) * 4;
            size_t go = (size_t)(b * S_LEN + t0 + row) * EMBED + hoff + p4;
            float4 kv = *(const float4*)(Km + go);
            float4 vv = *(const float4*)(Vm + go);
            Ksu[row * 36 + (p4 >> 1)]     = h2(kv.x, kv.y);
            Ksu[row * 36 + (p4 >> 1) + 1] = h2(kv.z, kv.w);
            Vsu[row * 36 + (p4 >> 1)]     = h2(vv.x, vv.y);
            Vsu[row * 36 + (p4 >> 1) + 1] = h2(vv.z, vv.w);
        }
        for (int q4 = tid; q4 < 127 * 16; q4 += 256) {
            int r  = q4 >> 4;
            int p4 = (q4 & 15) * 4;
            int d  = diag - 63 + r;
            int c  = (d <= 0) ? (S_LEN - 1 + d) : ((d == 1) ? -1 : (d - 2));
            float4 pv = make_float4(0.f, 0.f, 0.f, 0.f);
            if (c >= 0)
                pv = *(const float4*)(POS + (size_t)c * EMBED + hoff + p4);
            Esu[r * 36 + (p4 >> 1)]     = h2(pv.x, pv.y);
            Esu[r * 36 + (p4 >> 1) + 1] = h2(pv.z, pv.w);
        }
        if (tid < 64) UKs[tid] = UK[((b * NHEAD + h) << 11) + t0 + tid];
        if (tid < 128) {
            int r = tid;
            float val = 0.f;
            if (r < 127) {
                int d = diag - 63 + r;
                int c = (d <= 0) ? (S_LEN - 1 + d) : ((d == 1) ? -1 : (d - 2));
                if (c >= 0) val = VE[(h << 11) + c];
            }
            VEs[r] = val;
        }
        __syncthreads();

        // ---- content score MMA: sc = q @ K^T ----
        float sc[4][4];
#pragma unroll
        for (int nf = 0; nf < 4; nf++)
#pragma unroll
            for (int e = 0; e < 4; e++) sc[nf][e] = 0.f;
        {
            const uint32_t* Aq = Qsu + (16 * wr + g) * 36 + t4;
            const uint32_t* Bk = Ksu + (32 * wc + g) * 36 + t4;
#pragma unroll
            for (int kk = 0; kk < 4; kk++) {
                uint32_t a0 = Aq[8 * kk];
                uint32_t a1 = Aq[8 * 36 + 8 * kk];
                uint32_t a2 = Aq[8 * kk + 4];
                uint32_t a3 = Aq[8 * 36 + 8 * kk + 4];
#pragma unroll
                for (int nf = 0; nf < 4; nf++) {
                    uint32_t b0 = Bk[nf * 8 * 36 + 8 * kk];
                    uint32_t b1 = Bk[nf * 8 * 36 + 8 * kk + 4];
                    mma_f16(sc[nf], a0, a1, a2, a3, b0, b1);
                }
            }
        }

        // ---- positional: G = q(+pass) @ E^T, store fp16, diagonal gather ----
        const bool passA = (diag <= 0);
        const bool passB = (diag >= 0);
#pragma unroll 1
        for (int pass = 0; pass < 2; pass++) {
            if (pass == 0 && !passA) continue;
            if (pass == 1 && !passB) continue;
            if (pass == 1 && passA) __syncthreads();   // pass-0 gathers done

            const uint32_t* Aq = Qsu + (16 * wr + g + pass) * 36 + t4;
#pragma unroll 1
            for (int ch = 0; ch < 2; ch++) {
                float ga[4][4];
#pragma unroll
                for (int nf = 0; nf < 4; nf++)
#pragma unroll
                    for (int e = 0; e < 4; e++) ga[nf][e] = 0.f;
                const uint32_t* Be = Esu + (64 * wc + 32 * ch + g) * 36 + t4;
#pragma unroll
                for (int kk = 0; kk < 4; kk++) {
                    uint32_t a0 = Aq[8 * kk];
                    uint32_t a1 = Aq[8 * 36 + 8 * kk];
                    uint32_t a2 = Aq[8 * kk + 4];
                    uint32_t a3 = Aq[8 * 36 + 8 * kk + 4];
#pragma unroll
                    for (int nf = 0; nf < 4; nf++) {
                        uint32_t b0 = Be[nf * 8 * 36 + 8 * kk];
                        uint32_t b1 = Be[nf * 8 * 36 + 8 * kk + 4];
                        mma_f16(ga[nf], a0, a1, a2, a3, b0, b1);
                    }
                }
#pragma unroll
                for (int nf = 0; nf < 4; nf++)
#pragma unroll
                    for (int he = 0; he < 2; he++) {
                        int row = 16 * wr + g + 8 * he;
                        int h2c = 32 * wc + 16 * ch + 4 * nf + t4;
                        Gsu[row * 66 + h2c] = h2(ga[nf][2 * he], ga[nf][2 * he + 1]);
                    }
            }
            __syncthreads();       // G stores visible
#pragma unroll
            for (int nf = 0; nf < 4; nf++)
#pragma unroll
                for (int e = 0; e < 4; e++) {
                    int ss = 16 * wr + g + 8 * (e >> 1);
                    int tt = 2 * t4 + (e & 1) + 8 * nf + 32 * wc;
                    int d  = diag + tt - ss;
                    bool take = pass ? (d >= 2) : (d <= 0);
                    if (take) {
                        int r = tt - ss + 63;
                        sc[nf][e] += __half2float(Gh[ss * 132 + r]) + VEs[r];
                    }
                }
        }

        // ---- add UK, scale ----
#pragma unroll
        for (int nf = 0; nf < 4; nf++)
#pragma unroll
            for (int e = 0; e < 4; e++) {
                int tt = 2 * t4 + (e & 1) + 8 * nf + 32 * wc;
                sc[nf][e] = (sc[nf][e] + UKs[tt]) * 0.125f;
            }

        // ---- one-sync online softmax: publish (rowmax, sumexp) per warp ----
        float rmx[2] = {-1e30f, -1e30f};
#pragma unroll
        for (int nf = 0; nf < 4; nf++)
#pragma unroll
            for (int e = 0; e < 4; e++)
                rmx[e >> 1] = fmaxf(rmx[e >> 1], sc[nf][e]);
#pragma unroll
        for (int msk = 1; msk < 4; msk <<= 1) {
            rmx[0] = fmaxf(rmx[0], __shfl_xor_sync(0xffffffffu, rmx[0], msk));
            rmx[1] = fmaxf(rmx[1], __shfl_xor_sync(0xffffffffu, rmx[1], msk));
        }
        float rs[2] = {0.f, 0.f};
#pragma unroll
        for (int nf = 0; nf < 4; nf++)
#pragma unroll
            for (int e = 0; e < 4; e++) {
                float p = __expf(sc[nf][e] - rmx[e >> 1]);
                sc[nf][e] = p;
                rs[e >> 1] += p;
            }
#pragma unroll
        for (int msk = 1; msk < 4; msk <<= 1) {
            rs[0] += __shfl_xor_sync(0xffffffffu, rs[0], msk);
            rs[1] += __shfl_xor_sync(0xffffffffu, rs[1], msk);
        }
        if (t4 == 0) {
            redmax[(16 * wr + g) * 2 + wc]     = rmx[0];
            redmax[(16 * wr + g + 8) * 2 + wc] = rmx[1];
            redsum[(16 * wr + g) * 2 + wc]     = rs[0];
            redsum[(16 * wr + g + 8) * 2 + wc] = rs[1];
        }
        __syncthreads();

        float corr[2], pscale[2];
#pragma unroll
        for (int hh = 0; hh < 2; hh++) {
            int row = 16 * wr + g + 8 * hh;
            float M0 = redmax[row * 2 + 0], S0 = redsum[row * 2 + 0];
            float M1 = redmax[row * 2 + 1], S1 = redsum[row * 2 + 1];
            float M  = fmaxf(m_r[hh], fmaxf(M0, M1));
            float cA = __expf(m_r[hh] - M);
            l_r[hh]  = l_r[hh] * cA + S0 * __expf(M0 - M) + S1 * __expf(M1 - M);
            corr[hh]   = cA;
            pscale[hh] = __expf(rmx[hh] - M);
            m_r[hh]    = M;
        }
#pragma unroll
        for (int nf = 0; nf < 8; nf++)
#pragma unroll
            for (int e = 0; e < 4; e++) acc[nf][e] *= corr[e >> 1];

        // ---- P -> A-fragments in-register; PV over own 32 t-cols, full 64 dims ----
        uint32_t pa[2][4];
#pragma unroll
        for (int kk = 0; kk < 2; kk++) {
            pa[kk][0] = h2(sc[2*kk][0]   * pscale[0], sc[2*kk][1]   * pscale[0]);
            pa[kk][1] = h2(sc[2*kk][2]   * pscale[1], sc[2*kk][3]   * pscale[1]);
            pa[kk][2] = h2(sc[2*kk+1][0] * pscale[0], sc[2*kk+1][1] * pscale[0]);
            pa[kk][3] = h2(sc[2*kk+1][2] * pscale[1], sc[2*kk+1][3] * pscale[1]);
        }
#pragma unroll
        for (int kk = 0; kk < 2; kk++) {
            uint32_t rowaddr = vbase + (uint32_t)(((32 * wc + 16 * kk + (lane & 15)) * 36) * 4);
#pragma unroll
            for (int nf = 0; nf < 8; nf++) {
                uint32_t b0, b1;
                asm volatile(
                    "ldmatrix.sync.aligned.m8n8.x2.trans.shared.b16 {%0,%1}, [%2];"
                    : "=r"(b0), "=r"(b1) : "r"(rowaddr + nf * 16));
                mma_f16(acc[nf], pa[kk][0], pa[kk][1], pa[kk][2], pa[kk][3], b0, b1);
            }
        }
    }

    // ---- epilogue: combine col-half warps via smem, normalize, store ----
    float inv[2] = {1.f / l_r[0], 1.f / l_r[1]};
    if (wc == 0) {
#pragma unroll
        for (int nf = 0; nf < 8; nf++)
#pragma unroll
            for (int e = 0; e < 4; e++) {
                int row = 16 * wr + g + 8 * (e >> 1);
                int col = 2 * t4 + (e & 1) + 8 * nf;
                CB[row * 65 + col] = acc[nf][e];
            }
    }
    __syncthreads();
    if (wc == 1) {
#pragma unroll
        for (int nf = 0; nf < 8; nf++)
#pragma unroll
            for (int he = 0; he < 2; he++) {
                int row = 16 * wr + g + 8 * he;
                int col = 2 * t4 + 8 * nf;
                float2 o;
                o.x = (acc[nf][2 * he + 0] + CB[row * 65 + col])     * inv[he];
                o.y = (acc[nf][2 * he + 1] + CB[row * 65 + col + 1]) * inv[he];
                *(float2*)&OUT[(size_t)(b * S_LEN + s0 + row) * EMBED + hoff + col] = o;
            }
    }
}

// ---------------- launch ----------------
extern "C" void kernel_launch(void* const* d_in, const int* in_sizes, int n_in,
                              void* d_out, int out_size)
{
    const float* x   = (const float*)d_in[0];
    const float* Wq  = (const float*)d_in[1];
    const float* bq  = (const float*)d_in[2];
    const float* Wk  = (const float*)d_in[3];
    const float* bk  = (const float*)d_in[4];
    const float* Wv  = (const float*)d_in[5];
    const float* bv_ = (const float*)d_in[6];
    const float* Wp  = (const float*)d_in[7];
    const float* bp  = (const float*)d_in[8];
    const float* Wo  = (const float*)d_in[9];
    const float* bo  = (const float*)d_in[10];
    const float* u   = (const float*)d_in[11];
    const float* v   = (const float*)d_in[12];
    float* out = (float*)d_out;

    float *psin, *ppos, *pq, *pk, *pv, *pattn, *puk, *pve;
    cudaGetSymbolAddress((void**)&psin,  g_sin);
    cudaGetSymbolAddress((void**)&ppos,  g_pos);
    cudaGetSymbolAddress((void**)&pq,    g_q);
    cudaGetSymbolAddress((void**)&pk,    g_k);
    cudaGetSymbolAddress((void**)&pv,    g_v);
    cudaGetSymbolAddress((void**)&pattn, g_attn);
    cudaGetSymbolAddress((void**)&puk,   g_uk);
    cudaGetSymbolAddress((void**)&pve,   g_ve);

    cudaFuncSetAttribute(attn_kernel, cudaFuncAttributeMaxDynamicSharedMemorySize,
                         ATT_SMEM_U32 * 4);

    invf_kernel<<<2, 256>>>();
    sinusoid_kernel<<<(S_LEN * (EMBED / 2) + 255) / 256, 256>>>();

    dim3 gBig(EMBED / 128, (BATCH * S_LEN) / 128);         // (8, 32)
    dim3 gQKVP(EMBED / 128, (BATCH * S_LEN) / 128, 4);     // (8, 32, 4)

    gemm_tf32_qkvp_kernel<<<gQKVP, 256>>>(x, psin,
                                          Wq, bq, Wk, bk, Wv, bv_, Wp, bp,
                                          pq, pk, pv, ppos, EMBED, EMBED);

    int nwarp = BATCH * NHEAD * S_LEN + NHEAD * S_LEN;
    ukve_kernel<<<(nwarp * 32 + 255) / 256, 256>>>(pk, ppos, u, v);

    dim3 gAtt(S_LEN / 64, NHEAD, BATCH);                   // (32, 16, 2)
    attn_kernel<<<gAtt, 256, ATT_SMEM_U32 * 4>>>(pq, pk, pv, ppos, puk, pve, pattn);

    gemm_f16x3_kernel<<<gBig, 256>>>(pattn, Wo, bo, out, BATCH * S_LEN, EMBED, EMBED);
}

// round 14
// speedup vs baseline: 4.7811x; 1.0473x over previous
#include <cuda_runtime.h>
#include <cuda_fp16.h>
#include <math.h>
#include <stdint.h>

#define S_LEN 2048
#define BATCH 2
#define EMBED 1024
#define NHEAD 16
#define HDIM  64

// ---------------- scratch (static device globals; no allocation) ----------------
__device__ float  g_sin[S_LEN * EMBED];
__device__ float  g_pos[S_LEN * EMBED];            // fp32 (ukve needs exact dots)
__device__ float  g_k[BATCH * S_LEN * EMBED];      // fp32 (ukve)
__device__ float  g_attn[BATCH * S_LEN * EMBED];
__device__ __half g_qh[BATCH * S_LEN * EMBED];     // fp16 staged for attn
__device__ __half g_kh[BATCH * S_LEN * EMBED];
__device__ __half g_vh[BATCH * S_LEN * EMBED];
__device__ __half g_posh[S_LEN * EMBED];
__device__ float  g_uk[BATCH * NHEAD * S_LEN];     // u . k_t   per (b,h,t)
__device__ float  g_ve[NHEAD * S_LEN];             // v . pos_c per (h,c)
__device__ float  g_invf[EMBED / 2];

// ---------------- sinusoid position embedding (fp32 fast path) ----------------
__global__ void invf_kernel() {
    int i = blockIdx.x * blockDim.x + threadIdx.x;
    if (i >= EMBED / 2) return;
    double invf = exp(-(2.0 * (double)i / (double)EMBED) * log(10000.0));
    g_invf[i] = (float)invf;
}

__global__ void sinusoid_kernel() {
    int idx = blockIdx.x * blockDim.x + threadIdx.x;
    if (idx >= S_LEN * (EMBED / 2)) return;
    int s = idx / (EMBED / 2);
    int i = idx % (EMBED / 2);
    float ang = (float)s * g_invf[i];
    float sv, cv;
    sincosf(ang, &sv, &cv);
    g_sin[s * EMBED + i]             = sv;
    g_sin[s * EMBED + (EMBED/2) + i] = cv;
}

// ---------------- UK/VE precompute: one warp per dot-64 (fp32 exact) ----------------
__global__ void ukve_kernel(const float* __restrict__ K, const float* __restrict__ POS,
                            const float* __restrict__ u, const float* __restrict__ v)
{
    int w    = (blockIdx.x * blockDim.x + threadIdx.x) >> 5;
    int lane = threadIdx.x & 31;
    const int UKW = BATCH * NHEAD * S_LEN;
    if (w < UKW) {
        int t = w & (S_LEN - 1);
        int h = (w >> 11) & (NHEAD - 1);
        int b = w >> 15;
        const float* kp = K + ((size_t)(b * S_LEN + t)) * EMBED + h * HDIM;
        const float* up = u + h * HDIM;
        float s = kp[lane] * up[lane] + kp[lane + 32] * up[lane + 32];
#pragma unroll
        for (int m = 16; m; m >>= 1) s += __shfl_xor_sync(~0u, s, m);
        if (!lane) g_uk[w] = s;
    } else if (w < UKW + NHEAD * S_LEN) {
        int w2 = w - UKW;
        int c = w2 & (S_LEN - 1);
        int h = w2 >> 11;
        const float* pp = POS + (size_t)c * EMBED + h * HDIM;
        const float* vp = v + h * HDIM;
        float s = pp[lane] * vp[lane] + pp[lane + 32] * vp[lane + 32];
#pragma unroll
        for (int m = 16; m; m >>= 1) s += __shfl_xor_sync(~0u, s, m);
        if (!lane) g_ve[w2] = s;
    }
}

// ---------------- helpers ----------------
__device__ __forceinline__ float tf32f(float f) {
    uint32_t u;
    asm("cvt.rna.tf32.f32 %0, %1;" : "=r"(u) : "f"(f));
    return __uint_as_float(u);
}
__device__ __forceinline__ uint32_t fb(float f) { return __float_as_uint(f); }
__device__ __forceinline__ uint32_t h2(float x, float y) {
    __half2 h = __floats2half2_rn(x, y);
    return *(uint32_t*)&h;
}
__device__ __forceinline__ void split2(float x, float y, uint32_t& hi, uint32_t& lo) {
    __half hx = __float2half_rn(x), hy = __float2half_rn(y);
    float rx = x - __half2float(hx), ry = y - __half2float(hy);
    __half2 hh; hh.x = hx; hh.y = hy;
    hi = *(uint32_t*)&hh;
    lo = h2(rx, ry);
}
__device__ __forceinline__ void mma_tf32(float* d,
    uint32_t a0, uint32_t a1, uint32_t a2, uint32_t a3, uint32_t b0, uint32_t b1)
{
    asm volatile(
        "mma.sync.aligned.m16n8k8.row.col.f32.tf32.tf32.f32 "
        "{%0,%1,%2,%3}, {%4,%5,%6,%7}, {%8,%9}, {%0,%1,%2,%3};"
        : "+f"(d[0]), "+f"(d[1]), "+f"(d[2]), "+f"(d[3])
        : "r"(a0), "r"(a1), "r"(a2), "r"(a3), "r"(b0), "r"(b1));
}
__device__ __forceinline__ void mma_f16(float* d,
    uint32_t a0, uint32_t a1, uint32_t a2, uint32_t a3, uint32_t b0, uint32_t b1)
{
    asm volatile(
        "mma.sync.aligned.m16n8k16.row.col.f32.f16.f16.f32 "
        "{%0,%1,%2,%3}, {%4,%5,%6,%7}, {%8,%9}, {%0,%1,%2,%3};"
        : "+f"(d[0]), "+f"(d[1]), "+f"(d[2]), "+f"(d[3])
        : "r"(a0), "r"(a1), "r"(a2), "r"(a3), "r"(b0), "r"(b1));
}

// ---------------- tf32 tensor-core GEMM + bias (2-stage, dual fp32/fp16 output) ----
__device__ __forceinline__ void gemm_tf32_body(
    const float* __restrict__ A, const float* __restrict__ B,
    const float* __restrict__ bias, float* __restrict__ C32,
    __half* __restrict__ C16, int N, int K)
{
    __shared__ float As[2][128 * 20];
    __shared__ float Bs[2][16 * 136];
    const int tid  = threadIdx.x;
    const int lane = tid & 31;
    const int wid  = tid >> 5;
    const int wr   = wid >> 2;
    const int wc   = wid & 3;
    const int g    = lane >> 2;
    const int t4   = lane & 3;
    const int m0   = blockIdx.y * 128;
    const int n0   = blockIdx.x * 128;

    float acc[4][4][4];
#pragma unroll
    for (int mf = 0; mf < 4; mf++)
#pragma unroll
        for (int nf = 0; nf < 4; nf++)
#pragma unroll
            for (int e = 0; e < 4; e++) acc[mf][nf][e] = 0.f;

    const int a_row = tid >> 2;
    const int a_k4  = (tid & 3) * 4;
    const int b_k   = tid >> 4;
    const int b_n4  = (tid & 15) * 4;

    const float* Ap = A + (size_t)(m0 + a_row) * K + a_k4;
    const float* Bp = B + (size_t)b_k * N + n0 + b_n4;

    {
        float4 av0 = *(const float4*)(Ap);
        float4 av1 = *(const float4*)(Ap + (size_t)64 * K);
        float4 bv0 = *(const float4*)(Bp);
        float4 bv1 = *(const float4*)(Bp + 64);
        float* as0 = As[0] + a_row * 20 + a_k4;
        as0[0] = tf32f(av0.x); as0[1] = tf32f(av0.y);
        as0[2] = tf32f(av0.z); as0[3] = tf32f(av0.w);
        float* as1 = As[0] + (a_row + 64) * 20 + a_k4;
        as1[0] = tf32f(av1.x); as1[1] = tf32f(av1.y);
        as1[2] = tf32f(av1.z); as1[3] = tf32f(av1.w);
        float* bs0 = Bs[0] + b_k * 136 + b_n4;
        bs0[0] = tf32f(bv0.x); bs0[1] = tf32f(bv0.y);
        bs0[2] = tf32f(bv0.z); bs0[3] = tf32f(bv0.w);
        float* bs1 = bs0 + 64;
        bs1[0] = tf32f(bv1.x); bs1[1] = tf32f(bv1.y);
        bs1[2] = tf32f(bv1.z); bs1[3] = tf32f(bv1.w);
    }
    int cur = 0;

    for (int k0 = 0; k0 < K; k0 += 16) {
        __syncthreads();
        const bool more = (k0 + 16 < K);
        float4 av0, av1, bv0, bv1;
        if (more) {
            int kn = k0 + 16;
            av0 = *(const float4*)(Ap + kn);
            av1 = *(const float4*)(Ap + (size_t)64 * K + kn);
            bv0 = *(const float4*)(Bp + (size_t)kn * N);
            bv1 = *(const float4*)(Bp + (size_t)kn * N + 64);
        }

        const float* Acur = As[cur];
        const float* Bcur = Bs[cur];
#pragma unroll
        for (int kk = 0; kk < 2; kk++) {
            uint32_t af[4][4];
#pragma unroll
            for (int mf = 0; mf < 4; mf++) {
                const float* pa = Acur + (64 * wr + 16 * mf + g) * 20 + 8 * kk + t4;
                af[mf][0] = fb(pa[0]);
                af[mf][1] = fb(pa[8 * 20]);
                af[mf][2] = fb(pa[4]);
                af[mf][3] = fb(pa[8 * 20 + 4]);
            }
#pragma unroll
            for (int nf = 0; nf < 4; nf++) {
                const float* pb = Bcur + (8 * kk + t4) * 136 + 32 * wc + 8 * nf + g;
                uint32_t b0 = fb(pb[0]);
                uint32_t b1 = fb(pb[4 * 136]);
#pragma unroll
                for (int mf = 0; mf < 4; mf++)
                    mma_tf32(acc[mf][nf], af[mf][0], af[mf][1], af[mf][2], af[mf][3], b0, b1);
            }
        }

        if (more) {
            int nxt = cur ^ 1;
            float* as0 = As[nxt] + a_row * 20 + a_k4;
            as0[0] = tf32f(av0.x); as0[1] = tf32f(av0.y);
            as0[2] = tf32f(av0.z); as0[3] = tf32f(av0.w);
            float* as1 = As[nxt] + (a_row + 64) * 20 + a_k4;
            as1[0] = tf32f(av1.x); as1[1] = tf32f(av1.y);
            as1[2] = tf32f(av1.z); as1[3] = tf32f(av1.w);
            float* bs0 = Bs[nxt] + b_k * 136 + b_n4;
            bs0[0] = tf32f(bv0.x); bs0[1] = tf32f(bv0.y);
            bs0[2] = tf32f(bv0.z); bs0[3] = tf32f(bv0.w);
            float* bs1 = bs0 + 64;
            bs1[0] = tf32f(bv1.x); bs1[1] = tf32f(bv1.y);
            bs1[2] = tf32f(bv1.z); bs1[3] = tf32f(bv1.w);
            cur = nxt;
        }
    }
#pragma unroll
    for (int mf = 0; mf < 4; mf++)
#pragma unroll
        for (int nf = 0; nf < 4; nf++)
#pragma unroll
            for (int h2i = 0; h2i < 2; h2i++) {
                int row = m0 + 64 * wr + 16 * mf + g + 8 * h2i;
                int col = n0 + 32 * wc + 8 * nf + 2 * t4;
                float ox = acc[mf][nf][2 * h2i + 0] + bias[col];
                float oy = acc[mf][nf][2 * h2i + 1] + bias[col + 1];
                if (C32) {
                    float2 o; o.x = ox; o.y = oy;
                    *(float2*)&C32[(size_t)row * N + col] = o;
                }
                if (C16) {
                    __half2 oh = __floats2half2_rn(ox, oy);
                    *(__half2*)&C16[(size_t)row * N + col] = oh;
                }
            }
}

// Q/K/V/pos fused into ONE launch via blockIdx.z (z=3 is the pos proj, y<16)
__global__ void __launch_bounds__(256, 2) gemm_tf32_qkvp_kernel(
    const float* __restrict__ x, const float* __restrict__ sinu,
    const float* __restrict__ W0, const float* __restrict__ c0,
    const float* __restrict__ W1, const float* __restrict__ c1,
    const float* __restrict__ W2, const float* __restrict__ c2,
    const float* __restrict__ W3, const float* __restrict__ c3,
    __half* __restrict__ Qh, float* __restrict__ Kf, __half* __restrict__ Kh,
    __half* __restrict__ Vh, float* __restrict__ Pf, __half* __restrict__ Ph,
    int N, int K)
{
    const float* A; const float* B; const float* bias;
    float* C32; __half* C16;
    if (blockIdx.z == 0)      { A = x;    B = W0; bias = c0; C32 = 0;  C16 = Qh; }
    else if (blockIdx.z == 1) { A = x;    B = W1; bias = c1; C32 = Kf; C16 = Kh; }
    else if (blockIdx.z == 2) { A = x;    B = W2; bias = c2; C32 = 0;  C16 = Vh; }
    else {
        if (blockIdx.y >= 16) return;
        A = sinu; B = W3; bias = c3; C32 = Pf; C16 = Ph;
    }
    gemm_tf32_body(A, B, bias, C32, C16, N, K);
}

// ---------------- fp16-split tensor-core GEMM + bias (out-proj; 2-stage) ----------
#define OP_AST 12
#define OP_WST 68
__global__ void __launch_bounds__(256, 2) gemm_f16x3_kernel(
    const float* __restrict__ A, const float* __restrict__ W,
    const float* __restrict__ bias, float* __restrict__ C,
    int M, int N, int K)
{
    __shared__ uint32_t A1[2][128 * OP_AST];
    __shared__ uint32_t A2[2][128 * OP_AST];
    __shared__ uint32_t W1[2][16 * OP_WST];
    __shared__ uint32_t W2[2][16 * OP_WST];
    const int tid  = threadIdx.x;
    const int lane = tid & 31;
    const int wid  = tid >> 5;
    const int wr   = wid >> 2;
    const int wc   = wid & 3;
    const int g    = lane >> 2;
    const int t4   = lane & 3;
    const int m0   = blockIdx.y * 128;
    const int n0   = blockIdx.x * 128;

    uint32_t w1b[2], w2b[2];
    w1b[0] = (uint32_t)__cvta_generic_to_shared(W1[0]);
    w1b[1] = (uint32_t)__cvta_generic_to_shared(W1[1]);
    w2b[0] = (uint32_t)__cvta_generic_to_shared(W2[0]);
    w2b[1] = (uint32_t)__cvta_generic_to_shared(W2[1]);

    float acc[4][4][4];
#pragma unroll
    for (int mf = 0; mf < 4; mf++)
#pragma unroll
        for (int nf = 0; nf < 4; nf++)
#pragma unroll
            for (int e = 0; e < 4; e++) acc[mf][nf][e] = 0.f;

    const int a_row = tid >> 2;
    const int a_k4  = (tid & 3) * 4;
    const int b_k   = tid >> 4;
    const int b_n4  = (tid & 15) * 4;

    const float* Ap = A + (size_t)(m0 + a_row) * K + a_k4;
    const float* Wp = W + (size_t)b_k * N + n0 + b_n4;

    {
        float4 av0 = *(const float4*)(Ap);
        float4 av1 = *(const float4*)(Ap + (size_t)64 * K);
        float4 wv0 = *(const float4*)(Wp);
        float4 wv1 = *(const float4*)(Wp + 64);
        uint32_t hi, lo;
        uint32_t* p1 = A1[0] + a_row * OP_AST + (a_k4 >> 1);
        uint32_t* p2 = A2[0] + a_row * OP_AST + (a_k4 >> 1);
        split2(av0.x, av0.y, hi, lo); p1[0] = hi; p2[0] = lo;
        split2(av0.z, av0.w, hi, lo); p1[1] = hi; p2[1] = lo;
        p1 = A1[0] + (a_row + 64) * OP_AST + (a_k4 >> 1);
        p2 = A2[0] + (a_row + 64) * OP_AST + (a_k4 >> 1);
        split2(av1.x, av1.y, hi, lo); p1[0] = hi; p2[0] = lo;
        split2(av1.z, av1.w, hi, lo); p1[1] = hi; p2[1] = lo;
        uint32_t* q1 = W1[0] + b_k * OP_WST + (b_n4 >> 1);
        uint32_t* q2 = W2[0] + b_k * OP_WST + (b_n4 >> 1);
        split2(wv0.x, wv0.y, hi, lo); q1[0] = hi; q2[0] = lo;
        split2(wv0.z, wv0.w, hi, lo); q1[1] = hi; q2[1] = lo;
        split2(wv1.x, wv1.y, hi, lo); q1[32] = hi; q2[32] = lo;
        split2(wv1.z, wv1.w, hi, lo); q1[33] = hi; q2[33] = lo;
    }
    int cur = 0;

    for (int k0 = 0; k0 < K; k0 += 16) {
        __syncthreads();
        const bool more = (k0 + 16 < K);
        float4 av0, av1, wv0, wv1;
        if (more) {
            int kn = k0 + 16;
            av0 = *(const float4*)(Ap + kn);
            av1 = *(const float4*)(Ap + (size_t)64 * K + kn);
            wv0 = *(const float4*)(Wp + (size_t)kn * N);
            wv1 = *(const float4*)(Wp + (size_t)kn * N + 64);
        }

        uint32_t af1[4][4], af2[4][4];
#pragma unroll
        for (int mf = 0; mf < 4; mf++) {
            const uint32_t* pa1 = A1[cur] + (64 * wr + 16 * mf + g) * OP_AST + t4;
            const uint32_t* pa2 = A2[cur] + (64 * wr + 16 * mf + g) * OP_AST + t4;
            af1[mf][0] = pa1[0];  af1[mf][1] = pa1[8 * OP_AST];
            af1[mf][2] = pa1[4];  af1[mf][3] = pa1[8 * OP_AST + 4];
            af2[mf][0] = pa2[0];  af2[mf][1] = pa2[8 * OP_AST];
            af2[mf][2] = pa2[4];  af2[mf][3] = pa2[8 * OP_AST + 4];
        }
#pragma unroll
        for (int nf = 0; nf < 4; nf++) {
            uint32_t off = (((lane & 15) * OP_WST) + 16 * wc + 4 * nf) * 4;
            uint32_t b10, b11, b20, b21;
            asm volatile("ldmatrix.sync.aligned.m8n8.x2.trans.shared.b16 {%0,%1}, [%2];"
                         : "=r"(b10), "=r"(b11) : "r"(w1b[cur] + off));
            asm volatile("ldmatrix.sync.aligned.m8n8.x2.trans.shared.b16 {%0,%1}, [%2];"
                         : "=r"(b20), "=r"(b21) : "r"(w2b[cur] + off));
#pragma unroll
            for (int mf = 0; mf < 4; mf++) {
                mma_f16(acc[mf][nf], af1[mf][0], af1[mf][1], af1[mf][2], af1[mf][3], b10, b11);
                mma_f16(acc[mf][nf], af1[mf][0], af1[mf][1], af1[mf][2], af1[mf][3], b20, b21);
                mma_f16(acc[mf][nf], af2[mf][0], af2[mf][1], af2[mf][2], af2[mf][3], b10, b11);
            }
        }

        if (more) {
            int nxt = cur ^ 1;
            uint32_t hi, lo;
            uint32_t* p1 = A1[nxt] + a_row * OP_AST + (a_k4 >> 1);
            uint32_t* p2 = A2[nxt] + a_row * OP_AST + (a_k4 >> 1);
            split2(av0.x, av0.y, hi, lo); p1[0] = hi; p2[0] = lo;
            split2(av0.z, av0.w, hi, lo); p1[1] = hi; p2[1] = lo;
            p1 = A1[nxt] + (a_row + 64) * OP_AST + (a_k4 >> 1);
            p2 = A2[nxt] + (a_row + 64) * OP_AST + (a_k4 >> 1);
            split2(av1.x, av1.y, hi, lo); p1[0] = hi; p2[0] = lo;
            split2(av1.z, av1.w, hi, lo); p1[1] = hi; p2[1] = lo;
            uint32_t* q1 = W1[nxt] + b_k * OP_WST + (b_n4 >> 1);
            uint32_t* q2 = W2[nxt] + b_k * OP_WST + (b_n4 >> 1);
            split2(wv0.x, wv0.y, hi, lo); q1[0] = hi; q2[0] = lo;
            split2(wv0.z, wv0.w, hi, lo); q1[1] = hi; q2[1] = lo;
            split2(wv1.x, wv1.y, hi, lo); q1[32] = hi; q2[32] = lo;
            split2(wv1.z, wv1.w, hi, lo); q1[33] = hi; q2[33] = lo;
            cur = nxt;
        }
    }
#pragma unroll
    for (int mf = 0; mf < 4; mf++)
#pragma unroll
        for (int nf = 0; nf < 4; nf++)
#pragma unroll
            for (int he = 0; he < 2; he++) {
                int row = m0 + 64 * wr + 16 * mf + g + 8 * he;
                int col = n0 + 32 * wc + 8 * nf + 2 * t4;
                float2 o;
                o.x = acc[mf][nf][2 * he + 0] + bias[col];
                o.y = acc[mf][nf][2 * he + 1] + bias[col + 1];
                *(float2*)&C[(size_t)row * N + col] = o;
            }
}

// ---------------- fused relative attention (fp16 staged; pure-copy smem fill) ------
// score[s][t] = ( q_s.k_t + UK[t] + shifted(q.E^T)[s][r] + VE[r] ) / 8
// d = t-s: d<=0 -> pos[S-1+d] (row s); d==1 -> 0; d>=2 -> pos[d-2] (row s+1).
#define QS_OFF   0        // 65*36
#define KS_OFF   2340     // 64*36
#define VS_OFF   4644     // 64*36
#define ES_OFF   6948     // 128*36
#define GS_OFF   11556    // G: 64*66 u32; epilogue combine buffer 64*65 f32 aliases
#define UK_OFF   15780    // 64 f32
#define VE_OFF   15844    // 128 f32
#define RMX_OFF  15972    // 128 f32
#define RSM_OFF  16100    // 128 f32
#define ATT_SMEM_U32 16228  // 64,912 B -> 3 blocks/SM

__global__ void __launch_bounds__(256, 3) attn_kernel(
    const __half* __restrict__ Qh, const __half* __restrict__ Kh,
    const __half* __restrict__ Vh, const __half* __restrict__ POSh,
    const float* __restrict__ UK, const float* __restrict__ VE,
    float* __restrict__ OUT)
{
    extern __shared__ uint32_t su[];
    uint32_t* Qsu = su + QS_OFF;
    uint32_t* Ksu = su + KS_OFF;
    uint32_t* Vsu = su + VS_OFF;
    uint32_t* Esu = su + ES_OFF;
    uint32_t* Gsu = su + GS_OFF;
    __half*   Gh  = (__half*)(su + GS_OFF);
    float*    CB  = (float*)(su + GS_OFF);  // epilogue combine (G dead by then)
    float* UKs    = (float*)(su + UK_OFF);
    float* VEs    = (float*)(su + VE_OFF);
    float* redmax = (float*)(su + RMX_OFF);
    float* redsum = (float*)(su + RSM_OFF);

    const int tid  = threadIdx.x;
    const int lane = tid & 31;
    const int wid  = tid >> 5;
    const int wr   = wid >> 1;     // 0..3 : 16-row group
    const int wc   = wid & 1;      // 0..1 : 32-col half
    const int g    = lane >> 2;
    const int t4   = lane & 3;

    const int s0   = blockIdx.x * 64;
    const int h    = blockIdx.y;
    const int b    = blockIdx.z;
    const int hoff = h * HDIM;

    const uint32_t vbase = (uint32_t)__cvta_generic_to_shared(Vsu);

    if (tid < 32) Esu[127 * 36 + tid] = 0u;
    // Q prologue: pure uint4 copy (8 halves each), 65 rows x 8 chunks
    for (int it = tid; it < 65 * 8; it += 256) {
        int row = it >> 3;
        int p8  = (it & 7) * 8;
        int s   = s0 + row; if (s > S_LEN - 1) s = S_LEN - 1;
        uint4 qv = *(const uint4*)(Qh + (size_t)(b * S_LEN + s) * EMBED + hoff + p8);
        *(uint4*)(Qsu + row * 36 + (p8 >> 1)) = qv;
    }

    float acc[8][4];               // 16 rows x 64 head-dims
    float m_r[2], l_r[2];
#pragma unroll
    for (int nf = 0; nf < 8; nf++)
#pragma unroll
        for (int e = 0; e < 4; e++) acc[nf][e] = 0.f;
    m_r[0] = m_r[1] = -1e30f;
    l_r[0] = l_r[1] = 0.f;

    for (int t0 = 0; t0 < S_LEN; t0 += 64) {
        const int diag = t0 - s0;
        __syncthreads();           // prev PV reads of VS complete

        // K + V fill: pure uint4 copies
        for (int it = tid; it < 64 * 8; it += 256) {
            int row = it >> 3;
            int p8  = (it & 7) * 8;
            size_t go = (size_t)(b * S_LEN + t0 + row) * EMBED + hoff + p8;
            uint4 kv = *(const uint4*)(Kh + go);
            uint4 vv = *(const uint4*)(Vh + go);
            *(uint4*)(Ksu + row * 36 + (p8 >> 1)) = kv;
            *(uint4*)(Vsu + row * 36 + (p8 >> 1)) = vv;
        }
        // E band fill: uint4 copy from fp16 POS (zero where c < 0)
        for (int it = tid; it < 127 * 8; it += 256) {
            int r  = it >> 3;
            int p8 = (it & 7) * 8;
            int d  = diag - 63 + r;
            int c  = (d <= 0) ? (S_LEN - 1 + d) : ((d == 1) ? -1 : (d - 2));
            uint4 pv = make_uint4(0u, 0u, 0u, 0u);
            if (c >= 0)
                pv = *(const uint4*)(POSh + (size_t)c * EMBED + hoff + p8);
            *(uint4*)(Esu + r * 36 + (p8 >> 1)) = pv;
        }
        if (tid < 64) UKs[tid] = UK[((b * NHEAD + h) << 11) + t0 + tid];
        if (tid < 128) {
            int r = tid;
            float val = 0.f;
            if (r < 127) {
                int d = diag - 63 + r;
                int c = (d <= 0) ? (S_LEN - 1 + d) : ((d == 1) ? -1 : (d - 2));
                if (c >= 0) val = VE[(h << 11) + c];
            }
            VEs[r] = val;
        }
        __syncthreads();

        // ---- content score MMA: sc = q @ K^T ----
        float sc[4][4];
#pragma unroll
        for (int nf = 0; nf < 4; nf++)
#pragma unroll
            for (int e = 0; e < 4; e++) sc[nf][e] = 0.f;
        {
            const uint32_t* Aq = Qsu + (16 * wr + g) * 36 + t4;
            const uint32_t* Bk = Ksu + (32 * wc + g) * 36 + t4;
#pragma unroll
            for (int kk = 0; kk < 4; kk++) {
                uint32_t a0 = Aq[8 * kk];
                uint32_t a1 = Aq[8 * 36 + 8 * kk];
                uint32_t a2 = Aq[8 * kk + 4];
                uint32_t a3 = Aq[8 * 36 + 8 * kk + 4];
#pragma unroll
                for (int nf = 0; nf < 4; nf++) {
                    uint32_t b0 = Bk[nf * 8 * 36 + 8 * kk];
                    uint32_t b1 = Bk[nf * 8 * 36 + 8 * kk + 4];
                    mma_f16(sc[nf], a0, a1, a2, a3, b0, b1);
                }
            }
        }

        // ---- positional: G = q(+pass) @ E^T, store fp16, diagonal gather ----
        const bool passA = (diag <= 0);
        const bool passB = (diag >= 0);
#pragma unroll 1
        for (int pass = 0; pass < 2; pass++) {
            if (pass == 0 && !passA) continue;
            if (pass == 1 && !passB) continue;
            if (pass == 1 && passA) __syncthreads();   // pass-0 gathers done

            const uint32_t* Aq = Qsu + (16 * wr + g + pass) * 36 + t4;
#pragma unroll 1
            for (int ch = 0; ch < 2; ch++) {
                float ga[4][4];
#pragma unroll
                for (int nf = 0; nf < 4; nf++)
#pragma unroll
                    for (int e = 0; e < 4; e++) ga[nf][e] = 0.f;
                const uint32_t* Be = Esu + (64 * wc + 32 * ch + g) * 36 + t4;
#pragma unroll
                for (int kk = 0; kk < 4; kk++) {
                    uint32_t a0 = Aq[8 * kk];
                    uint32_t a1 = Aq[8 * 36 + 8 * kk];
                    uint32_t a2 = Aq[8 * kk + 4];
                    uint32_t a3 = Aq[8 * 36 + 8 * kk + 4];
#pragma unroll
                    for (int nf = 0; nf < 4; nf++) {
                        uint32_t b0 = Be[nf * 8 * 36 + 8 * kk];
                        uint32_t b1 = Be[nf * 8 * 36 + 8 * kk + 4];
                        mma_f16(ga[nf], a0, a1, a2, a3, b0, b1);
                    }
                }
#pragma unroll
                for (int nf = 0; nf < 4; nf++)
#pragma unroll
                    for (int he = 0; he < 2; he++) {
                        int row = 16 * wr + g + 8 * he;
                        int h2c = 32 * wc + 16 * ch + 4 * nf + t4;
                        Gsu[row * 66 + h2c] = h2(ga[nf][2 * he], ga[nf][2 * he + 1]);
                    }
            }
            __syncthreads();       // G stores visible
#pragma unroll
            for (int nf = 0; nf < 4; nf++)
#pragma unroll
                for (int e = 0; e < 4; e++) {
                    int ss = 16 * wr + g + 8 * (e >> 1);
                    int tt = 2 * t4 + (e & 1) + 8 * nf + 32 * wc;
                    int d  = diag + tt - ss;
                    bool take = pass ? (d >= 2) : (d <= 0);
                    if (take) {
                        int r = tt - ss + 63;
                        sc[nf][e] += __half2float(Gh[ss * 132 + r]) + VEs[r];
                    }
                }
        }

        // ---- add UK, scale ----
#pragma unroll
        for (int nf = 0; nf < 4; nf++)
#pragma unroll
            for (int e = 0; e < 4; e++) {
                int tt = 2 * t4 + (e & 1) + 8 * nf + 32 * wc;
                sc[nf][e] = (sc[nf][e] + UKs[tt]) * 0.125f;
            }

        // ---- one-sync online softmax ----
        float rmx[2] = {-1e30f, -1e30f};
#pragma unroll
        for (int nf = 0; nf < 4; nf++)
#pragma unroll
            for (int e = 0; e < 4; e++)
                rmx[e >> 1] = fmaxf(rmx[e >> 1], sc[nf][e]);
#pragma unroll
        for (int msk = 1; msk < 4; msk <<= 1) {
            rmx[0] = fmaxf(rmx[0], __shfl_xor_sync(0xffffffffu, rmx[0], msk));
            rmx[1] = fmaxf(rmx[1], __shfl_xor_sync(0xffffffffu, rmx[1], msk));
        }
        float rs[2] = {0.f, 0.f};
#pragma unroll
        for (int nf = 0; nf < 4; nf++)
#pragma unroll
            for (int e = 0; e < 4; e++) {
                float p = __expf(sc[nf][e] - rmx[e >> 1]);
                sc[nf][e] = p;
                rs[e >> 1] += p;
            }
#pragma unroll
        for (int msk = 1; msk < 4; msk <<= 1) {
            rs[0] += __shfl_xor_sync(0xffffffffu, rs[0], msk);
            rs[1] += __shfl_xor_sync(0xffffffffu, rs[1], msk);
        }
        if (t4 == 0) {
            redmax[(16 * wr + g) * 2 + wc]     = rmx[0];
            redmax[(16 * wr + g + 8) * 2 + wc] = rmx[1];
            redsum[(16 * wr + g) * 2 + wc]     = rs[0];
            redsum[(16 * wr + g + 8) * 2 + wc] = rs[1];
        }
        __syncthreads();

        float corr[2], pscale[2];
#pragma unroll
        for (int hh = 0; hh < 2; hh++) {
            int row = 16 * wr + g + 8 * hh;
            float M0 = redmax[row * 2 + 0], S0 = redsum[row * 2 + 0];
            float M1 = redmax[row * 2 + 1], S1 = redsum[row * 2 + 1];
            float M  = fmaxf(m_r[hh], fmaxf(M0, M1));
            float cA = __expf(m_r[hh] - M);
            l_r[hh]  = l_r[hh] * cA + S0 * __expf(M0 - M) + S1 * __expf(M1 - M);
            corr[hh]   = cA;
            pscale[hh] = __expf(rmx[hh] - M);
            m_r[hh]    = M;
        }
#pragma unroll
        for (int nf = 0; nf < 8; nf++)
#pragma unroll
            for (int e = 0; e < 4; e++) acc[nf][e] *= corr[e >> 1];

        // ---- P -> A-fragments in-register; PV over own 32 t-cols, 64 dims ----
        uint32_t pa[2][4];
#pragma unroll
        for (int kk = 0; kk < 2; kk++) {
            pa[kk][0] = h2(sc[2*kk][0]   * pscale[0], sc[2*kk][1]   * pscale[0]);
            pa[kk][1] = h2(sc[2*kk][2]   * pscale[1], sc[2*kk][3]   * pscale[1]);
            pa[kk][2] = h2(sc[2*kk+1][0] * pscale[0], sc[2*kk+1][1] * pscale[0]);
            pa[kk][3] = h2(sc[2*kk+1][2] * pscale[1], sc[2*kk+1][3] * pscale[1]);
        }
#pragma unroll
        for (int kk = 0; kk < 2; kk++) {
            uint32_t rowaddr = vbase + (uint32_t)(((32 * wc + 16 * kk + (lane & 15)) * 36) * 4);
#pragma unroll
            for (int nf = 0; nf < 8; nf++) {
                uint32_t b0, b1;
                asm volatile(
                    "ldmatrix.sync.aligned.m8n8.x2.trans.shared.b16 {%0,%1}, [%2];"
                    : "=r"(b0), "=r"(b1) : "r"(rowaddr + nf * 16));
                mma_f16(acc[nf], pa[kk][0], pa[kk][1], pa[kk][2], pa[kk][3], b0, b1);
            }
        }
    }

    // ---- epilogue: combine col-half warps via smem, normalize, store ----
    float inv[2] = {1.f / l_r[0], 1.f / l_r[1]};
    if (wc == 0) {
#pragma unroll
        for (int nf = 0; nf < 8; nf++)
#pragma unroll
            for (int e = 0; e < 4; e++) {
                int row = 16 * wr + g + 8 * (e >> 1);
                int col = 2 * t4 + (e & 1) + 8 * nf;
                CB[row * 65 + col] = acc[nf][e];
            }
    }
    __syncthreads();
    if (wc == 1) {
#pragma unroll
        for (int nf = 0; nf < 8; nf++)
#pragma unroll
            for (int he = 0; he < 2; he++) {
                int row = 16 * wr + g + 8 * he;
                int col = 2 * t4 + 8 * nf;
                float2 o;
                o.x = (acc[nf][2 * he + 0] + CB[row * 65 + col])     * inv[he];
                o.y = (acc[nf][2 * he + 1] + CB[row * 65 + col + 1]) * inv[he];
                *(float2*)&OUT[(size_t)(b * S_LEN + s0 + row) * EMBED + hoff + col] = o;
            }
    }
}

// ---------------- launch ----------------
extern "C" void kernel_launch(void* const* d_in, const int* in_sizes, int n_in,
                              void* d_out, int out_size)
{
    const float* x   = (const float*)d_in[0];
    const float* Wq  = (const float*)d_in[1];
    const float* bq  = (const float*)d_in[2];
    const float* Wk  = (const float*)d_in[3];
    const float* bk  = (const float*)d_in[4];
    const float* Wv  = (const float*)d_in[5];
    const float* bv_ = (const float*)d_in[6];
    const float* Wp  = (const float*)d_in[7];
    const float* bp  = (const float*)d_in[8];
    const float* Wo  = (const float*)d_in[9];
    const float* bo  = (const float*)d_in[10];
    const float* u   = (const float*)d_in[11];
    const float* v   = (const float*)d_in[12];
    float* out = (float*)d_out;

    float *psin, *ppos, *pk, *pattn, *puk, *pve;
    __half *pqh, *pkh, *pvh, *pposh;
    cudaGetSymbolAddress((void**)&psin,  g_sin);
    cudaGetSymbolAddress((void**)&ppos,  g_pos);
    cudaGetSymbolAddress((void**)&pk,    g_k);
    cudaGetSymbolAddress((void**)&pattn, g_attn);
    cudaGetSymbolAddress((void**)&puk,   g_uk);
    cudaGetSymbolAddress((void**)&pve,   g_ve);
    cudaGetSymbolAddress((void**)&pqh,   g_qh);
    cudaGetSymbolAddress((void**)&pkh,   g_kh);
    cudaGetSymbolAddress((void**)&pvh,   g_vh);
    cudaGetSymbolAddress((void**)&pposh, g_posh);

    cudaFuncSetAttribute(attn_kernel, cudaFuncAttributeMaxDynamicSharedMemorySize,
                         ATT_SMEM_U32 * 4);

    invf_kernel<<<2, 256>>>();
    sinusoid_kernel<<<(S_LEN * (EMBED / 2) + 255) / 256, 256>>>();

    dim3 gBig(EMBED / 128, (BATCH * S_LEN) / 128);         // (8, 32)
    dim3 gQKVP(EMBED / 128, (BATCH * S_LEN) / 128, 4);     // (8, 32, 4)

    gemm_tf32_qkvp_kernel<<<gQKVP, 256>>>(x, psin,
                                          Wq, bq, Wk, bk, Wv, bv_, Wp, bp,
                                          pqh, pk, pkh, pvh, ppos, pposh,
                                          EMBED, EMBED);

    int nwarp = BATCH * NHEAD * S_LEN + NHEAD * S_LEN;
    ukve_kernel<<<(nwarp * 32 + 255) / 256, 256>>>(pk, ppos, u, v);

    dim3 gAtt(S_LEN / 64, NHEAD, BATCH);                   // (32, 16, 2)
    attn_kernel<<<gAtt, 256, ATT_SMEM_U32 * 4>>>(pqh, pkh, pvh, pposh, puk, pve, pattn);

    gemm_f16x3_kernel<<<gBig, 256>>>(pattn, Wo, bo, out, BATCH * S_LEN, EMBED, EMBED);
}

// round 17
// speedup vs baseline: 5.1525x; 1.0777x over previous
#include <cuda_runtime.h>
#include <cuda_fp16.h>
#include <math.h>
#include <stdint.h>

#define S_LEN 2048
#define BATCH 2
#define EMBED 1024
#define NHEAD 16
#define HDIM  64

// ---------------- scratch (static device globals; no allocation) ----------------
__device__ float  g_sin[S_LEN * EMBED];
__device__ float  g_pos[S_LEN * EMBED];            // fp32 (ukve needs exact dots)
__device__ float  g_k[BATCH * S_LEN * EMBED];      // fp32 (ukve)
__device__ float  g_attn[BATCH * S_LEN * EMBED];
__device__ __half g_qh[BATCH * S_LEN * EMBED];     // fp16 staged for attn
__device__ __half g_kh[BATCH * S_LEN * EMBED];
__device__ __half g_vh[BATCH * S_LEN * EMBED];
__device__ __half g_posh[S_LEN * EMBED];
__device__ float  g_uk[BATCH * NHEAD * S_LEN];     // u . k_t   per (b,h,t)
__device__ float  g_ve[NHEAD * S_LEN];             // v . pos_c per (h,c)
__device__ float  g_invf[EMBED / 2];

// ---------------- sinusoid position embedding (fp32 fast path) ----------------
__global__ void invf_kernel() {
    int i = blockIdx.x * blockDim.x + threadIdx.x;
    if (i >= EMBED / 2) return;
    double invf = exp(-(2.0 * (double)i / (double)EMBED) * log(10000.0));
    g_invf[i] = (float)invf;
}

__global__ void sinusoid_kernel() {
    int idx = blockIdx.x * blockDim.x + threadIdx.x;
    if (idx >= S_LEN * (EMBED / 2)) return;
    int s = idx / (EMBED / 2);
    int i = idx % (EMBED / 2);
    float ang = (float)s * g_invf[i];
    float sv, cv;
    sincosf(ang, &sv, &cv);
    g_sin[s * EMBED + i]             = sv;
    g_sin[s * EMBED + (EMBED/2) + i] = cv;
}

// ---------------- UK/VE precompute: one warp per dot-64 (fp32 exact) ----------------
__global__ void ukve_kernel(const float* __restrict__ K, const float* __restrict__ POS,
                            const float* __restrict__ u, const float* __restrict__ v)
{
    int w    = (blockIdx.x * blockDim.x + threadIdx.x) >> 5;
    int lane = threadIdx.x & 31;
    const int UKW = BATCH * NHEAD * S_LEN;
    if (w < UKW) {
        int t = w & (S_LEN - 1);
        int h = (w >> 11) & (NHEAD - 1);
        int b = w >> 15;
        const float* kp = K + ((size_t)(b * S_LEN + t)) * EMBED + h * HDIM;
        const float* up = u + h * HDIM;
        float s = kp[lane] * up[lane] + kp[lane + 32] * up[lane + 32];
#pragma unroll
        for (int m = 16; m; m >>= 1) s += __shfl_xor_sync(~0u, s, m);
        if (!lane) g_uk[w] = s;
    } else if (w < UKW + NHEAD * S_LEN) {
        int w2 = w - UKW;
        int c = w2 & (S_LEN - 1);
        int h = w2 >> 11;
        const float* pp = POS + (size_t)c * EMBED + h * HDIM;
        const float* vp = v + h * HDIM;
        float s = pp[lane] * vp[lane] + pp[lane + 32] * vp[lane + 32];
#pragma unroll
        for (int m = 16; m; m >>= 1) s += __shfl_xor_sync(~0u, s, m);
        if (!lane) g_ve[w2] = s;
    }
}

// ---------------- helpers ----------------
__device__ __forceinline__ float tf32f(float f) {
    uint32_t u;
    asm("cvt.rna.tf32.f32 %0, %1;" : "=r"(u) : "f"(f));
    return __uint_as_float(u);
}
__device__ __forceinline__ uint32_t fb(float f) { return __float_as_uint(f); }
__device__ __forceinline__ uint32_t h2(float x, float y) {
    __half2 h = __floats2half2_rn(x, y);
    return *(uint32_t*)&h;
}
__device__ __forceinline__ void split2(float x, float y, uint32_t& hi, uint32_t& lo) {
    __half hx = __float2half_rn(x), hy = __float2half_rn(y);
    float rx = x - __half2float(hx), ry = y - __half2float(hy);
    __half2 hh; hh.x = hx; hh.y = hy;
    hi = *(uint32_t*)&hh;
    lo = h2(rx, ry);
}
__device__ __forceinline__ void mma_tf32(float* d,
    uint32_t a0, uint32_t a1, uint32_t a2, uint32_t a3, uint32_t b0, uint32_t b1)
{
    asm volatile(
        "mma.sync.aligned.m16n8k8.row.col.f32.tf32.tf32.f32 "
        "{%0,%1,%2,%3}, {%4,%5,%6,%7}, {%8,%9}, {%0,%1,%2,%3};"
        : "+f"(d[0]), "+f"(d[1]), "+f"(d[2]), "+f"(d[3])
        : "r"(a0), "r"(a1), "r"(a2), "r"(a3), "r"(b0), "r"(b1));
}
__device__ __forceinline__ void mma_f16(float* d,
    uint32_t a0, uint32_t a1, uint32_t a2, uint32_t a3, uint32_t b0, uint32_t b1)
{
    asm volatile(
        "mma.sync.aligned.m16n8k16.row.col.f32.f16.f16.f32 "
        "{%0,%1,%2,%3}, {%4,%5,%6,%7}, {%8,%9}, {%0,%1,%2,%3};"
        : "+f"(d[0]), "+f"(d[1]), "+f"(d[2]), "+f"(d[3])
        : "r"(a0), "r"(a1), "r"(a2), "r"(a3), "r"(b0), "r"(b1));
}

// ---------------- tf32 tensor-core GEMM + bias (2-stage, dual fp32/fp16 output) ----
__device__ __forceinline__ void gemm_tf32_body(
    const float* __restrict__ A, const float* __restrict__ B,
    const float* __restrict__ bias, float* __restrict__ C32,
    __half* __restrict__ C16, int N, int K)
{
    __shared__ float As[2][128 * 20];
    __shared__ float Bs[2][16 * 136];
    const int tid  = threadIdx.x;
    const int lane = tid & 31;
    const int wid  = tid >> 5;
    const int wr   = wid >> 2;
    const int wc   = wid & 3;
    const int g    = lane >> 2;
    const int t4   = lane & 3;
    const int m0   = blockIdx.y * 128;
    const int n0   = blockIdx.x * 128;

    float acc[4][4][4];
#pragma unroll
    for (int mf = 0; mf < 4; mf++)
#pragma unroll
        for (int nf = 0; nf < 4; nf++)
#pragma unroll
            for (int e = 0; e < 4; e++) acc[mf][nf][e] = 0.f;

    const int a_row = tid >> 2;
    const int a_k4  = (tid & 3) * 4;
    const int b_k   = tid >> 4;
    const int b_n4  = (tid & 15) * 4;

    const float* Ap = A + (size_t)(m0 + a_row) * K + a_k4;
    const float* Bp = B + (size_t)b_k * N + n0 + b_n4;

    {
        float4 av0 = *(const float4*)(Ap);
        float4 av1 = *(const float4*)(Ap + (size_t)64 * K);
        float4 bv0 = *(const float4*)(Bp);
        float4 bv1 = *(const float4*)(Bp + 64);
        float* as0 = As[0] + a_row * 20 + a_k4;
        as0[0] = tf32f(av0.x); as0[1] = tf32f(av0.y);
        as0[2] = tf32f(av0.z); as0[3] = tf32f(av0.w);
        float* as1 = As[0] + (a_row + 64) * 20 + a_k4;
        as1[0] = tf32f(av1.x); as1[1] = tf32f(av1.y);
        as1[2] = tf32f(av1.z); as1[3] = tf32f(av1.w);
        float* bs0 = Bs[0] + b_k * 136 + b_n4;
        bs0[0] = tf32f(bv0.x); bs0[1] = tf32f(bv0.y);
        bs0[2] = tf32f(bv0.z); bs0[3] = tf32f(bv0.w);
        float* bs1 = bs0 + 64;
        bs1[0] = tf32f(bv1.x); bs1[1] = tf32f(bv1.y);
        bs1[2] = tf32f(bv1.z); bs1[3] = tf32f(bv1.w);
    }
    int cur = 0;

    for (int k0 = 0; k0 < K; k0 += 16) {
        __syncthreads();
        const bool more = (k0 + 16 < K);
        float4 av0, av1, bv0, bv1;
        if (more) {
            int kn = k0 + 16;
            av0 = *(const float4*)(Ap + kn);
            av1 = *(const float4*)(Ap + (size_t)64 * K + kn);
            bv0 = *(const float4*)(Bp + (size_t)kn * N);
            bv1 = *(const float4*)(Bp + (size_t)kn * N + 64);
        }

        const float* Acur = As[cur];
        const float* Bcur = Bs[cur];
#pragma unroll
        for (int kk = 0; kk < 2; kk++) {
            uint32_t af[4][4];
#pragma unroll
            for (int mf = 0; mf < 4; mf++) {
                const float* pa = Acur + (64 * wr + 16 * mf + g) * 20 + 8 * kk + t4;
                af[mf][0] = fb(pa[0]);
                af[mf][1] = fb(pa[8 * 20]);
                af[mf][2] = fb(pa[4]);
                af[mf][3] = fb(pa[8 * 20 + 4]);
            }
#pragma unroll
            for (int nf = 0; nf < 4; nf++) {
                const float* pb = Bcur + (8 * kk + t4) * 136 + 32 * wc + 8 * nf + g;
                uint32_t b0 = fb(pb[0]);
                uint32_t b1 = fb(pb[4 * 136]);
#pragma unroll
                for (int mf = 0; mf < 4; mf++)
                    mma_tf32(acc[mf][nf], af[mf][0], af[mf][1], af[mf][2], af[mf][3], b0, b1);
            }
        }

        if (more) {
            int nxt = cur ^ 1;
            float* as0 = As[nxt] + a_row * 20 + a_k4;
            as0[0] = tf32f(av0.x); as0[1] = tf32f(av0.y);
            as0[2] = tf32f(av0.z); as0[3] = tf32f(av0.w);
            float* as1 = As[nxt] + (a_row + 64) * 20 + a_k4;
            as1[0] = tf32f(av1.x); as1[1] = tf32f(av1.y);
            as1[2] = tf32f(av1.z); as1[3] = tf32f(av1.w);
            float* bs0 = Bs[nxt] + b_k * 136 + b_n4;
            bs0[0] = tf32f(bv0.x); bs0[1] = tf32f(bv0.y);
            bs0[2] = tf32f(bv0.z); bs0[3] = tf32f(bv0.w);
            float* bs1 = bs0 + 64;
            bs1[0] = tf32f(bv1.x); bs1[1] = tf32f(bv1.y);
            bs1[2] = tf32f(bv1.z); bs1[3] = tf32f(bv1.w);
            cur = nxt;
        }
    }
#pragma unroll
    for (int mf = 0; mf < 4; mf++)
#pragma unroll
        for (int nf = 0; nf < 4; nf++)
#pragma unroll
            for (int h2i = 0; h2i < 2; h2i++) {
                int row = m0 + 64 * wr + 16 * mf + g + 8 * h2i;
                int col = n0 + 32 * wc + 8 * nf + 2 * t4;
                float ox = acc[mf][nf][2 * h2i + 0] + bias[col];
                float oy = acc[mf][nf][2 * h2i + 1] + bias[col + 1];
                if (C32) {
                    float2 o; o.x = ox; o.y = oy;
                    *(float2*)&C32[(size_t)row * N + col] = o;
                }
                if (C16) {
                    __half2 oh = __floats2half2_rn(ox, oy);
                    *(__half2*)&C16[(size_t)row * N + col] = oh;
                }
            }
}

// Q/K/V/pos fused into ONE launch via blockIdx.z (z=3 is the pos proj, y<16)
__global__ void __launch_bounds__(256, 2) gemm_tf32_qkvp_kernel(
    const float* __restrict__ x, const float* __restrict__ sinu,
    const float* __restrict__ W0, const float* __restrict__ c0,
    const float* __restrict__ W1, const float* __restrict__ c1,
    const float* __restrict__ W2, const float* __restrict__ c2,
    const float* __restrict__ W3, const float* __restrict__ c3,
    __half* __restrict__ Qh, float* __restrict__ Kf, __half* __restrict__ Kh,
    __half* __restrict__ Vh, float* __restrict__ Pf, __half* __restrict__ Ph,
    int N, int K)
{
    const float* A; const float* B; const float* bias;
    float* C32; __half* C16;
    if (blockIdx.z == 0)      { A = x;    B = W0; bias = c0; C32 = 0;  C16 = Qh; }
    else if (blockIdx.z == 1) { A = x;    B = W1; bias = c1; C32 = Kf; C16 = Kh; }
    else if (blockIdx.z == 2) { A = x;    B = W2; bias = c2; C32 = 0;  C16 = Vh; }
    else {
        if (blockIdx.y >= 16) return;
        A = sinu; B = W3; bias = c3; C32 = Pf; C16 = Ph;
    }
    gemm_tf32_body(A, B, bias, C32, C16, N, K);
}

// ---------------- fp16-split tensor-core GEMM + bias (out-proj; 2-stage) ----------
#define OP_AST 12
#define OP_WST 68
__global__ void __launch_bounds__(256, 2) gemm_f16x3_kernel(
    const float* __restrict__ A, const float* __restrict__ W,
    const float* __restrict__ bias, float* __restrict__ C,
    int M, int N, int K)
{
    __shared__ uint32_t A1[2][128 * OP_AST];
    __shared__ uint32_t A2[2][128 * OP_AST];
    __shared__ uint32_t W1[2][16 * OP_WST];
    __shared__ uint32_t W2[2][16 * OP_WST];
    const int tid  = threadIdx.x;
    const int lane = tid & 31;
    const int wid  = tid >> 5;
    const int wr   = wid >> 2;
    const int wc   = wid & 3;
    const int g    = lane >> 2;
    const int t4   = lane & 3;
    const int m0   = blockIdx.y * 128;
    const int n0   = blockIdx.x * 128;

    uint32_t w1b[2], w2b[2];
    w1b[0] = (uint32_t)__cvta_generic_to_shared(W1[0]);
    w1b[1] = (uint32_t)__cvta_generic_to_shared(W1[1]);
    w2b[0] = (uint32_t)__cvta_generic_to_shared(W2[0]);
    w2b[1] = (uint32_t)__cvta_generic_to_shared(W2[1]);

    float acc[4][4][4];
#pragma unroll
    for (int mf = 0; mf < 4; mf++)
#pragma unroll
        for (int nf = 0; nf < 4; nf++)
#pragma unroll
            for (int e = 0; e < 4; e++) acc[mf][nf][e] = 0.f;

    const int a_row = tid >> 2;
    const int a_k4  = (tid & 3) * 4;
    const int b_k   = tid >> 4;
    const int b_n4  = (tid & 15) * 4;

    const float* Ap = A + (size_t)(m0 + a_row) * K + a_k4;
    const float* Wp = W + (size_t)b_k * N + n0 + b_n4;

    {
        float4 av0 = *(const float4*)(Ap);
        float4 av1 = *(const float4*)(Ap + (size_t)64 * K);
        float4 wv0 = *(const float4*)(Wp);
        float4 wv1 = *(const float4*)(Wp + 64);
        uint32_t hi, lo;
        uint32_t* p1 = A1[0] + a_row * OP_AST + (a_k4 >> 1);
        uint32_t* p2 = A2[0] + a_row * OP_AST + (a_k4 >> 1);
        split2(av0.x, av0.y, hi, lo); p1[0] = hi; p2[0] = lo;
        split2(av0.z, av0.w, hi, lo); p1[1] = hi; p2[1] = lo;
        p1 = A1[0] + (a_row + 64) * OP_AST + (a_k4 >> 1);
        p2 = A2[0] + (a_row + 64) * OP_AST + (a_k4 >> 1);
        split2(av1.x, av1.y, hi, lo); p1[0] = hi; p2[0] = lo;
        split2(av1.z, av1.w, hi, lo); p1[1] = hi; p2[1] = lo;
        uint32_t* q1 = W1[0] + b_k * OP_WST + (b_n4 >> 1);
        uint32_t* q2 = W2[0] + b_k * OP_WST + (b_n4 >> 1);
        split2(wv0.x, wv0.y, hi, lo); q1[0] = hi; q2[0] = lo;
        split2(wv0.z, wv0.w, hi, lo); q1[1] = hi; q2[1] = lo;
        split2(wv1.x, wv1.y, hi, lo); q1[32] = hi; q2[32] = lo;
        split2(wv1.z, wv1.w, hi, lo); q1[33] = hi; q2[33] = lo;
    }
    int cur = 0;

    for (int k0 = 0; k0 < K; k0 += 16) {
        __syncthreads();
        const bool more = (k0 + 16 < K);
        float4 av0, av1, wv0, wv1;
        if (more) {
            int kn = k0 + 16;
            av0 = *(const float4*)(Ap + kn);
            av1 = *(const float4*)(Ap + (size_t)64 * K + kn);
            wv0 = *(const float4*)(Wp + (size_t)kn * N);
            wv1 = *(const float4*)(Wp + (size_t)kn * N + 64);
        }

        uint32_t af1[4][4], af2[4][4];
#pragma unroll
        for (int mf = 0; mf < 4; mf++) {
            const uint32_t* pa1 = A1[cur] + (64 * wr + 16 * mf + g) * OP_AST + t4;
            const uint32_t* pa2 = A2[cur] + (64 * wr + 16 * mf + g) * OP_AST + t4;
            af1[mf][0] = pa1[0];  af1[mf][1] = pa1[8 * OP_AST];
            af1[mf][2] = pa1[4];  af1[mf][3] = pa1[8 * OP_AST + 4];
            af2[mf][0] = pa2[0];  af2[mf][1] = pa2[8 * OP_AST];
            af2[mf][2] = pa2[4];  af2[mf][3] = pa2[8 * OP_AST + 4];
        }
#pragma unroll
        for (int nf = 0; nf < 4; nf++) {
            uint32_t off = (((lane & 15) * OP_WST) + 16 * wc + 4 * nf) * 4;
            uint32_t b10, b11, b20, b21;
            asm volatile("ldmatrix.sync.aligned.m8n8.x2.trans.shared.b16 {%0,%1}, [%2];"
                         : "=r"(b10), "=r"(b11) : "r"(w1b[cur] + off));
            asm volatile("ldmatrix.sync.aligned.m8n8.x2.trans.shared.b16 {%0,%1}, [%2];"
                         : "=r"(b20), "=r"(b21) : "r"(w2b[cur] + off));
#pragma unroll
            for (int mf = 0; mf < 4; mf++) {
                mma_f16(acc[mf][nf], af1[mf][0], af1[mf][1], af1[mf][2], af1[mf][3], b10, b11);
                mma_f16(acc[mf][nf], af1[mf][0], af1[mf][1], af1[mf][2], af1[mf][3], b20, b21);
                mma_f16(acc[mf][nf], af2[mf][0], af2[mf][1], af2[mf][2], af2[mf][3], b10, b11);
            }
        }

        if (more) {
            int nxt = cur ^ 1;
            uint32_t hi, lo;
            uint32_t* p1 = A1[nxt] + a_row * OP_AST + (a_k4 >> 1);
            uint32_t* p2 = A2[nxt] + a_row * OP_AST + (a_k4 >> 1);
            split2(av0.x, av0.y, hi, lo); p1[0] = hi; p2[0] = lo;
            split2(av0.z, av0.w, hi, lo); p1[1] = hi; p2[1] = lo;
            p1 = A1[nxt] + (a_row + 64) * OP_AST + (a_k4 >> 1);
            p2 = A2[nxt] + (a_row + 64) * OP_AST + (a_k4 >> 1);
            split2(av1.x, av1.y, hi, lo); p1[0] = hi; p2[0] = lo;
            split2(av1.z, av1.w, hi, lo); p1[1] = hi; p2[1] = lo;
            uint32_t* q1 = W1[nxt] + b_k * OP_WST + (b_n4 >> 1);
            uint32_t* q2 = W2[nxt] + b_k * OP_WST + (b_n4 >> 1);
            split2(wv0.x, wv0.y, hi, lo); q1[0] = hi; q2[0] = lo;
            split2(wv0.z, wv0.w, hi, lo); q1[1] = hi; q2[1] = lo;
            split2(wv1.x, wv1.y, hi, lo); q1[32] = hi; q2[32] = lo;
            split2(wv1.z, wv1.w, hi, lo); q1[33] = hi; q2[33] = lo;
            cur = nxt;
        }
    }
#pragma unroll
    for (int mf = 0; mf < 4; mf++)
#pragma unroll
        for (int nf = 0; nf < 4; nf++)
#pragma unroll
            for (int he = 0; he < 2; he++) {
                int row = m0 + 64 * wr + 16 * mf + g + 8 * he;
                int col = n0 + 32 * wc + 8 * nf + 2 * t4;
                float2 o;
                o.x = acc[mf][nf][2 * he + 0] + bias[col];
                o.y = acc[mf][nf][2 * he + 1] + bias[col + 1];
                *(float2*)&C[(size_t)row * N + col] = o;
            }
}

// ---------------- fused relative attention (incremental-G ring) --------------------
// score[s][t] = ( q_s.k_t + UK[t] + F[s][d] + VE_d ) / 8,  d = t - s
//   F[s][d] = q_s.pos[S-1+d]  (d<=0) | 0 (d==1) | q_{s+1}.pos[d-2] (d>=2)
// F depends only on (s,d): computed ONCE per diagonal into a 128-wide ring
// (slot = (d/64) mod 2). Per tile only the 64 NEW diagonals [diag, diag+63] are
// computed (16 MMAs, one 64-row E chunk); the first tile also computes
// [diag-64, diag-1]. The d0==0 chunk straddles the q-row switch: main pass uses
// q_{s+1}, then a small pass writes the d==0 column pair with q_s (col d==1 is
// zero since its E row is zero-filled). Gather: d != 1 -> ring[(d mod 128)] + VE.
#define QS_OFF   0        // 65*36
#define KS_OFF   2340     // 64*36
#define VS_OFF   4644     // 64*36
#define ES_OFF   6948     // 128*36 (chunk rows; init uses all 128, steady 64)
#define GS_OFF   11556    // ring: 64 rows x 66 u32 (132 halves: 128 data + pad)
#define UK_OFF   15780    // 64 f32
#define VE_OFF   15844    // 128 f32
#define RMX_OFF  15972    // 128 f32
#define RSM_OFF  16100    // 128 f32
#define ATT_SMEM_U32 16228  // 64,912 B -> 3 blocks/SM

__global__ void __launch_bounds__(256, 3) attn_kernel(
    const __half* __restrict__ Qh, const __half* __restrict__ Kh,
    const __half* __restrict__ Vh, const __half* __restrict__ POSh,
    const float* __restrict__ UK, const float* __restrict__ VE,
    float* __restrict__ OUT)
{
    extern __shared__ uint32_t su[];
    uint32_t* Qsu = su + QS_OFF;
    uint32_t* Ksu = su + KS_OFF;
    uint32_t* Vsu = su + VS_OFF;
    uint32_t* Esu = su + ES_OFF;
    uint32_t* Gsu = su + GS_OFF;
    __half*   Ghh = (__half*)(su + GS_OFF);
    float*    CB  = (float*)(su + GS_OFF);  // epilogue combine (ring dead by then)
    float* UKs    = (float*)(su + UK_OFF);
    float* VEs    = (float*)(su + VE_OFF);
    float* redmax = (float*)(su + RMX_OFF);
    float* redsum = (float*)(su + RSM_OFF);

    const int tid  = threadIdx.x;
    const int lane = tid & 31;
    const int wid  = tid >> 5;
    const int wr   = wid >> 1;     // 0..3 : 16-row group
    const int wc   = wid & 1;      // 0..1 : 32-col half
    const int g    = lane >> 2;
    const int t4   = lane & 3;

    const int s0   = blockIdx.x * 64;
    const int h    = blockIdx.y;
    const int b    = blockIdx.z;
    const int hoff = h * HDIM;

    const uint32_t vbase = (uint32_t)__cvta_generic_to_shared(Vsu);

    // Q prologue: pure uint4 copy, 65 rows
    for (int it = tid; it < 65 * 8; it += 256) {
        int row = it >> 3;
        int p8  = (it & 7) * 8;
        int s   = s0 + row; if (s > S_LEN - 1) s = S_LEN - 1;
        uint4 qv = *(const uint4*)(Qh + (size_t)(b * S_LEN + s) * EMBED + hoff + p8);
        *(uint4*)(Qsu + row * 36 + (p8 >> 1)) = qv;
    }

    float acc[8][4];
    float m_r[2], l_r[2];
#pragma unroll
    for (int nf = 0; nf < 8; nf++)
#pragma unroll
        for (int e = 0; e < 4; e++) acc[nf][e] = 0.f;
    m_r[0] = m_r[1] = -1e30f;
    l_r[0] = l_r[1] = 0.f;

    for (int t0 = 0; t0 < S_LEN; t0 += 64) {
        const int diag   = t0 - s0;
        const int nchunk = (t0 == 0) ? 2 : 1;
        const int dbase  = (t0 == 0) ? (diag - 64) : diag;
        __syncthreads();           // prev PV/gather reads complete

        // K + V fill: pure uint4 copies
        for (int it = tid; it < 64 * 8; it += 256) {
            int row = it >> 3;
            int p8  = (it & 7) * 8;
            size_t go = (size_t)(b * S_LEN + t0 + row) * EMBED + hoff + p8;
            uint4 kv = *(const uint4*)(Kh + go);
            uint4 vv = *(const uint4*)(Vh + go);
            *(uint4*)(Ksu + row * 36 + (p8 >> 1)) = kv;
            *(uint4*)(Vsu + row * 36 + (p8 >> 1)) = vv;
        }
        // E chunk fill: rows r hold pos for d = dbase + r
        for (int it = tid; it < nchunk * 64 * 8; it += 256) {
            int r  = it >> 3;
            int p8 = (it & 7) * 8;
            int d  = dbase + r;
            int c  = (d <= 0) ? (S_LEN - 1 + d) : ((d == 1) ? -1 : (d - 2));
            uint4 pv = make_uint4(0u, 0u, 0u, 0u);
            if (c >= 0)
                pv = *(const uint4*)(POSh + (size_t)c * EMBED + hoff + p8);
            *(uint4*)(Esu + r * 36 + (p8 >> 1)) = pv;
        }
        if (tid < 64) UKs[tid] = UK[((b * NHEAD + h) << 11) + t0 + tid];
        if (tid < 128) {
            int r = tid;
            float val = 0.f;
            if (r < 127) {
                int d = diag - 63 + r;
                int c = (d <= 0) ? (S_LEN - 1 + d) : ((d == 1) ? -1 : (d - 2));
                if (c >= 0) val = VE[(h << 11) + c];
            }
            VEs[r] = val;
        }
        __syncthreads();

        // ---- content score MMA: sc = q @ K^T ----
        float sc[4][4];
#pragma unroll
        for (int nf = 0; nf < 4; nf++)
#pragma unroll
            for (int e = 0; e < 4; e++) sc[nf][e] = 0.f;
        {
            const uint32_t* Aq = Qsu + (16 * wr + g) * 36 + t4;
            const uint32_t* Bk = Ksu + (32 * wc + g) * 36 + t4;
#pragma unroll
            for (int kk = 0; kk < 4; kk++) {
                uint32_t a0 = Aq[8 * kk];
                uint32_t a1 = Aq[8 * 36 + 8 * kk];
                uint32_t a2 = Aq[8 * kk + 4];
                uint32_t a3 = Aq[8 * 36 + 8 * kk + 4];
#pragma unroll
                for (int nf = 0; nf < 4; nf++) {
                    uint32_t b0 = Bk[nf * 8 * 36 + 8 * kk];
                    uint32_t b1 = Bk[nf * 8 * 36 + 8 * kk + 4];
                    mma_f16(sc[nf], a0, a1, a2, a3, b0, b1);
                }
            }
        }

        // ---- incremental G: one 64-wide chunk per tile (two on init) ----
#pragma unroll 1
        for (int cc = 0; cc < nchunk; cc++) {
            const int d0    = dbase + 64 * cc;
            const int ebase = 64 * cc;
            const int slot  = ((unsigned)(d0 + 8192) >> 6) & 1;
            const bool straddle = (d0 == 0);
            const int mainpass  = (d0 > 0 || straddle) ? 1 : 0;

            {
                const uint32_t* Aq = Qsu + (16 * wr + g + mainpass) * 36 + t4;
                const uint32_t* Be = Esu + (ebase + 32 * wc + g) * 36 + t4;
                float ga[4][4];
#pragma unroll
                for (int nf = 0; nf < 4; nf++)
#pragma unroll
                    for (int e = 0; e < 4; e++) ga[nf][e] = 0.f;
#pragma unroll
                for (int kk = 0; kk < 4; kk++) {
                    uint32_t a0 = Aq[8 * kk];
                    uint32_t a1 = Aq[8 * 36 + 8 * kk];
                    uint32_t a2 = Aq[8 * kk + 4];
                    uint32_t a3 = Aq[8 * 36 + 8 * kk + 4];
#pragma unroll
                    for (int nf = 0; nf < 4; nf++) {
                        uint32_t b0 = Be[nf * 8 * 36 + 8 * kk];
                        uint32_t b1 = Be[nf * 8 * 36 + 8 * kk + 4];
                        mma_f16(ga[nf], a0, a1, a2, a3, b0, b1);
                    }
                }
#pragma unroll
                for (int nf = 0; nf < 4; nf++)
#pragma unroll
                    for (int he = 0; he < 2; he++) {
                        int row = 16 * wr + g + 8 * he;
                        int h2c = slot * 32 + 16 * wc + 4 * nf + t4;
                        bool skip = straddle && (wc == 0) && (nf == 0) && (t4 == 0);
                        if (!skip)
                            Gsu[row * 66 + h2c] = h2(ga[nf][2 * he], ga[nf][2 * he + 1]);
                    }
            }
            if (straddle && wc == 0) {
                // q_s pass for the d==0 column pair (col d==1 is zero: E row zeroed)
                const uint32_t* Aq = Qsu + (16 * wr + g) * 36 + t4;
                const uint32_t* Be = Esu + (ebase + g) * 36 + t4;
                float ga0[4] = {0.f, 0.f, 0.f, 0.f};
#pragma unroll
                for (int kk = 0; kk < 4; kk++) {
                    uint32_t a0 = Aq[8 * kk];
                    uint32_t a1 = Aq[8 * 36 + 8 * kk];
                    uint32_t a2 = Aq[8 * kk + 4];
                    uint32_t a3 = Aq[8 * 36 + 8 * kk + 4];
                    uint32_t b0 = Be[8 * kk];
                    uint32_t b1 = Be[8 * kk + 4];
                    mma_f16(ga0, a0, a1, a2, a3, b0, b1);
                }
                if (t4 == 0) {
#pragma unroll
                    for (int he = 0; he < 2; he++)
                        Gsu[(16 * wr + g + 8 * he) * 66 + slot * 32] =
                            h2(ga0[2 * he], ga0[2 * he + 1]);
                }
            }
        }
        __syncthreads();           // ring stores visible

        // ---- gather: all diagonals from the ring ----
#pragma unroll
        for (int nf = 0; nf < 4; nf++)
#pragma unroll
            for (int e = 0; e < 4; e++) {
                int ss = 16 * wr + g + 8 * (e >> 1);
                int tt = 2 * t4 + (e & 1) + 8 * nf + 32 * wc;
                int d  = diag + tt - ss;
                if (d != 1) {
                    int rh = (int)((unsigned)(d + 8192) & 127u);
                    sc[nf][e] += __half2float(Ghh[ss * 132 + rh]) + VEs[tt - ss + 63];
                }
            }

        // ---- add UK, scale ----
#pragma unroll
        for (int nf = 0; nf < 4; nf++)
#pragma unroll
            for (int e = 0; e < 4; e++) {
                int tt = 2 * t4 + (e & 1) + 8 * nf + 32 * wc;
                sc[nf][e] = (sc[nf][e] + UKs[tt]) * 0.125f;
            }

        // ---- one-sync online softmax ----
        float rmx[2] = {-1e30f, -1e30f};
#pragma unroll
        for (int nf = 0; nf < 4; nf++)
#pragma unroll
            for (int e = 0; e < 4; e++)
                rmx[e >> 1] = fmaxf(rmx[e >> 1], sc[nf][e]);
#pragma unroll
        for (int msk = 1; msk < 4; msk <<= 1) {
            rmx[0] = fmaxf(rmx[0], __shfl_xor_sync(0xffffffffu, rmx[0], msk));
            rmx[1] = fmaxf(rmx[1], __shfl_xor_sync(0xffffffffu, rmx[1], msk));
        }
        float rs[2] = {0.f, 0.f};
#pragma unroll
        for (int nf = 0; nf < 4; nf++)
#pragma unroll
            for (int e = 0; e < 4; e++) {
                float p = __expf(sc[nf][e] - rmx[e >> 1]);
                sc[nf][e] = p;
                rs[e >> 1] += p;
            }
#pragma unroll
        for (int msk = 1; msk < 4; msk <<= 1) {
            rs[0] += __shfl_xor_sync(0xffffffffu, rs[0], msk);
            rs[1] += __shfl_xor_sync(0xffffffffu, rs[1], msk);
        }
        if (t4 == 0) {
            redmax[(16 * wr + g) * 2 + wc]     = rmx[0];
            redmax[(16 * wr + g + 8) * 2 + wc] = rmx[1];
            redsum[(16 * wr + g) * 2 + wc]     = rs[0];
            redsum[(16 * wr + g + 8) * 2 + wc] = rs[1];
        }
        __syncthreads();

        float corr[2], pscale[2];
#pragma unroll
        for (int hh = 0; hh < 2; hh++) {
            int row = 16 * wr + g + 8 * hh;
            float M0 = redmax[row * 2 + 0], S0 = redsum[row * 2 + 0];
            float M1 = redmax[row * 2 + 1], S1 = redsum[row * 2 + 1];
            float M  = fmaxf(m_r[hh], fmaxf(M0, M1));
            float cA = __expf(m_r[hh] - M);
            l_r[hh]  = l_r[hh] * cA + S0 * __expf(M0 - M) + S1 * __expf(M1 - M);
            corr[hh]   = cA;
            pscale[hh] = __expf(rmx[hh] - M);
            m_r[hh]    = M;
        }
#pragma unroll
        for (int nf = 0; nf < 8; nf++)
#pragma unroll
            for (int e = 0; e < 4; e++) acc[nf][e] *= corr[e >> 1];

        // ---- P -> A-fragments in-register; PV over own 32 t-cols, 64 dims ----
        uint32_t pa[2][4];
#pragma unroll
        for (int kk = 0; kk < 2; kk++) {
            pa[kk][0] = h2(sc[2*kk][0]   * pscale[0], sc[2*kk][1]   * pscale[0]);
            pa[kk][1] = h2(sc[2*kk][2]   * pscale[1], sc[2*kk][3]   * pscale[1]);
            pa[kk][2] = h2(sc[2*kk+1][0] * pscale[0], sc[2*kk+1][1] * pscale[0]);
            pa[kk][3] = h2(sc[2*kk+1][2] * pscale[1], sc[2*kk+1][3] * pscale[1]);
        }
#pragma unroll
        for (int kk = 0; kk < 2; kk++) {
            uint32_t rowaddr = vbase + (uint32_t)(((32 * wc + 16 * kk + (lane & 15)) * 36) * 4);
#pragma unroll
            for (int nf = 0; nf < 8; nf++) {
                uint32_t b0, b1;
                asm volatile(
                    "ldmatrix.sync.aligned.m8n8.x2.trans.shared.b16 {%0,%1}, [%2];"
                    : "=r"(b0), "=r"(b1) : "r"(rowaddr + nf * 16));
                mma_f16(acc[nf], pa[kk][0], pa[kk][1], pa[kk][2], pa[kk][3], b0, b1);
            }
        }
    }

    // ---- epilogue: combine col-half warps via smem, normalize, store ----
    float inv[2] = {1.f / l_r[0], 1.f / l_r[1]};
    if (wc == 0) {
#pragma unroll
        for (int nf = 0; nf < 8; nf++)
#pragma unroll
            for (int e = 0; e < 4; e++) {
                int row = 16 * wr + g + 8 * (e >> 1);
                int col = 2 * t4 + (e & 1) + 8 * nf;
                CB[row * 65 + col] = acc[nf][e];
            }
    }
    __syncthreads();
    if (wc == 1) {
#pragma unroll
        for (int nf = 0; nf < 8; nf++)
#pragma unroll
            for (int he = 0; he < 2; he++) {
                int row = 16 * wr + g + 8 * he;
                int col = 2 * t4 + 8 * nf;
                float2 o;
                o.x = (acc[nf][2 * he + 0] + CB[row * 65 + col])     * inv[he];
                o.y = (acc[nf][2 * he + 1] + CB[row * 65 + col + 1]) * inv[he];
                *(float2*)&OUT[(size_t)(b * S_LEN + s0 + row) * EMBED + hoff + col] = o;
            }
    }
}

// ---------------- launch ----------------
extern "C" void kernel_launch(void* const* d_in, const int* in_sizes, int n_in,
                              void* d_out, int out_size)
{
    const float* x   = (const float*)d_in[0];
    const float* Wq  = (const float*)d_in[1];
    const float* bq  = (const float*)d_in[2];
    const float* Wk  = (const float*)d_in[3];
    const float* bk  = (const float*)d_in[4];
    const float* Wv  = (const float*)d_in[5];
    const float* bv_ = (const float*)d_in[6];
    const float* Wp  = (const float*)d_in[7];
    const float* bp  = (const float*)d_in[8];
    const float* Wo  = (const float*)d_in[9];
    const float* bo  = (const float*)d_in[10];
    const float* u   = (const float*)d_in[11];
    const float* v   = (const float*)d_in[12];
    float* out = (float*)d_out;

    float *psin, *ppos, *pk, *pattn, *puk, *pve;
    __half *pqh, *pkh, *pvh, *pposh;
    cudaGetSymbolAddress((void**)&psin,  g_sin);
    cudaGetSymbolAddress((void**)&ppos,  g_pos);
    cudaGetSymbolAddress((void**)&pk,    g_k);
    cudaGetSymbolAddress((void**)&pattn, g_attn);
    cudaGetSymbolAddress((void**)&puk,   g_uk);
    cudaGetSymbolAddress((void**)&pve,   g_ve);
    cudaGetSymbolAddress((void**)&pqh,   g_qh);
    cudaGetSymbolAddress((void**)&pkh,   g_kh);
    cudaGetSymbolAddress((void**)&pvh,   g_vh);
    cudaGetSymbolAddress((void**)&pposh, g_posh);

    cudaFuncSetAttribute(attn_kernel, cudaFuncAttributeMaxDynamicSharedMemorySize,
                         ATT_SMEM_U32 * 4);

    invf_kernel<<<2, 256>>>();
    sinusoid_kernel<<<(S_LEN * (EMBED / 2) + 255) / 256, 256>>>();

    dim3 gBig(EMBED / 128, (BATCH * S_LEN) / 128);         // (8, 32)
    dim3 gQKVP(EMBED / 128, (BATCH * S_LEN) / 128, 4);     // (8, 32, 4)

    gemm_tf32_qkvp_kernel<<<gQKVP, 256>>>(x, psin,
                                          Wq, bq, Wk, bk, Wv, bv_, Wp, bp,
                                          pqh, pk, pkh, pvh, ppos, pposh,
                                          EMBED, EMBED);

    int nwarp = BATCH * NHEAD * S_LEN + NHEAD * S_LEN;
    ukve_kernel<<<(nwarp * 32 + 255) / 256, 256>>>(pk, ppos, u, v);

    dim3 gAtt(S_LEN / 64, NHEAD, BATCH);                   // (32, 16, 2)
    attn_kernel<<<gAtt, 256, ATT_SMEM_U32 * 4>>>(pqh, pkh, pvh, pposh, puk, pve, pattn);

    gemm_f16x3_kernel<<<gBig, 256>>>(pattn, Wo, bo, out, BATCH * S_LEN, EMBED, EMBED);
}